// round 1
// baseline (speedup 1.0000x reference)
#include <cuda_runtime.h>
#include <math.h>

#define L_ 8
#define H_ 16
#define T_ 2048
#define C_ 1024
#define OUT_ 1024
#define B_ 4
#define DH_ 64
#define FF_ 4096
#define M_ (B_*T_)   // 8192 rows

// ---------------- scratch (static device globals; no allocation) ----------------
__device__ float g_x[M_*C_];
__device__ float g_h[M_*C_];
__device__ float g_q[M_*C_];
__device__ float g_k[M_*C_];
__device__ float g_v[M_*C_];
__device__ float g_y[M_*C_];
__device__ float g_u[(size_t)M_*FF_];

// ---------------- x = seq + pos (pos broadcast over batch) ----------------
__global__ void __launch_bounds__(256) addpos_kernel(
    const float* __restrict__ seq, const float* __restrict__ pos, float* __restrict__ x)
{
    int i = blockIdx.x * 256 + threadIdx.x;          // float4 index
    float4 s = ((const float4*)seq)[i];
    float4 p = ((const float4*)pos)[i & (T_*C_/4 - 1)];
    s.x += p.x; s.y += p.y; s.z += p.z; s.w += p.w;
    ((float4*)x)[i] = s;
}

// ---------------- LayerNorm: one block per row of C=1024 ----------------
__global__ void __launch_bounds__(256) ln_kernel(
    const float* __restrict__ x, const float* __restrict__ w,
    const float* __restrict__ b, float* __restrict__ out)
{
    const int row = blockIdx.x;
    const int t = threadIdx.x;
    const float4 v = *(const float4*)(x + (size_t)row * C_ + t * 4);
    float s  = v.x + v.y + v.z + v.w;
    float sq = v.x*v.x + v.y*v.y + v.z*v.z + v.w*v.w;
    #pragma unroll
    for (int off = 16; off; off >>= 1) {
        s  += __shfl_xor_sync(0xffffffffu, s,  off);
        sq += __shfl_xor_sync(0xffffffffu, sq, off);
    }
    __shared__ float rs_[8], rq_[8];
    if ((t & 31) == 0) { rs_[t >> 5] = s; rq_[t >> 5] = sq; }
    __syncthreads();
    s = 0.f; sq = 0.f;
    #pragma unroll
    for (int i = 0; i < 8; i++) { s += rs_[i]; sq += rq_[i]; }
    const float mu   = s * (1.0f / 1024.0f);
    const float var  = sq * (1.0f / 1024.0f) - mu * mu;
    const float rstd = rsqrtf(var + 1e-5f);
    const float4 wv = *(const float4*)(w + t * 4);
    const float4 bv = *(const float4*)(b + t * 4);
    float4 o;
    o.x = (v.x - mu) * rstd * wv.x + bv.x;
    o.y = (v.y - mu) * rstd * wv.y + bv.y;
    o.z = (v.z - mu) * rstd * wv.z + bv.z;
    o.w = (v.w - mu) * rstd * wv.w + bv.w;
    *(float4*)(out + (size_t)row * C_ + t * 4) = o;
}

// ---------------- SGEMM: C[M,N] = A[M,K] @ W[N,K]^T (+epilogue) ----------------
// EPI: 0=none, 1=+bias, 2=+bias then exact GELU, 3=+bias+residual
__device__ __forceinline__ float gelu_exact(float v) {
    return 0.5f * v * (1.0f + erff(v * 0.70710678118654752f));
}

template <int EPI>
__global__ void __launch_bounds__(256) gemm_nt(
    const float* __restrict__ A, const float* __restrict__ Bw,
    const float* __restrict__ bias, const float* __restrict__ resid,
    float* __restrict__ Cout, int M, int N, int K)
{
    __shared__ __align__(16) float As[16][132];
    __shared__ __align__(16) float Bs[16][132];
    const int bm = blockIdx.y, bn = blockIdx.x;
    const int t = threadIdx.x;
    const int tx4 = (t & 15) * 4, ty4 = (t >> 4) * 4;
    const int lrow = t >> 1;
    const int lk   = (t & 1) * 8;
    const float* Aptr = A  + (size_t)(bm * 128 + lrow) * K + lk;
    const float* Bptr = Bw + (size_t)(bn * 128 + lrow) * K + lk;

    float acc[8][8];
    #pragma unroll
    for (int i = 0; i < 8; i++)
        #pragma unroll
        for (int j = 0; j < 8; j++) acc[i][j] = 0.f;

    for (int kt = 0; kt < K; kt += 16) {
        float4 a0 = *(const float4*)(Aptr);
        float4 a1 = *(const float4*)(Aptr + 4);
        float4 b0 = *(const float4*)(Bptr);
        float4 b1 = *(const float4*)(Bptr + 4);
        Aptr += 16; Bptr += 16;
        __syncthreads();
        As[lk+0][lrow] = a0.x; As[lk+1][lrow] = a0.y; As[lk+2][lrow] = a0.z; As[lk+3][lrow] = a0.w;
        As[lk+4][lrow] = a1.x; As[lk+5][lrow] = a1.y; As[lk+6][lrow] = a1.z; As[lk+7][lrow] = a1.w;
        Bs[lk+0][lrow] = b0.x; Bs[lk+1][lrow] = b0.y; Bs[lk+2][lrow] = b0.z; Bs[lk+3][lrow] = b0.w;
        Bs[lk+4][lrow] = b1.x; Bs[lk+5][lrow] = b1.y; Bs[lk+6][lrow] = b1.z; Bs[lk+7][lrow] = b1.w;
        __syncthreads();
        #pragma unroll
        for (int kk = 0; kk < 16; kk++) {
            float ar[8], br[8];
            *(float4*)&ar[0] = *(const float4*)&As[kk][ty4];
            *(float4*)&ar[4] = *(const float4*)&As[kk][ty4 + 64];
            *(float4*)&br[0] = *(const float4*)&Bs[kk][tx4];
            *(float4*)&br[4] = *(const float4*)&Bs[kk][tx4 + 64];
            #pragma unroll
            for (int i = 0; i < 8; i++)
                #pragma unroll
                for (int j = 0; j < 8; j++)
                    acc[i][j] = fmaf(ar[i], br[j], acc[i][j]);
        }
    }

    #pragma unroll
    for (int i = 0; i < 8; i++) {
        const int row = bm * 128 + ((i < 4) ? (ty4 + i) : (64 + ty4 + i - 4));
        const size_t rb = (size_t)row * N;
        #pragma unroll
        for (int jg = 0; jg < 2; jg++) {
            const int col = bn * 128 + jg * 64 + tx4;
            float4 r = make_float4(acc[i][jg*4+0], acc[i][jg*4+1], acc[i][jg*4+2], acc[i][jg*4+3]);
            if (EPI >= 1) {
                float4 bb = *(const float4*)(bias + col);
                r.x += bb.x; r.y += bb.y; r.z += bb.z; r.w += bb.w;
            }
            if (EPI == 2) {
                r.x = gelu_exact(r.x); r.y = gelu_exact(r.y);
                r.z = gelu_exact(r.z); r.w = gelu_exact(r.w);
            }
            if (EPI == 3) {
                float4 rr = *(const float4*)(resid + rb + col);
                r.x += rr.x; r.y += rr.y; r.z += rr.z; r.w += rr.w;
            }
            *(float4*)(Cout + rb + col) = r;
        }
    }
}

// ---------------- Flash attention (fp32, non-causal, full softmax) ----------------
// grid: (T/64, B*H); block 256 (16x16 threads, 4x4 outputs each)
// smem: Qt[64][68] (d-major), Kt[64][68] (d-major), Vs[64][68] (token-major), Ps[64][68]
#define APITCH 68
__global__ void __launch_bounds__(256) attn_kernel(
    const float* __restrict__ q, const float* __restrict__ k,
    const float* __restrict__ v, float* __restrict__ y)
{
    extern __shared__ float smdyn[];
    float* Qt = smdyn;
    float* Kt = Qt + 64 * APITCH;
    float* Vs = Kt + 64 * APITCH;
    float* Ps = Vs + 64 * APITCH;

    const int bh = blockIdx.y;
    const int b = bh >> 4, h = bh & 15;
    const int qbase = blockIdx.x * 64;
    const int t = threadIdx.x;
    const int tx4 = (t & 15) * 4, ty4 = (t >> 4) * 4;
    const int rr = t >> 2, l4 = t & 3;

    const float* qb = q + (size_t)b * T_ * C_ + h * DH_;
    const float* kb = k + (size_t)b * T_ * C_ + h * DH_;
    const float* vb = v + (size_t)b * T_ * C_ + h * DH_;

    // Q tile, transposed to d-major, pre-scaled by 1/sqrt(DH)=0.125
    #pragma unroll
    for (int j = 0; j < 4; j++) {
        const int d0 = (l4 + 4 * j) * 4;
        float4 qv = *(const float4*)(qb + (size_t)(qbase + rr) * C_ + d0);
        Qt[(d0+0)*APITCH + rr] = qv.x * 0.125f;
        Qt[(d0+1)*APITCH + rr] = qv.y * 0.125f;
        Qt[(d0+2)*APITCH + rr] = qv.z * 0.125f;
        Qt[(d0+3)*APITCH + rr] = qv.w * 0.125f;
    }

    float m_[4], l_[4], acc[4][4];
    #pragma unroll
    for (int i = 0; i < 4; i++) {
        m_[i] = -1e30f; l_[i] = 0.f;
        #pragma unroll
        for (int j = 0; j < 4; j++) acc[i][j] = 0.f;
    }

    for (int kt0 = 0; kt0 < T_; kt0 += 64) {
        float4 kr[4], vr[4];
        #pragma unroll
        for (int j = 0; j < 4; j++) {
            const int d0 = (l4 + 4 * j) * 4;
            kr[j] = *(const float4*)(kb + (size_t)(kt0 + rr) * C_ + d0);
            vr[j] = *(const float4*)(vb + (size_t)(kt0 + rr) * C_ + d0);
        }
        __syncthreads();   // previous tile's P/V reads complete
        #pragma unroll
        for (int j = 0; j < 4; j++) {
            const int d0 = (l4 + 4 * j) * 4;
            Kt[(d0+0)*APITCH + rr] = kr[j].x;
            Kt[(d0+1)*APITCH + rr] = kr[j].y;
            Kt[(d0+2)*APITCH + rr] = kr[j].z;
            Kt[(d0+3)*APITCH + rr] = kr[j].w;
            *(float4*)&Vs[rr * APITCH + d0] = vr[j];
        }
        __syncthreads();

        float s[4][4];
        #pragma unroll
        for (int i = 0; i < 4; i++)
            #pragma unroll
            for (int j = 0; j < 4; j++) s[i][j] = 0.f;

        #pragma unroll 4
        for (int d = 0; d < 64; d++) {
            float4 qf = *(const float4*)&Qt[d * APITCH + ty4];
            float4 kf = *(const float4*)&Kt[d * APITCH + tx4];
            float qa[4] = {qf.x, qf.y, qf.z, qf.w};
            float ka[4] = {kf.x, kf.y, kf.z, kf.w};
            #pragma unroll
            for (int i = 0; i < 4; i++)
                #pragma unroll
                for (int j = 0; j < 4; j++)
                    s[i][j] = fmaf(qa[i], ka[j], s[i][j]);
        }

        // online softmax (row groups are 16-lane half-warps: xor 1,2,4,8)
        #pragma unroll
        for (int i = 0; i < 4; i++) {
            float tm = fmaxf(fmaxf(s[i][0], s[i][1]), fmaxf(s[i][2], s[i][3]));
            tm = fmaxf(tm, __shfl_xor_sync(0xffffffffu, tm, 1));
            tm = fmaxf(tm, __shfl_xor_sync(0xffffffffu, tm, 2));
            tm = fmaxf(tm, __shfl_xor_sync(0xffffffffu, tm, 4));
            tm = fmaxf(tm, __shfl_xor_sync(0xffffffffu, tm, 8));
            const float mn = fmaxf(m_[i], tm);
            const float corr = __expf(m_[i] - mn);
            m_[i] = mn;
            float rs = 0.f;
            #pragma unroll
            for (int j = 0; j < 4; j++) {
                s[i][j] = __expf(s[i][j] - mn);
                rs += s[i][j];
            }
            rs += __shfl_xor_sync(0xffffffffu, rs, 1);
            rs += __shfl_xor_sync(0xffffffffu, rs, 2);
            rs += __shfl_xor_sync(0xffffffffu, rs, 4);
            rs += __shfl_xor_sync(0xffffffffu, rs, 8);
            l_[i] = l_[i] * corr + rs;
            #pragma unroll
            for (int j = 0; j < 4; j++) acc[i][j] *= corr;
            *(float4*)&Ps[(ty4 + i) * APITCH + tx4] =
                make_float4(s[i][0], s[i][1], s[i][2], s[i][3]);
        }
        __syncthreads();

        #pragma unroll 2
        for (int j = 0; j < 64; j++) {
            float4 vf = *(const float4*)&Vs[j * APITCH + tx4];
            #pragma unroll
            for (int i = 0; i < 4; i++) {
                const float p = Ps[(ty4 + i) * APITCH + j];
                acc[i][0] = fmaf(p, vf.x, acc[i][0]);
                acc[i][1] = fmaf(p, vf.y, acc[i][1]);
                acc[i][2] = fmaf(p, vf.z, acc[i][2]);
                acc[i][3] = fmaf(p, vf.w, acc[i][3]);
            }
        }
    }

    #pragma unroll
    for (int i = 0; i < 4; i++) {
        const float inv = 1.0f / l_[i];
        const int row = qbase + ty4 + i;
        float4 o = make_float4(acc[i][0]*inv, acc[i][1]*inv, acc[i][2]*inv, acc[i][3]*inv);
        *(float4*)(y + (size_t)(b * T_ + row) * C_ + h * DH_ + tx4) = o;
    }
}

// ---------------- orchestration ----------------
extern "C" void kernel_launch(void* const* d_in, const int* in_sizes, int n_in,
                              void* d_out, int out_size)
{
    const float* seq  = (const float*)d_in[0];
    const float* pos  = (const float*)d_in[1];
    const float* Wq   = (const float*)d_in[2];
    const float* bq   = (const float*)d_in[3];
    const float* Wk   = (const float*)d_in[4];
    const float* bk   = (const float*)d_in[5];
    const float* Wv   = (const float*)d_in[6];
    const float* bv   = (const float*)d_in[7];
    const float* Wo   = (const float*)d_in[8];
    const float* bo   = (const float*)d_in[9];
    const float* ln1w = (const float*)d_in[10];
    const float* ln1b = (const float*)d_in[11];
    const float* ln2w = (const float*)d_in[12];
    const float* ln2b = (const float*)d_in[13];
    const float* W1   = (const float*)d_in[14];
    const float* b1   = (const float*)d_in[15];
    const float* W2   = (const float*)d_in[16];
    const float* b2   = (const float*)d_in[17];
    const float* lnfw = (const float*)d_in[18];
    const float* lnfb = (const float*)d_in[19];
    const float* Wh   = (const float*)d_in[20];
    float* out = (float*)d_out;

    float *px, *ph, *pq, *pk, *pv, *py, *pu;
    cudaGetSymbolAddress((void**)&px, g_x);
    cudaGetSymbolAddress((void**)&ph, g_h);
    cudaGetSymbolAddress((void**)&pq, g_q);
    cudaGetSymbolAddress((void**)&pk, g_k);
    cudaGetSymbolAddress((void**)&pv, g_v);
    cudaGetSymbolAddress((void**)&py, g_y);
    cudaGetSymbolAddress((void**)&pu, g_u);

    const int attn_smem = 4 * 64 * APITCH * (int)sizeof(float);  // 69632 B
    cudaFuncSetAttribute(attn_kernel, cudaFuncAttributeMaxDynamicSharedMemorySize, attn_smem);

    addpos_kernel<<<M_ * C_ / 4 / 256, 256>>>(seq, pos, px);

    dim3 gC(C_ / 128, M_ / 128);    // (8, 64)
    dim3 gF(FF_ / 128, M_ / 128);   // (32, 64)
    dim3 gA(T_ / 64, B_ * H_);      // (32, 64)

    for (int l = 0; l < L_; l++) {
        ln_kernel<<<M_, 256>>>(px, ln1w + l * C_, ln1b + l * C_, ph);
        gemm_nt<1><<<gC, 256>>>(ph, Wq + (size_t)l * C_ * C_, bq + l * C_, nullptr, pq, M_, C_, C_);
        gemm_nt<1><<<gC, 256>>>(ph, Wk + (size_t)l * C_ * C_, bk + l * C_, nullptr, pk, M_, C_, C_);
        gemm_nt<1><<<gC, 256>>>(ph, Wv + (size_t)l * C_ * C_, bv + l * C_, nullptr, pv, M_, C_, C_);
        attn_kernel<<<gA, 256, attn_smem>>>(pq, pk, pv, py);
        gemm_nt<3><<<gC, 256>>>(py, Wo + (size_t)l * C_ * C_, bo + l * C_, px, px, M_, C_, C_);
        ln_kernel<<<M_, 256>>>(px, ln2w + l * C_, ln2b + l * C_, ph);
        gemm_nt<2><<<gF, 256>>>(ph, W1 + (size_t)l * FF_ * C_, b1 + l * FF_, nullptr, pu, M_, FF_, C_);
        gemm_nt<3><<<gC, 256>>>(pu, W2 + (size_t)l * C_ * FF_, b2 + l * C_, px, px, M_, C_, FF_);
    }

    ln_kernel<<<M_, 256>>>(px, lnfw, lnfb, ph);
    gemm_nt<0><<<gC, 256>>>(ph, Wh, nullptr, nullptr, out, M_, OUT_, C_);
}

// round 3
// speedup vs baseline: 2.3431x; 2.3431x over previous
#include <cuda_runtime.h>
#include <cuda_fp16.h>
#include <math.h>
#include <stdint.h>

#define L_ 8
#define H_ 16
#define T_ 2048
#define C_ 1024
#define OUT_ 1024
#define B_ 4
#define DH_ 64
#define FF_ 4096
#define M_ (B_*T_)   // 8192 rows

// ---------------- scratch (static device globals; no allocation) ----------------
__device__ float g_x[M_*C_];
__device__ float g_h[M_*C_];
__device__ float g_q[M_*C_];
__device__ float g_k[M_*C_];
__device__ float g_v[M_*C_];
__device__ float g_y[M_*C_];
__device__ float g_u[(size_t)M_*FF_];

// ================= helpers =================
__device__ __forceinline__ uint32_t smem_u32(const void* p) {
    uint32_t a;
    asm("{ .reg .u64 t; cvta.to.shared.u64 t, %1; cvt.u32.u64 %0, t; }" : "=r"(a) : "l"(p));
    return a;
}

__device__ __forceinline__ void mma16816(float* c, const uint32_t* a, uint32_t b0, uint32_t b1) {
    asm volatile(
        "mma.sync.aligned.m16n8k16.row.col.f32.f16.f16.f32 "
        "{%0,%1,%2,%3}, {%4,%5,%6,%7}, {%8,%9}, {%0,%1,%2,%3};"
        : "+f"(c[0]), "+f"(c[1]), "+f"(c[2]), "+f"(c[3])
        : "r"(a[0]), "r"(a[1]), "r"(a[2]), "r"(a[3]), "r"(b0), "r"(b1));
}
__device__ __forceinline__ void ldsm4(uint32_t* r, uint32_t addr) {
    asm volatile("ldmatrix.sync.aligned.m8n8.x4.shared.b16 {%0,%1,%2,%3}, [%4];"
                 : "=r"(r[0]), "=r"(r[1]), "=r"(r[2]), "=r"(r[3]) : "r"(addr));
}
__device__ __forceinline__ void ldsm4t(uint32_t* r, uint32_t addr) {
    asm volatile("ldmatrix.sync.aligned.m8n8.x4.trans.shared.b16 {%0,%1,%2,%3}, [%4];"
                 : "=r"(r[0]), "=r"(r[1]), "=r"(r[2]), "=r"(r[3]) : "r"(addr));
}

// fp32 pair -> fp16 hi + fp16 lo (packed half2 each)
__device__ __forceinline__ void split2(float x, float y, uint32_t& h, uint32_t& l) {
    __half2 hh = __floats2half2_rn(x, y);
    float2 hf = __half22float2(hh);
    __half2 ll = __floats2half2_rn(x - hf.x, y - hf.y);
    h = *(uint32_t*)&hh;
    l = *(uint32_t*)&ll;
}

__device__ __forceinline__ float gelu_exact(float v) {
    return 0.5f * v * (1.0f + erff(v * 0.70710678118654752f));
}

// ================= split-fp16 mma.sync GEMM =================
// D[M,N] = A[M,K] @ W[N,K]^T (+epilogue). Tile 128x128, K-chunk 32, dbl-buffered smem.
// Per buffer (40960B): Ah[128x32] pitch 80B, Al +10240, Bh +20480, Bl +30720.
// EPI: 0=none, 1=+bias, 2=+bias+GELU, 3=+bias+residual
#define GEMM_BUF 40960
#define GEMM_SMEM (2*GEMM_BUF)

__device__ __forceinline__ void store_stage(char* smp, uint32_t sto,
                                            const float4* sa, const float4* sbv) {
    uint32_t h[8], l[8];
    #pragma unroll
    for (int i = 0; i < 4; i++) {
        split2(sa[i].x, sa[i].y, h[2*i], l[2*i]);
        split2(sa[i].z, sa[i].w, h[2*i+1], l[2*i+1]);
    }
    *(uint4*)(smp + sto)          = make_uint4(h[0],h[1],h[2],h[3]);
    *(uint4*)(smp + sto + 16)     = make_uint4(h[4],h[5],h[6],h[7]);
    *(uint4*)(smp + 10240 + sto)      = make_uint4(l[0],l[1],l[2],l[3]);
    *(uint4*)(smp + 10240 + sto + 16) = make_uint4(l[4],l[5],l[6],l[7]);
    #pragma unroll
    for (int i = 0; i < 4; i++) {
        split2(sbv[i].x, sbv[i].y, h[2*i], l[2*i]);
        split2(sbv[i].z, sbv[i].w, h[2*i+1], l[2*i+1]);
    }
    *(uint4*)(smp + 20480 + sto)      = make_uint4(h[0],h[1],h[2],h[3]);
    *(uint4*)(smp + 20480 + sto + 16) = make_uint4(h[4],h[5],h[6],h[7]);
    *(uint4*)(smp + 30720 + sto)      = make_uint4(l[0],l[1],l[2],l[3]);
    *(uint4*)(smp + 30720 + sto + 16) = make_uint4(l[4],l[5],l[6],l[7]);
}

template <int EPI>
__global__ void __launch_bounds__(256) gemm_mma(
    const float* __restrict__ A, const float* __restrict__ Bw,
    const float* __restrict__ bias, const float* __restrict__ resid,
    float* __restrict__ Cout, int M, int N, int K)
{
    extern __shared__ char sm[];
    const uint32_t sb = smem_u32(sm);
    const int t = threadIdx.x;
    const int w = t >> 5, lane = t & 31;
    const int bm = blockIdx.y, bn = blockIdx.x;
    const int wm = w & 3, wn = w >> 2;

    const int lr  = t >> 1;          // 0..127
    const int lkb = (t & 1) * 16;    // 0 or 16 (float offset)
    const float* Ap = A  + (size_t)(bm*128 + lr) * K + lkb;
    const float* Bp = Bw + (size_t)(bn*128 + lr) * K + lkb;
    const uint32_t sto = (uint32_t)lr * 80u + (uint32_t)lkb * 2u;

    // ldmatrix per-lane byte offsets (without ks term)
    const uint32_t a_off = (uint32_t)((wm*32 + (lane&7) + ((lane>>3)&1)*8) * 80 + (lane>>4)*16);
    const uint32_t b_off = (uint32_t)((wn*64 + (lane&7) + (lane>>4)*8) * 80 + ((lane>>3)&1)*16);

    float acc[2][8][4];
    #pragma unroll
    for (int i = 0; i < 2; i++)
        #pragma unroll
        for (int j = 0; j < 8; j++)
            #pragma unroll
            for (int r = 0; r < 4; r++) acc[i][j][r] = 0.f;

    float4 stgA[4], stgB[4];
    #pragma unroll
    for (int i = 0; i < 4; i++) { stgA[i] = *(const float4*)(Ap + 4*i); stgB[i] = *(const float4*)(Bp + 4*i); }
    store_stage(sm, sto, stgA, stgB);
    __syncthreads();

    const int NC = K >> 5;
    for (int c = 0; c < NC; c++) {
        const int bsel = c & 1;
        if (c + 1 < NC) {
            const float* Ap2 = Ap + (size_t)(c+1) * 32;
            const float* Bp2 = Bp + (size_t)(c+1) * 32;
            #pragma unroll
            for (int i = 0; i < 4; i++) { stgA[i] = *(const float4*)(Ap2 + 4*i); stgB[i] = *(const float4*)(Bp2 + 4*i); }
        }
        const uint32_t bufb = sb + (uint32_t)bsel * GEMM_BUF;
        #pragma unroll
        for (int ks = 0; ks < 2; ks++) {
            uint32_t ah[2][4], al[2][4];
            #pragma unroll
            for (int mt = 0; mt < 2; mt++) {
                ldsm4(ah[mt], bufb + a_off + mt*16*80 + ks*32);
                ldsm4(al[mt], bufb + 10240 + a_off + mt*16*80 + ks*32);
            }
            uint32_t bh[4][4], bl[4][4];
            #pragma unroll
            for (int nq = 0; nq < 4; nq++) {
                ldsm4(bh[nq], bufb + 20480 + b_off + nq*16*80 + ks*32);
                ldsm4(bl[nq], bufb + 30720 + b_off + nq*16*80 + ks*32);
            }
            #pragma unroll
            for (int mt = 0; mt < 2; mt++)
                #pragma unroll
                for (int nt = 0; nt < 8; nt++) {
                    const int nq = nt >> 1, s2 = (nt & 1) * 2;
                    mma16816(acc[mt][nt], ah[mt], bh[nq][s2], bh[nq][s2+1]);
                    mma16816(acc[mt][nt], ah[mt], bl[nq][s2], bl[nq][s2+1]);
                    mma16816(acc[mt][nt], al[mt], bh[nq][s2], bh[nq][s2+1]);
                }
        }
        __syncthreads();
        if (c + 1 < NC) {
            store_stage(sm + (bsel^1) * GEMM_BUF, sto, stgA, stgB);
            __syncthreads();
        }
    }

    // ---- epilogue ----
    const int grbase = bm*128 + wm*32;
    const int gcbase = bn*128 + wn*64;
    #pragma unroll
    for (int mt = 0; mt < 2; mt++) {
        const int r0 = grbase + mt*16 + (lane >> 2);
        #pragma unroll
        for (int nt = 0; nt < 8; nt++) {
            const int gc = gcbase + nt*8 + (lane & 3)*2;
            float2 v0 = make_float2(acc[mt][nt][0], acc[mt][nt][1]);
            float2 v1 = make_float2(acc[mt][nt][2], acc[mt][nt][3]);
            if (EPI >= 1) {
                float2 bb = *(const float2*)(bias + gc);
                v0.x += bb.x; v0.y += bb.y; v1.x += bb.x; v1.y += bb.y;
            }
            if (EPI == 2) {
                v0.x = gelu_exact(v0.x); v0.y = gelu_exact(v0.y);
                v1.x = gelu_exact(v1.x); v1.y = gelu_exact(v1.y);
            }
            if (EPI == 3) {
                float2 ra = *(const float2*)(resid + (size_t)r0 * N + gc);
                float2 rb = *(const float2*)(resid + (size_t)(r0+8) * N + gc);
                v0.x += ra.x; v0.y += ra.y; v1.x += rb.x; v1.y += rb.y;
            }
            *(float2*)(Cout + (size_t)r0 * N + gc) = v0;
            *(float2*)(Cout + (size_t)(r0+8) * N + gc) = v1;
        }
    }
}

// ================= flash attention on mma.sync (split-fp16) =================
// Block: 256 thr (8 warps), Q tile 128 rows (16/warp), KV tile 64, DH=64.
// smem: Qh[128][64] pitch144, Ql, Kh[64][64] p144, Kl, Vh, Vl
#define SQH 0
#define SQL 18432
#define SKH 36864
#define SKL 46080
#define SVH 55296
#define SVL 64512
#define ATT_SMEM 73728

__global__ void __launch_bounds__(256) attn_mma(
    const float* __restrict__ q, const float* __restrict__ k,
    const float* __restrict__ v, float* __restrict__ y)
{
    extern __shared__ char sm[];
    const uint32_t sb = smem_u32(sm);
    const int t = threadIdx.x, w = t >> 5, lane = t & 31;
    const int bh = blockIdx.y, b = bh >> 4, h = bh & 15;
    const int q0 = blockIdx.x * 128;

    // ---- load Q tile (scaled by 1/8), split to hi/lo fp16 ----
    {
        const int qr = t >> 1, qc = (t & 1) * 32;
        const float* qg = q + (size_t)(b*T_ + q0 + qr) * C_ + h*64 + qc;
        uint32_t hh[16], ll[16];
        #pragma unroll
        for (int i = 0; i < 8; i++) {
            float4 f = *(const float4*)(qg + 4*i);
            split2(f.x*0.125f, f.y*0.125f, hh[2*i], ll[2*i]);
            split2(f.z*0.125f, f.w*0.125f, hh[2*i+1], ll[2*i+1]);
        }
        const uint32_t o = (uint32_t)qr*144u + (uint32_t)qc*2u;
        #pragma unroll
        for (int i = 0; i < 4; i++) {
            *(uint4*)(sm + SQH + o + 16*i) = make_uint4(hh[4*i],hh[4*i+1],hh[4*i+2],hh[4*i+3]);
            *(uint4*)(sm + SQL + o + 16*i) = make_uint4(ll[4*i],ll[4*i+1],ll[4*i+2],ll[4*i+3]);
        }
    }
    __syncthreads();

    // ---- Q fragments in registers ----
    uint32_t qh[4][4], ql[4][4];
    const uint32_t a_off = (uint32_t)((w*16 + (lane&7) + ((lane>>3)&1)*8) * 144 + (lane>>4)*16);
    #pragma unroll
    for (int ks = 0; ks < 4; ks++) {
        ldsm4(qh[ks], sb + SQH + a_off + ks*32);
        ldsm4(ql[ks], sb + SQL + a_off + ks*32);
    }

    float o_[8][4];
    #pragma unroll
    for (int i = 0; i < 8; i++)
        #pragma unroll
        for (int j = 0; j < 4; j++) o_[i][j] = 0.f;
    float m_a = -1e30f, m_b = -1e30f, l_a = 0.f, l_b = 0.f;

    const uint32_t kb_off = (uint32_t)(((lane&7) + (lane>>4)*8) * 144 + ((lane>>3)&1)*16);
    const uint32_t vb_off = (uint32_t)(((lane&7) + ((lane>>3)&1)*8) * 144 + (lane>>4)*16);

    const int kvr = t >> 2, kvc = (t & 3) * 16;
    const float* kg = k + (size_t)(b*T_ + kvr) * C_ + h*64 + kvc;
    const float* vg = v + (size_t)(b*T_ + kvr) * C_ + h*64 + kvc;
    const uint32_t kvo = (uint32_t)kvr*144u + (uint32_t)kvc*2u;

    for (int kt = 0; kt < T_/64; kt++) {
        // ---- fill K/V tile (hi/lo split) ----
        {
            uint32_t hh[8], ll[8];
            const float* kp = kg + (size_t)kt * 64 * C_;
            #pragma unroll
            for (int i = 0; i < 4; i++) {
                float4 f = *(const float4*)(kp + 4*i);
                split2(f.x, f.y, hh[2*i], ll[2*i]);
                split2(f.z, f.w, hh[2*i+1], ll[2*i+1]);
            }
            *(uint4*)(sm + SKH + kvo)      = make_uint4(hh[0],hh[1],hh[2],hh[3]);
            *(uint4*)(sm + SKH + kvo + 16) = make_uint4(hh[4],hh[5],hh[6],hh[7]);
            *(uint4*)(sm + SKL + kvo)      = make_uint4(ll[0],ll[1],ll[2],ll[3]);
            *(uint4*)(sm + SKL + kvo + 16) = make_uint4(ll[4],ll[5],ll[6],ll[7]);
            const float* vp = vg + (size_t)kt * 64 * C_;
            #pragma unroll
            for (int i = 0; i < 4; i++) {
                float4 f = *(const float4*)(vp + 4*i);
                split2(f.x, f.y, hh[2*i], ll[2*i]);
                split2(f.z, f.w, hh[2*i+1], ll[2*i+1]);
            }
            *(uint4*)(sm + SVH + kvo)      = make_uint4(hh[0],hh[1],hh[2],hh[3]);
            *(uint4*)(sm + SVH + kvo + 16) = make_uint4(hh[4],hh[5],hh[6],hh[7]);
            *(uint4*)(sm + SVL + kvo)      = make_uint4(ll[0],ll[1],ll[2],ll[3]);
            *(uint4*)(sm + SVL + kvo + 16) = make_uint4(ll[4],ll[5],ll[6],ll[7]);
        }
        __syncthreads();

        // ---- S = Q K^T (3-pass split) ----
        float sc[8][4];
        #pragma unroll
        for (int i = 0; i < 8; i++)
            #pragma unroll
            for (int j = 0; j < 4; j++) sc[i][j] = 0.f;
        #pragma unroll
        for (int ks = 0; ks < 4; ks++) {
            uint32_t kh4[4][4], kl4[4][4];
            #pragma unroll
            for (int nq = 0; nq < 4; nq++) {
                ldsm4(kh4[nq], sb + SKH + kb_off + nq*16*144 + ks*32);
                ldsm4(kl4[nq], sb + SKL + kb_off + nq*16*144 + ks*32);
            }
            #pragma unroll
            for (int nt = 0; nt < 8; nt++) {
                const int nq = nt >> 1, s2 = (nt & 1) * 2;
                mma16816(sc[nt], qh[ks], kh4[nq][s2], kh4[nq][s2+1]);
                mma16816(sc[nt], qh[ks], kl4[nq][s2], kl4[nq][s2+1]);
                mma16816(sc[nt], ql[ks], kh4[nq][s2], kh4[nq][s2+1]);
            }
        }

        // ---- online softmax ----
        float mxa = -1e30f, mxb = -1e30f;
        #pragma unroll
        for (int nt = 0; nt < 8; nt++) {
            mxa = fmaxf(mxa, fmaxf(sc[nt][0], sc[nt][1]));
            mxb = fmaxf(mxb, fmaxf(sc[nt][2], sc[nt][3]));
        }
        mxa = fmaxf(mxa, __shfl_xor_sync(0xffffffffu, mxa, 1));
        mxa = fmaxf(mxa, __shfl_xor_sync(0xffffffffu, mxa, 2));
        mxb = fmaxf(mxb, __shfl_xor_sync(0xffffffffu, mxb, 1));
        mxb = fmaxf(mxb, __shfl_xor_sync(0xffffffffu, mxb, 2));
        const float nma = fmaxf(m_a, mxa), nmb = fmaxf(m_b, mxb);
        const float ca = __expf(m_a - nma), cb = __expf(m_b - nmb);
        m_a = nma; m_b = nmb;
        float rsa = 0.f, rsb = 0.f;
        #pragma unroll
        for (int nt = 0; nt < 8; nt++) {
            sc[nt][0] = __expf(sc[nt][0] - m_a); rsa += sc[nt][0];
            sc[nt][1] = __expf(sc[nt][1] - m_a); rsa += sc[nt][1];
            sc[nt][2] = __expf(sc[nt][2] - m_b); rsb += sc[nt][2];
            sc[nt][3] = __expf(sc[nt][3] - m_b); rsb += sc[nt][3];
        }
        rsa += __shfl_xor_sync(0xffffffffu, rsa, 1);
        rsa += __shfl_xor_sync(0xffffffffu, rsa, 2);
        rsb += __shfl_xor_sync(0xffffffffu, rsb, 1);
        rsb += __shfl_xor_sync(0xffffffffu, rsb, 2);
        l_a = l_a * ca + rsa;
        l_b = l_b * cb + rsb;
        #pragma unroll
        for (int dt = 0; dt < 8; dt++) {
            o_[dt][0] *= ca; o_[dt][1] *= ca; o_[dt][2] *= cb; o_[dt][3] *= cb;
        }

        // ---- O += P V (3-pass split) ----
        #pragma unroll
        for (int ks = 0; ks < 4; ks++) {
            uint32_t ph[4], pl[4];
            split2(sc[2*ks][0],   sc[2*ks][1],   ph[0], pl[0]);
            split2(sc[2*ks][2],   sc[2*ks][3],   ph[1], pl[1]);
            split2(sc[2*ks+1][0], sc[2*ks+1][1], ph[2], pl[2]);
            split2(sc[2*ks+1][2], sc[2*ks+1][3], ph[3], pl[3]);
            uint32_t vh4[4][4], vl4[4][4];
            #pragma unroll
            for (int nq = 0; nq < 4; nq++) {
                ldsm4t(vh4[nq], sb + SVH + vb_off + ks*16*144 + nq*32);
                ldsm4t(vl4[nq], sb + SVL + vb_off + ks*16*144 + nq*32);
            }
            #pragma unroll
            for (int dt = 0; dt < 8; dt++) {
                const int nq = dt >> 1, s2 = (dt & 1) * 2;
                mma16816(o_[dt], ph, vh4[nq][s2], vh4[nq][s2+1]);
                mma16816(o_[dt], ph, vl4[nq][s2], vl4[nq][s2+1]);
                mma16816(o_[dt], pl, vh4[nq][s2], vh4[nq][s2+1]);
            }
        }
        __syncthreads();
    }

    // ---- write y ----
    const float ia = 1.f / l_a, ib = 1.f / l_b;
    const int r0 = q0 + w*16 + (lane >> 2);
    float* yb = y + (size_t)(b*T_ + r0) * C_ + h*64;
    #pragma unroll
    for (int dt = 0; dt < 8; dt++) {
        const int gc = dt*8 + (lane & 3)*2;
        *(float2*)(yb + gc) = make_float2(o_[dt][0]*ia, o_[dt][1]*ia);
        *(float2*)(yb + (size_t)8*C_ + gc) = make_float2(o_[dt][2]*ib, o_[dt][3]*ib);
    }
}

// ---------------- x = seq + pos ----------------
__global__ void __launch_bounds__(256) addpos_kernel(
    const float* __restrict__ seq, const float* __restrict__ pos, float* __restrict__ x)
{
    int i = blockIdx.x * 256 + threadIdx.x;
    float4 s = ((const float4*)seq)[i];
    float4 p = ((const float4*)pos)[i & (T_*C_/4 - 1)];
    s.x += p.x; s.y += p.y; s.z += p.z; s.w += p.w;
    ((float4*)x)[i] = s;
}

// ---------------- LayerNorm ----------------
__global__ void __launch_bounds__(256) ln_kernel(
    const float* __restrict__ x, const float* __restrict__ w,
    const float* __restrict__ b, float* __restrict__ out)
{
    const int row = blockIdx.x;
    const int t = threadIdx.x;
    const float4 v = *(const float4*)(x + (size_t)row * C_ + t * 4);
    float s  = v.x + v.y + v.z + v.w;
    float sq = v.x*v.x + v.y*v.y + v.z*v.z + v.w*v.w;
    #pragma unroll
    for (int off = 16; off; off >>= 1) {
        s  += __shfl_xor_sync(0xffffffffu, s,  off);
        sq += __shfl_xor_sync(0xffffffffu, sq, off);
    }
    __shared__ float rs_[8], rq_[8];
    if ((t & 31) == 0) { rs_[t >> 5] = s; rq_[t >> 5] = sq; }
    __syncthreads();
    s = 0.f; sq = 0.f;
    #pragma unroll
    for (int i = 0; i < 8; i++) { s += rs_[i]; sq += rq_[i]; }
    const float mu   = s * (1.0f / 1024.0f);
    const float var  = sq * (1.0f / 1024.0f) - mu * mu;
    const float rstd = rsqrtf(var + 1e-5f);
    const float4 wv = *(const float4*)(w + t * 4);
    const float4 bv = *(const float4*)(b + t * 4);
    float4 o;
    o.x = (v.x - mu) * rstd * wv.x + bv.x;
    o.y = (v.y - mu) * rstd * wv.y + bv.y;
    o.z = (v.z - mu) * rstd * wv.z + bv.z;
    o.w = (v.w - mu) * rstd * wv.w + bv.w;
    *(float4*)(out + (size_t)row * C_ + t * 4) = o;
}

// ---------------- orchestration ----------------
extern "C" void kernel_launch(void* const* d_in, const int* in_sizes, int n_in,
                              void* d_out, int out_size)
{
    const float* seq  = (const float*)d_in[0];
    const float* pos  = (const float*)d_in[1];
    const float* Wq   = (const float*)d_in[2];
    const float* bq   = (const float*)d_in[3];
    const float* Wk   = (const float*)d_in[4];
    const float* bk   = (const float*)d_in[5];
    const float* Wv   = (const float*)d_in[6];
    const float* bv   = (const float*)d_in[7];
    const float* Wo   = (const float*)d_in[8];
    const float* bo   = (const float*)d_in[9];
    const float* ln1w = (const float*)d_in[10];
    const float* ln1b = (const float*)d_in[11];
    const float* ln2w = (const float*)d_in[12];
    const float* ln2b = (const float*)d_in[13];
    const float* W1   = (const float*)d_in[14];
    const float* b1   = (const float*)d_in[15];
    const float* W2   = (const float*)d_in[16];
    const float* b2   = (const float*)d_in[17];
    const float* lnfw = (const float*)d_in[18];
    const float* lnfb = (const float*)d_in[19];
    const float* Wh   = (const float*)d_in[20];
    float* out = (float*)d_out;

    float *px, *ph, *pq, *pk, *pv, *py, *pu;
    cudaGetSymbolAddress((void**)&px, g_x);
    cudaGetSymbolAddress((void**)&ph, g_h);
    cudaGetSymbolAddress((void**)&pq, g_q);
    cudaGetSymbolAddress((void**)&pk, g_k);
    cudaGetSymbolAddress((void**)&pv, g_v);
    cudaGetSymbolAddress((void**)&py, g_y);
    cudaGetSymbolAddress((void**)&pu, g_u);

    cudaFuncSetAttribute(attn_mma, cudaFuncAttributeMaxDynamicSharedMemorySize, ATT_SMEM);
    cudaFuncSetAttribute(gemm_mma<0>, cudaFuncAttributeMaxDynamicSharedMemorySize, GEMM_SMEM);
    cudaFuncSetAttribute(gemm_mma<1>, cudaFuncAttributeMaxDynamicSharedMemorySize, GEMM_SMEM);
    cudaFuncSetAttribute(gemm_mma<2>, cudaFuncAttributeMaxDynamicSharedMemorySize, GEMM_SMEM);
    cudaFuncSetAttribute(gemm_mma<3>, cudaFuncAttributeMaxDynamicSharedMemorySize, GEMM_SMEM);

    addpos_kernel<<<M_ * C_ / 4 / 256, 256>>>(seq, pos, px);

    dim3 gC(C_ / 128, M_ / 128);    // (8, 64)
    dim3 gF(FF_ / 128, M_ / 128);   // (32, 64)
    dim3 gA(T_ / 128, B_ * H_);     // (16, 64)

    for (int l = 0; l < L_; l++) {
        ln_kernel<<<M_, 256>>>(px, ln1w + l * C_, ln1b + l * C_, ph);
        gemm_mma<1><<<gC, 256, GEMM_SMEM>>>(ph, Wq + (size_t)l * C_ * C_, bq + l * C_, nullptr, pq, M_, C_, C_);
        gemm_mma<1><<<gC, 256, GEMM_SMEM>>>(ph, Wk + (size_t)l * C_ * C_, bk + l * C_, nullptr, pk, M_, C_, C_);
        gemm_mma<1><<<gC, 256, GEMM_SMEM>>>(ph, Wv + (size_t)l * C_ * C_, bv + l * C_, nullptr, pv, M_, C_, C_);
        attn_mma<<<gA, 256, ATT_SMEM>>>(pq, pk, pv, py);
        gemm_mma<3><<<gC, 256, GEMM_SMEM>>>(py, Wo + (size_t)l * C_ * C_, bo + l * C_, px, px, M_, C_, C_);
        ln_kernel<<<M_, 256>>>(px, ln2w + l * C_, ln2b + l * C_, ph);
        gemm_mma<2><<<gF, 256, GEMM_SMEM>>>(ph, W1 + (size_t)l * FF_ * C_, b1 + l * FF_, nullptr, pu, M_, FF_, C_);
        gemm_mma<3><<<gC, 256, GEMM_SMEM>>>(pu, W2 + (size_t)l * C_ * FF_, b2 + l * C_, px, px, M_, C_, FF_);
    }

    ln_kernel<<<M_, 256>>>(px, lnfw, lnfb, ph);
    gemm_mma<0><<<gC, 256, GEMM_SMEM>>>(ph, Wh, nullptr, nullptr, out, M_, OUT_, C_);
}

// round 5
// speedup vs baseline: 2.7104x; 1.1568x over previous
#include <cuda_runtime.h>
#include <cuda_fp16.h>
#include <math.h>
#include <stdint.h>

#define L_ 8
#define H_ 16
#define T_ 2048
#define C_ 1024
#define OUT_ 1024
#define B_ 4
#define DH_ 64
#define FF_ 4096
#define M_ (B_*T_)   // 8192 rows

#define CC_ (C_*C_)                   // 1048576
#define WPL_ (12*CC_)                 // weights per layer (halves)
#define WOFF_QKV 0
#define WOFF_WO  (3*CC_)
#define WOFF_W1  (4*CC_)
#define WOFF_W2  (8*CC_)
#define WHEAD_OFF ((size_t)L_*WPL_)   // 100663296
#define WTOT (WHEAD_OFF + CC_)

// ---------------- scratch (static device globals) ----------------
__device__ float g_x[M_*C_];
__device__ __align__(16) __half g_hh[M_*C_],  g_hl[M_*C_];
__device__ __align__(16) __half g_qkvh[3*M_*C_], g_qkvl[3*M_*C_];
__device__ __align__(16) __half g_yh[M_*C_],  g_yl[M_*C_];
__device__ __align__(16) __half g_uh[(size_t)M_*FF_], g_ul[(size_t)M_*FF_];
__device__ __align__(16) __half g_wh[WTOT],   g_wl[WTOT];
__device__ float g_bqkv[L_*3*C_];

// ================= helpers =================
__device__ __forceinline__ uint32_t smem_u32(const void* p) {
    uint32_t a;
    asm("{ .reg .u64 t; cvta.to.shared.u64 t, %1; cvt.u32.u64 %0, t; }" : "=r"(a) : "l"(p));
    return a;
}
__device__ __forceinline__ void mma16816(float* c, const uint32_t* a, uint32_t b0, uint32_t b1) {
    asm volatile(
        "mma.sync.aligned.m16n8k16.row.col.f32.f16.f16.f32 "
        "{%0,%1,%2,%3}, {%4,%5,%6,%7}, {%8,%9}, {%0,%1,%2,%3};"
        : "+f"(c[0]), "+f"(c[1]), "+f"(c[2]), "+f"(c[3])
        : "r"(a[0]), "r"(a[1]), "r"(a[2]), "r"(a[3]), "r"(b0), "r"(b1));
}
__device__ __forceinline__ void ldsm4(uint32_t* r, uint32_t addr) {
    asm volatile("ldmatrix.sync.aligned.m8n8.x4.shared.b16 {%0,%1,%2,%3}, [%4];"
                 : "=r"(r[0]), "=r"(r[1]), "=r"(r[2]), "=r"(r[3]) : "r"(addr));
}
__device__ __forceinline__ void ldsm4t(uint32_t* r, uint32_t addr) {
    asm volatile("ldmatrix.sync.aligned.m8n8.x4.trans.shared.b16 {%0,%1,%2,%3}, [%4];"
                 : "=r"(r[0]), "=r"(r[1]), "=r"(r[2]), "=r"(r[3]) : "r"(addr));
}
#define CP_ASYNC16(dst, src) \
    asm volatile("cp.async.cg.shared.global [%0], [%1], 16;" :: "r"(dst), "l"(src))
#define CP_COMMIT asm volatile("cp.async.commit_group;" ::: "memory")
#define CP_WAIT(n) asm volatile("cp.async.wait_group %0;" :: "n"(n) : "memory")

__device__ __forceinline__ void split2(float x, float y, uint32_t& h, uint32_t& l) {
    __half2 hh = __floats2half2_rn(x, y);
    float2 hf = __half22float2(hh);
    __half2 ll = __floats2half2_rn(x - hf.x, y - hf.y);
    h = *(uint32_t*)&hh;
    l = *(uint32_t*)&ll;
}
__device__ __forceinline__ float gelu_exact(float v) {
    return 0.5f * v * (1.0f + erff(v * 0.70710678118654752f));
}

// ================= weight conversion =================
__global__ void __launch_bounds__(256) conv_w(
    const float* __restrict__ s, __half* __restrict__ dh, __half* __restrict__ dl)
{
    int i = (blockIdx.x * 256 + threadIdx.x) * 8;
    float4 a = *(const float4*)(s + i), b = *(const float4*)(s + i + 4);
    uint32_t h[4], l[4];
    split2(a.x, a.y, h[0], l[0]); split2(a.z, a.w, h[1], l[1]);
    split2(b.x, b.y, h[2], l[2]); split2(b.z, b.w, h[3], l[3]);
    *(uint4*)(dh + i) = make_uint4(h[0], h[1], h[2], h[3]);
    *(uint4*)(dl + i) = make_uint4(l[0], l[1], l[2], l[3]);
}
__global__ void __launch_bounds__(256) packqkvb(
    const float* __restrict__ bq, const float* __restrict__ bk,
    const float* __restrict__ bv, float* __restrict__ dst)
{
    int idx = blockIdx.x * 256 + threadIdx.x;      // L_*3072
    int l = idx / 3072, c = idx % 3072;
    float v = (c < 1024) ? bq[l*1024 + c] : (c < 2048) ? bk[l*1024 + c - 1024]
                                                        : bv[l*1024 + c - 2048];
    dst[idx] = v;
}

// ================= x = seq + pos =================
__global__ void __launch_bounds__(256) addpos_kernel(
    const float* __restrict__ seq, const float* __restrict__ pos, float* __restrict__ x)
{
    int i = blockIdx.x * 256 + threadIdx.x;
    float4 s = ((const float4*)seq)[i];
    float4 p = ((const float4*)pos)[i & (T_*C_/4 - 1)];
    s.x += p.x; s.y += p.y; s.z += p.z; s.w += p.w;
    ((float4*)x)[i] = s;
}

// ================= LayerNorm -> split fp16 =================
__global__ void __launch_bounds__(256) ln_split(
    const float* __restrict__ x, const float* __restrict__ w,
    const float* __restrict__ b, __half* __restrict__ outh, __half* __restrict__ outl)
{
    const int row = blockIdx.x;
    const int t = threadIdx.x;
    const float4 v = *(const float4*)(x + (size_t)row * C_ + t * 4);
    float s  = v.x + v.y + v.z + v.w;
    float sq = v.x*v.x + v.y*v.y + v.z*v.z + v.w*v.w;
    #pragma unroll
    for (int off = 16; off; off >>= 1) {
        s  += __shfl_xor_sync(0xffffffffu, s,  off);
        sq += __shfl_xor_sync(0xffffffffu, sq, off);
    }
    __shared__ float rs_[8], rq_[8];
    if ((t & 31) == 0) { rs_[t >> 5] = s; rq_[t >> 5] = sq; }
    __syncthreads();
    s = 0.f; sq = 0.f;
    #pragma unroll
    for (int i = 0; i < 8; i++) { s += rs_[i]; sq += rq_[i]; }
    const float mu   = s * (1.0f / 1024.0f);
    const float var  = sq * (1.0f / 1024.0f) - mu * mu;
    const float rstd = rsqrtf(var + 1e-5f);
    const float4 wv = *(const float4*)(w + t * 4);
    const float4 bv = *(const float4*)(b + t * 4);
    float ox = (v.x - mu) * rstd * wv.x + bv.x;
    float oy = (v.y - mu) * rstd * wv.y + bv.y;
    float oz = (v.z - mu) * rstd * wv.z + bv.z;
    float ow = (v.w - mu) * rstd * wv.w + bv.w;
    uint32_t h0, l0, h1, l1;
    split2(ox, oy, h0, l0);
    split2(oz, ow, h1, l1);
    *(uint2*)(outh + (size_t)row * C_ + t * 4) = make_uint2(h0, h1);
    *(uint2*)(outl + (size_t)row * C_ + t * 4) = make_uint2(l0, l1);
}

// ================= split-fp16 pipelined GEMM =================
// D[M,N] = A[M,K] @ W[N,K]^T, A/W already split fp16 (h + l). 3-pass MMA.
// Tile 128x128, Kc=64, 3-stage cp.async. Stage 64KB: Ah@0 Al@16K Bh@32K Bl@48K.
// EPI: 0 = fp32 out, 1 = +bias -> qkv split out (N=3072), 2 = +bias+GELU -> split out,
//      3 = +bias+residual -> fp32 out
#define GSTG 65536
#define GEMM_SMEM (3*GSTG)

template <int EPI>
__global__ void __launch_bounds__(256, 1) gemm_h(
    const __half* __restrict__ Ah, const __half* __restrict__ Al,
    const __half* __restrict__ Wh, const __half* __restrict__ Wl,
    const float* __restrict__ bias, const float* __restrict__ resid,
    float* __restrict__ outf, __half* __restrict__ outh, __half* __restrict__ outl,
    int N, int K)
{
    extern __shared__ char sm[];
    const uint32_t sb = smem_u32(sm);
    const int t = threadIdx.x, w = t >> 5, lane = t & 31;
    const int bm = blockIdx.y, bn = blockIdx.x;
    const int wm = w & 3, wn = w >> 2;

    const int crow = t >> 1, chalf = t & 1;
    const __half* agh = Ah + (size_t)(bm*128 + crow) * K + chalf*32;
    const __half* agl = Al + (size_t)(bm*128 + crow) * K + chalf*32;
    const __half* bgh = Wh + (size_t)(bn*128 + crow) * K + chalf*32;
    const __half* bgl = Wl + (size_t)(bn*128 + crow) * K + chalf*32;
    uint32_t dsto[4];
    #pragma unroll
    for (int i = 0; i < 4; i++) {
        int c16 = chalf*4 + i;
        dsto[i] = (uint32_t)(crow*128 + ((c16 ^ (crow & 7)) << 4));
    }
    auto load_stage = [&](int c, int slot) {
        const uint32_t s0 = sb + (uint32_t)slot * GSTG;
        const __half* a0 = agh + c*64;
        const __half* a1 = agl + c*64;
        const __half* b0 = bgh + c*64;
        const __half* b1 = bgl + c*64;
        #pragma unroll
        for (int i = 0; i < 4; i++) CP_ASYNC16(s0 + dsto[i],          a0 + i*8);
        #pragma unroll
        for (int i = 0; i < 4; i++) CP_ASYNC16(s0 + 16384u + dsto[i], a1 + i*8);
        #pragma unroll
        for (int i = 0; i < 4; i++) CP_ASYNC16(s0 + 32768u + dsto[i], b0 + i*8);
        #pragma unroll
        for (int i = 0; i < 4; i++) CP_ASYNC16(s0 + 49152u + dsto[i], b1 + i*8);
    };

    // ldmatrix lane geometry
    const int ra = lane & 15, ca = lane >> 4;
    const int rb = (lane & 7) + ((lane >> 4) << 3), cb = (lane >> 3) & 1;
    const int xr = lane & 7;
    const uint32_t aro = (uint32_t)((wm*32 + ra) * 128);
    const uint32_t bro = (uint32_t)((wn*64 + rb) * 128);

    float acc[2][8][4];
    #pragma unroll
    for (int i = 0; i < 2; i++)
        #pragma unroll
        for (int j = 0; j < 8; j++)
            #pragma unroll
            for (int r = 0; r < 4; r++) acc[i][j][r] = 0.f;

    load_stage(0, 0); CP_COMMIT;
    load_stage(1, 1); CP_COMMIT;

    const int NC = K >> 6;
    int slot = 0;
    for (int c = 0; c < NC; c++) {
        CP_WAIT(1);
        __syncthreads();
        if (c + 2 < NC) {
            int ns = slot + 2; if (ns >= 3) ns -= 3;
            load_stage(c + 2, ns);
        }
        CP_COMMIT;
        const uint32_t st = sb + (uint32_t)slot * GSTG;
        #pragma unroll
        for (int ks = 0; ks < 4; ks++) {
            const uint32_t kca = (uint32_t)(((ks*2 + ca) ^ xr) << 4);
            const uint32_t kcb = (uint32_t)(((ks*2 + cb) ^ xr) << 4);
            uint32_t ah[2][4], al4[2][4], bh[4][4], bl4[4][4];
            #pragma unroll
            for (int mt = 0; mt < 2; mt++) {
                ldsm4(ah[mt],  st + aro + mt*2048u + kca);
                ldsm4(al4[mt], st + 16384u + aro + mt*2048u + kca);
            }
            #pragma unroll
            for (int nq = 0; nq < 4; nq++) {
                ldsm4(bh[nq],  st + 32768u + bro + nq*2048u + kcb);
                ldsm4(bl4[nq], st + 49152u + bro + nq*2048u + kcb);
            }
            // pass-major: 16 independent accs between reuses
            #pragma unroll
            for (int mt = 0; mt < 2; mt++)
                #pragma unroll
                for (int nt = 0; nt < 8; nt++) {
                    const int nq = nt >> 1, s2 = (nt & 1) * 2;
                    mma16816(acc[mt][nt], ah[mt], bh[nq][s2], bh[nq][s2+1]);
                }
            #pragma unroll
            for (int mt = 0; mt < 2; mt++)
                #pragma unroll
                for (int nt = 0; nt < 8; nt++) {
                    const int nq = nt >> 1, s2 = (nt & 1) * 2;
                    mma16816(acc[mt][nt], ah[mt], bl4[nq][s2], bl4[nq][s2+1]);
                }
            #pragma unroll
            for (int mt = 0; mt < 2; mt++)
                #pragma unroll
                for (int nt = 0; nt < 8; nt++) {
                    const int nq = nt >> 1, s2 = (nt & 1) * 2;
                    mma16816(acc[mt][nt], al4[mt], bh[nq][s2], bh[nq][s2+1]);
                }
        }
        slot = (slot + 1 == 3) ? 0 : slot + 1;
    }

    // ---- epilogue ----
    const int grbase = bm*128 + wm*32;
    const int gcbase = bn*128 + wn*64;
    #pragma unroll
    for (int mt = 0; mt < 2; mt++) {
        const int r0 = grbase + mt*16 + (lane >> 2);
        #pragma unroll
        for (int nt = 0; nt < 8; nt++) {
            const int gc = gcbase + nt*8 + (lane & 3)*2;
            float2 v0 = make_float2(acc[mt][nt][0], acc[mt][nt][1]);
            float2 v1 = make_float2(acc[mt][nt][2], acc[mt][nt][3]);
            if (EPI >= 1) {
                float2 bb = *(const float2*)(bias + gc);
                v0.x += bb.x; v0.y += bb.y; v1.x += bb.x; v1.y += bb.y;
            }
            if (EPI == 1) {
                const int third = gc >> 10, lc = gc & 1023;
                __half* oh = outh + (size_t)third * ((size_t)M_ * C_);
                __half* ol = outl + (size_t)third * ((size_t)M_ * C_);
                uint32_t h0, l0;
                split2(v0.x, v0.y, h0, l0);
                *(uint32_t*)(oh + (size_t)r0 * 1024 + lc) = h0;
                *(uint32_t*)(ol + (size_t)r0 * 1024 + lc) = l0;
                split2(v1.x, v1.y, h0, l0);
                *(uint32_t*)(oh + (size_t)(r0+8) * 1024 + lc) = h0;
                *(uint32_t*)(ol + (size_t)(r0+8) * 1024 + lc) = l0;
            } else if (EPI == 2) {
                v0.x = gelu_exact(v0.x); v0.y = gelu_exact(v0.y);
                v1.x = gelu_exact(v1.x); v1.y = gelu_exact(v1.y);
                uint32_t h0, l0;
                split2(v0.x, v0.y, h0, l0);
                *(uint32_t*)(outh + (size_t)r0 * N + gc) = h0;
                *(uint32_t*)(outl + (size_t)r0 * N + gc) = l0;
                split2(v1.x, v1.y, h0, l0);
                *(uint32_t*)(outh + (size_t)(r0+8) * N + gc) = h0;
                *(uint32_t*)(outl + (size_t)(r0+8) * N + gc) = l0;
            } else if (EPI == 3) {
                float2 ra2 = *(const float2*)(resid + (size_t)r0 * N + gc);
                float2 rb2 = *(const float2*)(resid + (size_t)(r0+8) * N + gc);
                v0.x += ra2.x; v0.y += ra2.y; v1.x += rb2.x; v1.y += rb2.y;
                *(float2*)(outf + (size_t)r0 * N + gc) = v0;
                *(float2*)(outf + (size_t)(r0+8) * N + gc) = v1;
            } else {
                *(float2*)(outf + (size_t)r0 * N + gc) = v0;
                *(float2*)(outf + (size_t)(r0+8) * N + gc) = v1;
            }
        }
    }
}

// ================= flash attention (fp16 split inputs, cp.async) =================
// Q tile 128, KV tile 64, DH=64. smem: Qh 16K @0, Ql @16K, stages @32K (2 x 32K):
// per stage: Kh@0 Kl@8K Vh@16K Vl@24K
#define ASTG 32768
#define ATT_SMEM (32768 + 2*ASTG)

__global__ void __launch_bounds__(256, 1) attn_h(
    const __half* __restrict__ qkvh, const __half* __restrict__ qkvl,
    __half* __restrict__ yh, __half* __restrict__ yl)
{
    extern __shared__ char sm[];
    const uint32_t sb = smem_u32(sm);
    const int t = threadIdx.x, w = t >> 5, lane = t & 31;
    const int bhx = blockIdx.y, b = bhx >> 4, h = bhx & 15;
    const int q0 = blockIdx.x * 128;
    const size_t MC = (size_t)M_ * C_;

    const __half* qgh = qkvh + (size_t)(b*T_ + q0) * C_ + h*64;
    const __half* qgl = qkvl + (size_t)(b*T_ + q0) * C_ + h*64;
    const __half* kgh = qkvh + MC   + (size_t)(b*T_) * C_ + h*64;
    const __half* kgl = qkvl + MC   + (size_t)(b*T_) * C_ + h*64;
    const __half* vgh = qkvh + 2*MC + (size_t)(b*T_) * C_ + h*64;
    const __half* vgl = qkvl + 2*MC + (size_t)(b*T_) * C_ + h*64;

    // Q loads: row = t>>1, chalf = t&1
    {
        const int qr = t >> 1, qc = t & 1;
        #pragma unroll
        for (int i = 0; i < 4; i++) {
            const int c16 = qc*4 + i;
            const uint32_t d = (uint32_t)(qr*128 + ((c16 ^ (qr & 7)) << 4));
            CP_ASYNC16(sb + d,          qgh + (size_t)qr * C_ + c16*8);
            CP_ASYNC16(sb + 16384u + d, qgl + (size_t)qr * C_ + c16*8);
        }
    }
    CP_COMMIT;

    // KV stage loader: row = t>>2, 2 chunks
    const int kr = t >> 2, kc2 = (t & 3) * 2;
    auto load_kv = [&](int kt, int slot) {
        const uint32_t s0 = sb + 32768u + (uint32_t)slot * ASTG;
        const size_t rowoff = (size_t)(kt*64 + kr) * C_;
        #pragma unroll
        for (int i = 0; i < 2; i++) {
            const int c16 = kc2 + i;
            const uint32_t d = (uint32_t)(kr*128 + ((c16 ^ (kr & 7)) << 4));
            CP_ASYNC16(s0 + d,          kgh + rowoff + c16*8);
            CP_ASYNC16(s0 + 8192u + d,  kgl + rowoff + c16*8);
            CP_ASYNC16(s0 + 16384u + d, vgh + rowoff + c16*8);
            CP_ASYNC16(s0 + 24576u + d, vgl + rowoff + c16*8);
        }
    };
    load_kv(0, 0); CP_COMMIT;

    // Q fragments
    const int ra = lane & 15, ca = lane >> 4;
    const int rb = (lane & 7) + ((lane >> 4) << 3), cb = (lane >> 3) & 1;
    const int rv = (lane & 7) + (((lane >> 3) & 1) << 3), cv = lane >> 4;
    const int xr = lane & 7;

    CP_WAIT(1);
    __syncthreads();
    uint32_t qh4[4][4], ql4[4][4];
    {
        const uint32_t qro = (uint32_t)((w*16 + ra) * 128);
        #pragma unroll
        for (int ks = 0; ks < 4; ks++) {
            const uint32_t off = qro + (uint32_t)(((ks*2 + ca) ^ xr) << 4);
            ldsm4(qh4[ks], sb + off);
            ldsm4(ql4[ks], sb + 16384u + off);
        }
    }

    float o_[8][4];
    #pragma unroll
    for (int i = 0; i < 8; i++)
        #pragma unroll
        for (int j = 0; j < 4; j++) o_[i][j] = 0.f;
    float m_a = -1e30f, m_b = -1e30f, l_a = 0.f, l_b = 0.f;

    for (int kt = 0; kt < T_/64; kt++) {
        CP_WAIT(0);
        __syncthreads();
        if (kt + 1 < T_/64) load_kv(kt + 1, (kt + 1) & 1);
        CP_COMMIT;
        const uint32_t st = sb + 32768u + (uint32_t)(kt & 1) * ASTG;

        // ---- S = Q K^T (3-pass) ----
        float sc[8][4];
        #pragma unroll
        for (int i = 0; i < 8; i++)
            #pragma unroll
            for (int j = 0; j < 4; j++) sc[i][j] = 0.f;
        #pragma unroll
        for (int ks = 0; ks < 4; ks++) {
            uint32_t kh4[4][4], kl4[4][4];
            #pragma unroll
            for (int nq = 0; nq < 4; nq++) {
                const uint32_t off = (uint32_t)((nq*16 + rb) * 128)
                                   + (uint32_t)(((ks*2 + cb) ^ xr) << 4);
                ldsm4(kh4[nq], st + off);
                ldsm4(kl4[nq], st + 8192u + off);
            }
            #pragma unroll
            for (int nt = 0; nt < 8; nt++) {
                const int nq = nt >> 1, s2 = (nt & 1) * 2;
                mma16816(sc[nt], qh4[ks], kh4[nq][s2], kh4[nq][s2+1]);
            }
            #pragma unroll
            for (int nt = 0; nt < 8; nt++) {
                const int nq = nt >> 1, s2 = (nt & 1) * 2;
                mma16816(sc[nt], qh4[ks], kl4[nq][s2], kl4[nq][s2+1]);
            }
            #pragma unroll
            for (int nt = 0; nt < 8; nt++) {
                const int nq = nt >> 1, s2 = (nt & 1) * 2;
                mma16816(sc[nt], ql4[ks], kh4[nq][s2], kh4[nq][s2+1]);
            }
        }
        #pragma unroll
        for (int nt = 0; nt < 8; nt++) {
            sc[nt][0] *= 0.125f; sc[nt][1] *= 0.125f;
            sc[nt][2] *= 0.125f; sc[nt][3] *= 0.125f;
        }

        // ---- online softmax ----
        float mxa = -1e30f, mxb = -1e30f;
        #pragma unroll
        for (int nt = 0; nt < 8; nt++) {
            mxa = fmaxf(mxa, fmaxf(sc[nt][0], sc[nt][1]));
            mxb = fmaxf(mxb, fmaxf(sc[nt][2], sc[nt][3]));
        }
        mxa = fmaxf(mxa, __shfl_xor_sync(0xffffffffu, mxa, 1));
        mxa = fmaxf(mxa, __shfl_xor_sync(0xffffffffu, mxa, 2));
        mxb = fmaxf(mxb, __shfl_xor_sync(0xffffffffu, mxb, 1));
        mxb = fmaxf(mxb, __shfl_xor_sync(0xffffffffu, mxb, 2));
        const float nma = fmaxf(m_a, mxa), nmb = fmaxf(m_b, mxb);
        const float cfa = __expf(m_a - nma), cfb = __expf(m_b - nmb);
        m_a = nma; m_b = nmb;
        float rsa = 0.f, rsb = 0.f;
        #pragma unroll
        for (int nt = 0; nt < 8; nt++) {
            sc[nt][0] = __expf(sc[nt][0] - m_a); rsa += sc[nt][0];
            sc[nt][1] = __expf(sc[nt][1] - m_a); rsa += sc[nt][1];
            sc[nt][2] = __expf(sc[nt][2] - m_b); rsb += sc[nt][2];
            sc[nt][3] = __expf(sc[nt][3] - m_b); rsb += sc[nt][3];
        }
        rsa += __shfl_xor_sync(0xffffffffu, rsa, 1);
        rsa += __shfl_xor_sync(0xffffffffu, rsa, 2);
        rsb += __shfl_xor_sync(0xffffffffu, rsb, 1);
        rsb += __shfl_xor_sync(0xffffffffu, rsb, 2);
        l_a = l_a * cfa + rsa;
        l_b = l_b * cfb + rsb;
        #pragma unroll
        for (int dt = 0; dt < 8; dt++) {
            o_[dt][0] *= cfa; o_[dt][1] *= cfa; o_[dt][2] *= cfb; o_[dt][3] *= cfb;
        }

        // ---- O += P V (3-pass) ----
        #pragma unroll
        for (int ks = 0; ks < 4; ks++) {
            uint32_t ph[4], pl[4];
            split2(sc[2*ks][0],   sc[2*ks][1],   ph[0], pl[0]);
            split2(sc[2*ks][2],   sc[2*ks][3],   ph[1], pl[1]);
            split2(sc[2*ks+1][0], sc[2*ks+1][1], ph[2], pl[2]);
            split2(sc[2*ks+1][2], sc[2*ks+1][3], ph[3], pl[3]);
            uint32_t vh4[4][4], vl4[4][4];
            #pragma unroll
            for (int nq = 0; nq < 4; nq++) {
                const uint32_t off = (uint32_t)((ks*16 + rv) * 128)
                                   + (uint32_t)(((nq*2 + cv) ^ xr) << 4);
                ldsm4t(vh4[nq], st + 16384u + off);
                ldsm4t(vl4[nq], st + 24576u + off);
            }
            #pragma unroll
            for (int dt = 0; dt < 8; dt++) {
                const int nq = dt >> 1, s2 = (dt & 1) * 2;
                mma16816(o_[dt], ph, vh4[nq][s2], vh4[nq][s2+1]);
            }
            #pragma unroll
            for (int dt = 0; dt < 8; dt++) {
                const int nq = dt >> 1, s2 = (dt & 1) * 2;
                mma16816(o_[dt], ph, vl4[nq][s2], vl4[nq][s2+1]);
            }
            #pragma unroll
            for (int dt = 0; dt < 8; dt++) {
                const int nq = dt >> 1, s2 = (dt & 1) * 2;
                mma16816(o_[dt], pl, vh4[nq][s2], vh4[nq][s2+1]);
            }
        }
    }

    // ---- write y (split fp16) ----
    const float ia = 1.f / l_a, ib = 1.f / l_b;
    const int r0 = q0 + w*16 + (lane >> 2);
    __half* ybh = yh + (size_t)(b*T_ + r0) * C_ + h*64;
    __half* ybl = yl + (size_t)(b*T_ + r0) * C_ + h*64;
    #pragma unroll
    for (int dt = 0; dt < 8; dt++) {
        const int gc = dt*8 + (lane & 3)*2;
        uint32_t h0, l0;
        split2(o_[dt][0]*ia, o_[dt][1]*ia, h0, l0);
        *(uint32_t*)(ybh + gc) = h0;
        *(uint32_t*)(ybl + gc) = l0;
        split2(o_[dt][2]*ib, o_[dt][3]*ib, h0, l0);
        *(uint32_t*)(ybh + (size_t)8*C_ + gc) = h0;
        *(uint32_t*)(ybl + (size_t)8*C_ + gc) = l0;
    }
}

// ================= orchestration =================
extern "C" void kernel_launch(void* const* d_in, const int* in_sizes, int n_in,
                              void* d_out, int out_size)
{
    const float* seq  = (const float*)d_in[0];
    const float* pos  = (const float*)d_in[1];
    const float* Wq   = (const float*)d_in[2];
    const float* bq   = (const float*)d_in[3];
    const float* Wk   = (const float*)d_in[4];
    const float* bk   = (const float*)d_in[5];
    const float* Wv   = (const float*)d_in[6];
    const float* bv   = (const float*)d_in[7];
    const float* Wo   = (const float*)d_in[8];
    const float* bo   = (const float*)d_in[9];
    const float* ln1w = (const float*)d_in[10];
    const float* ln1b = (const float*)d_in[11];
    const float* ln2w = (const float*)d_in[12];
    const float* ln2b = (const float*)d_in[13];
    const float* W1   = (const float*)d_in[14];
    const float* b1   = (const float*)d_in[15];
    const float* W2   = (const float*)d_in[16];
    const float* b2   = (const float*)d_in[17];
    const float* lnfw = (const float*)d_in[18];
    const float* lnfb = (const float*)d_in[19];
    const float* Wh   = (const float*)d_in[20];
    float* out = (float*)d_out;

    float *px, *pbqkv;
    __half *phh, *phl, *pqkvh, *pqkvl, *pyh, *pyl, *puh, *pul, *pwh, *pwl;
    cudaGetSymbolAddress((void**)&px, g_x);
    cudaGetSymbolAddress((void**)&phh, g_hh);
    cudaGetSymbolAddress((void**)&phl, g_hl);
    cudaGetSymbolAddress((void**)&pqkvh, g_qkvh);
    cudaGetSymbolAddress((void**)&pqkvl, g_qkvl);
    cudaGetSymbolAddress((void**)&pyh, g_yh);
    cudaGetSymbolAddress((void**)&pyl, g_yl);
    cudaGetSymbolAddress((void**)&puh, g_uh);
    cudaGetSymbolAddress((void**)&pul, g_ul);
    cudaGetSymbolAddress((void**)&pwh, g_wh);
    cudaGetSymbolAddress((void**)&pwl, g_wl);
    cudaGetSymbolAddress((void**)&pbqkv, g_bqkv);

    cudaFuncSetAttribute(attn_h, cudaFuncAttributeMaxDynamicSharedMemorySize, ATT_SMEM);
    cudaFuncSetAttribute(gemm_h<0>, cudaFuncAttributeMaxDynamicSharedMemorySize, GEMM_SMEM);
    cudaFuncSetAttribute(gemm_h<1>, cudaFuncAttributeMaxDynamicSharedMemorySize, GEMM_SMEM);
    cudaFuncSetAttribute(gemm_h<2>, cudaFuncAttributeMaxDynamicSharedMemorySize, GEMM_SMEM);
    cudaFuncSetAttribute(gemm_h<3>, cudaFuncAttributeMaxDynamicSharedMemorySize, GEMM_SMEM);

    // ---- weight conversion ----
    const int GB_CC = CC_ / 2048;       // 512
    const int GB_4CC = 4*CC_ / 2048;    // 2048
    for (int l = 0; l < L_; l++) {
        size_t wl = (size_t)l * WPL_;
        conv_w<<<GB_CC, 256>>>(Wq + (size_t)l*CC_, pwh + wl,          pwl + wl);
        conv_w<<<GB_CC, 256>>>(Wk + (size_t)l*CC_, pwh + wl + CC_,    pwl + wl + CC_);
        conv_w<<<GB_CC, 256>>>(Wv + (size_t)l*CC_, pwh + wl + 2*CC_,  pwl + wl + 2*CC_);
        conv_w<<<GB_CC, 256>>>(Wo + (size_t)l*CC_, pwh + wl + WOFF_WO, pwl + wl + WOFF_WO);
        conv_w<<<GB_4CC, 256>>>(W1 + (size_t)l*4*CC_, pwh + wl + WOFF_W1, pwl + wl + WOFF_W1);
        conv_w<<<GB_4CC, 256>>>(W2 + (size_t)l*4*CC_, pwh + wl + WOFF_W2, pwl + wl + WOFF_W2);
    }
    conv_w<<<GB_CC, 256>>>(Wh, pwh + WHEAD_OFF, pwl + WHEAD_OFF);
    packqkvb<<<L_*3*C_/256, 256>>>(bq, bk, bv, pbqkv);

    addpos_kernel<<<M_ * C_ / 4 / 256, 256>>>(seq, pos, px);

    dim3 gQKV(3*C_ / 128, M_ / 128);   // (24, 64)
    dim3 gC(C_ / 128, M_ / 128);       // (8, 64)
    dim3 gF(FF_ / 128, M_ / 128);      // (32, 64)
    dim3 gA(T_ / 128, B_ * H_);        // (16, 64)

    for (int l = 0; l < L_; l++) {
        const size_t wl = (size_t)l * WPL_;
        ln_split<<<M_, 256>>>(px, ln1w + l*C_, ln1b + l*C_, phh, phl);
        gemm_h<1><<<gQKV, 256, GEMM_SMEM>>>(phh, phl, pwh + wl, pwl + wl,
            pbqkv + l*3*C_, nullptr, nullptr, pqkvh, pqkvl, 3*C_, C_);
        attn_h<<<gA, 256, ATT_SMEM>>>(pqkvh, pqkvl, pyh, pyl);
        gemm_h<3><<<gC, 256, GEMM_SMEM>>>(pyh, pyl, pwh + wl + WOFF_WO, pwl + wl + WOFF_WO,
            bo + l*C_, px, px, nullptr, nullptr, C_, C_);
        ln_split<<<M_, 256>>>(px, ln2w + l*C_, ln2b + l*C_, phh, phl);
        gemm_h<2><<<gF, 256, GEMM_SMEM>>>(phh, phl, pwh + wl + WOFF_W1, pwl + wl + WOFF_W1,
            b1 + l*FF_, nullptr, nullptr, puh, pul, FF_, C_);
        gemm_h<3><<<gC, 256, GEMM_SMEM>>>(puh, pul, pwh + wl + WOFF_W2, pwl + wl + WOFF_W2,
            b2 + l*C_, px, px, nullptr, nullptr, C_, FF_);
    }

    ln_split<<<M_, 256>>>(px, lnfw, lnfb, phh, phl);
    gemm_h<0><<<gC, 256, GEMM_SMEM>>>(phh, phl, pwh + WHEAD_OFF, pwl + WHEAD_OFF,
        nullptr, nullptr, out, nullptr, nullptr, OUT_, C_);
}

// round 6
// speedup vs baseline: 2.7359x; 1.0094x over previous
#include <cuda_runtime.h>
#include <cuda_fp16.h>
#include <math.h>
#include <stdint.h>

#define L_ 8
#define H_ 16
#define T_ 2048
#define C_ 1024
#define OUT_ 1024
#define B_ 4
#define DH_ 64
#define FF_ 4096
#define M_ (B_*T_)   // 8192 rows

#define CC_ (C_*C_)                   // 1048576
#define WPL_ (12*CC_)                 // weights per layer (halves)
#define WOFF_WO  (3*CC_)
#define WOFF_W1  (4*CC_)
#define WOFF_W2  (8*CC_)
#define WHEAD_OFF ((size_t)L_*WPL_)   // 100663296
#define WTOT (WHEAD_OFF + CC_)        // 101711872

// q pre-scale: 0.125 (1/sqrt(DH)) * log2(e) -> softmax in base-2 domain
#define QSCALE 0.1803368801111204f

// ---------------- scratch (static device globals) ----------------
__device__ float g_x[M_*C_];
__device__ __align__(16) __half g_hh[M_*C_],  g_hl[M_*C_];
__device__ __align__(16) __half g_qkvh[3*M_*C_], g_qkvl[3*M_*C_];
__device__ __align__(16) __half g_yh[M_*C_],  g_yl[M_*C_];
__device__ __align__(16) __half g_uh[(size_t)M_*FF_], g_ul[(size_t)M_*FF_];
__device__ __align__(16) __half g_wh[WTOT],   g_wl[WTOT];
__device__ float g_bqkv[L_*3*C_];

// ================= helpers =================
__device__ __forceinline__ uint32_t smem_u32(const void* p) {
    uint32_t a;
    asm("{ .reg .u64 t; cvta.to.shared.u64 t, %1; cvt.u32.u64 %0, t; }" : "=r"(a) : "l"(p));
    return a;
}
__device__ __forceinline__ void mma16816(float* c, const uint32_t* a, uint32_t b0, uint32_t b1) {
    asm volatile(
        "mma.sync.aligned.m16n8k16.row.col.f32.f16.f16.f32 "
        "{%0,%1,%2,%3}, {%4,%5,%6,%7}, {%8,%9}, {%0,%1,%2,%3};"
        : "+f"(c[0]), "+f"(c[1]), "+f"(c[2]), "+f"(c[3])
        : "r"(a[0]), "r"(a[1]), "r"(a[2]), "r"(a[3]), "r"(b0), "r"(b1));
}
__device__ __forceinline__ void ldsm4(uint32_t* r, uint32_t addr) {
    asm volatile("ldmatrix.sync.aligned.m8n8.x4.shared.b16 {%0,%1,%2,%3}, [%4];"
                 : "=r"(r[0]), "=r"(r[1]), "=r"(r[2]), "=r"(r[3]) : "r"(addr));
}
__device__ __forceinline__ void ldsm4t(uint32_t* r, uint32_t addr) {
    asm volatile("ldmatrix.sync.aligned.m8n8.x4.trans.shared.b16 {%0,%1,%2,%3}, [%4];"
                 : "=r"(r[0]), "=r"(r[1]), "=r"(r[2]), "=r"(r[3]) : "r"(addr));
}
#define CP_ASYNC16(dst, src) \
    asm volatile("cp.async.cg.shared.global [%0], [%1], 16;" :: "r"(dst), "l"(src))
#define CP_COMMIT asm volatile("cp.async.commit_group;" ::: "memory")
#define CP_WAIT(n) asm volatile("cp.async.wait_group %0;" :: "n"(n) : "memory")

__device__ __forceinline__ float fex2(float x) {
    float y;
    asm("ex2.approx.f32 %0, %1;" : "=f"(y) : "f"(x));
    return y;
}
__device__ __forceinline__ void split2(float x, float y, uint32_t& h, uint32_t& l) {
    __half2 hh = __floats2half2_rn(x, y);
    float2 hf = __half22float2(hh);
    __half2 ll = __floats2half2_rn(x - hf.x, y - hf.y);
    h = *(uint32_t*)&hh;
    l = *(uint32_t*)&ll;
}
__device__ __forceinline__ float gelu_exact(float v) {
    return 0.5f * v * (1.0f + erff(v * 0.70710678118654752f));
}

// ================= fused weight conversion (single launch) =================
__global__ void __launch_bounds__(256) conv_all(
    const float* __restrict__ Wq, const float* __restrict__ Wk,
    const float* __restrict__ Wv, const float* __restrict__ Wo,
    const float* __restrict__ W1, const float* __restrict__ W2,
    const float* __restrict__ Whd,
    __half* __restrict__ dh, __half* __restrict__ dl)
{
    const size_t i = ((size_t)blockIdx.x * 256 + threadIdx.x) * 8;
    const float* src;
    if (i >= WHEAD_OFF) {
        src = Whd + (i - WHEAD_OFF);
    } else {
        const int l = (int)(i / WPL_);
        const size_t r = i % WPL_;
        if      (r <   (size_t)CC_)   src = Wq + (size_t)l*CC_   + r;
        else if (r < 2*(size_t)CC_)   src = Wk + (size_t)l*CC_   + (r -   CC_);
        else if (r < 3*(size_t)CC_)   src = Wv + (size_t)l*CC_   + (r - 2*CC_);
        else if (r < 4*(size_t)CC_)   src = Wo + (size_t)l*CC_   + (r - 3*CC_);
        else if (r < 8*(size_t)CC_)   src = W1 + (size_t)l*4*CC_ + (r - 4*CC_);
        else                          src = W2 + (size_t)l*4*CC_ + (r - 8*CC_);
    }
    float4 a = *(const float4*)(src), b = *(const float4*)(src + 4);
    uint32_t h[4], l4[4];
    split2(a.x, a.y, h[0], l4[0]); split2(a.z, a.w, h[1], l4[1]);
    split2(b.x, b.y, h[2], l4[2]); split2(b.z, b.w, h[3], l4[3]);
    *(uint4*)(dh + i) = make_uint4(h[0], h[1], h[2], h[3]);
    *(uint4*)(dl + i) = make_uint4(l4[0], l4[1], l4[2], l4[3]);
}
__global__ void __launch_bounds__(256) packqkvb(
    const float* __restrict__ bq, const float* __restrict__ bk,
    const float* __restrict__ bv, float* __restrict__ dst)
{
    int idx = blockIdx.x * 256 + threadIdx.x;      // L_*3072
    int l = idx / 3072, c = idx % 3072;
    float v = (c < 1024) ? bq[l*1024 + c] : (c < 2048) ? bk[l*1024 + c - 1024]
                                                        : bv[l*1024 + c - 2048];
    dst[idx] = v;
}

// ================= x = seq + pos =================
__global__ void __launch_bounds__(256) addpos_kernel(
    const float* __restrict__ seq, const float* __restrict__ pos, float* __restrict__ x)
{
    int i = blockIdx.x * 256 + threadIdx.x;
    float4 s = ((const float4*)seq)[i];
    float4 p = ((const float4*)pos)[i & (T_*C_/4 - 1)];
    s.x += p.x; s.y += p.y; s.z += p.z; s.w += p.w;
    ((float4*)x)[i] = s;
}

// ================= LayerNorm -> split fp16 =================
__global__ void __launch_bounds__(256) ln_split(
    const float* __restrict__ x, const float* __restrict__ w,
    const float* __restrict__ b, __half* __restrict__ outh, __half* __restrict__ outl)
{
    const int row = blockIdx.x;
    const int t = threadIdx.x;
    const float4 v = *(const float4*)(x + (size_t)row * C_ + t * 4);
    float s  = v.x + v.y + v.z + v.w;
    float sq = v.x*v.x + v.y*v.y + v.z*v.z + v.w*v.w;
    #pragma unroll
    for (int off = 16; off; off >>= 1) {
        s  += __shfl_xor_sync(0xffffffffu, s,  off);
        sq += __shfl_xor_sync(0xffffffffu, sq, off);
    }
    __shared__ float rs_[8], rq_[8];
    if ((t & 31) == 0) { rs_[t >> 5] = s; rq_[t >> 5] = sq; }
    __syncthreads();
    s = 0.f; sq = 0.f;
    #pragma unroll
    for (int i = 0; i < 8; i++) { s += rs_[i]; sq += rq_[i]; }
    const float mu   = s * (1.0f / 1024.0f);
    const float var  = sq * (1.0f / 1024.0f) - mu * mu;
    const float rstd = rsqrtf(var + 1e-5f);
    const float4 wv = *(const float4*)(w + t * 4);
    const float4 bv = *(const float4*)(b + t * 4);
    float ox = (v.x - mu) * rstd * wv.x + bv.x;
    float oy = (v.y - mu) * rstd * wv.y + bv.y;
    float oz = (v.z - mu) * rstd * wv.z + bv.z;
    float ow = (v.w - mu) * rstd * wv.w + bv.w;
    uint32_t h0, l0, h1, l1;
    split2(ox, oy, h0, l0);
    split2(oz, ow, h1, l1);
    *(uint2*)(outh + (size_t)row * C_ + t * 4) = make_uint2(h0, h1);
    *(uint2*)(outl + (size_t)row * C_ + t * 4) = make_uint2(l0, l1);
}

// ================= split-fp16 pipelined GEMM =================
// D[M,N] = A[M,K] @ W[N,K]^T. 3-pass split-fp16 MMA, tile 128x128, Kc=64, 3-stage.
// EPI: 0 = fp32 out, 1 = +bias -> qkv split out (q third scaled by QSCALE),
//      2 = +bias+GELU -> split out, 3 = +bias+residual -> fp32 out
#define GSTG 65536
#define GEMM_SMEM (3*GSTG)

template <int EPI>
__global__ void __launch_bounds__(256, 1) gemm_h(
    const __half* __restrict__ Ah, const __half* __restrict__ Al,
    const __half* __restrict__ Wh, const __half* __restrict__ Wl,
    const float* __restrict__ bias, const float* __restrict__ resid,
    float* __restrict__ outf, __half* __restrict__ outh, __half* __restrict__ outl,
    int N, int K)
{
    extern __shared__ char sm[];
    const uint32_t sb = smem_u32(sm);
    const int t = threadIdx.x, w = t >> 5, lane = t & 31;
    const int bm = blockIdx.y, bn = blockIdx.x;
    const int wm = w & 3, wn = w >> 2;

    const int crow = t >> 1, chalf = t & 1;
    const __half* agh = Ah + (size_t)(bm*128 + crow) * K + chalf*32;
    const __half* agl = Al + (size_t)(bm*128 + crow) * K + chalf*32;
    const __half* bgh = Wh + (size_t)(bn*128 + crow) * K + chalf*32;
    const __half* bgl = Wl + (size_t)(bn*128 + crow) * K + chalf*32;
    uint32_t dsto[4];
    #pragma unroll
    for (int i = 0; i < 4; i++) {
        int c16 = chalf*4 + i;
        dsto[i] = (uint32_t)(crow*128 + ((c16 ^ (crow & 7)) << 4));
    }
    auto load_stage = [&](int c, int slot) {
        const uint32_t s0 = sb + (uint32_t)slot * GSTG;
        const __half* a0 = agh + c*64;
        const __half* a1 = agl + c*64;
        const __half* b0 = bgh + c*64;
        const __half* b1 = bgl + c*64;
        #pragma unroll
        for (int i = 0; i < 4; i++) CP_ASYNC16(s0 + dsto[i],          a0 + i*8);
        #pragma unroll
        for (int i = 0; i < 4; i++) CP_ASYNC16(s0 + 16384u + dsto[i], a1 + i*8);
        #pragma unroll
        for (int i = 0; i < 4; i++) CP_ASYNC16(s0 + 32768u + dsto[i], b0 + i*8);
        #pragma unroll
        for (int i = 0; i < 4; i++) CP_ASYNC16(s0 + 49152u + dsto[i], b1 + i*8);
    };

    // ldmatrix lane geometry
    const int ra = lane & 15, ca = lane >> 4;
    const int rb = (lane & 7) + ((lane >> 4) << 3), cb = (lane >> 3) & 1;
    const int xr = lane & 7;
    const uint32_t aro = (uint32_t)((wm*32 + ra) * 128);
    const uint32_t bro = (uint32_t)((wn*64 + rb) * 128);

    float acc[2][8][4];
    #pragma unroll
    for (int i = 0; i < 2; i++)
        #pragma unroll
        for (int j = 0; j < 8; j++)
            #pragma unroll
            for (int r = 0; r < 4; r++) acc[i][j][r] = 0.f;

    load_stage(0, 0); CP_COMMIT;
    load_stage(1, 1); CP_COMMIT;

    const int NC = K >> 6;
    int slot = 0;
    for (int c = 0; c < NC; c++) {
        CP_WAIT(1);
        __syncthreads();
        if (c + 2 < NC) {
            int ns = slot + 2; if (ns >= 3) ns -= 3;
            load_stage(c + 2, ns);
        }
        CP_COMMIT;
        const uint32_t st = sb + (uint32_t)slot * GSTG;
        #pragma unroll
        for (int ks = 0; ks < 4; ks++) {
            const uint32_t kca = (uint32_t)(((ks*2 + ca) ^ xr) << 4);
            const uint32_t kcb = (uint32_t)(((ks*2 + cb) ^ xr) << 4);
            uint32_t ah[2][4], al4[2][4], bh[4][4], bl4[4][4];
            #pragma unroll
            for (int mt = 0; mt < 2; mt++) {
                ldsm4(ah[mt],  st + aro + mt*2048u + kca);
                ldsm4(al4[mt], st + 16384u + aro + mt*2048u + kca);
            }
            #pragma unroll
            for (int nq = 0; nq < 4; nq++) {
                ldsm4(bh[nq],  st + 32768u + bro + nq*2048u + kcb);
                ldsm4(bl4[nq], st + 49152u + bro + nq*2048u + kcb);
            }
            // pass-major: 16 independent accs between reuses
            #pragma unroll
            for (int mt = 0; mt < 2; mt++)
                #pragma unroll
                for (int nt = 0; nt < 8; nt++) {
                    const int nq = nt >> 1, s2 = (nt & 1) * 2;
                    mma16816(acc[mt][nt], ah[mt], bh[nq][s2], bh[nq][s2+1]);
                }
            #pragma unroll
            for (int mt = 0; mt < 2; mt++)
                #pragma unroll
                for (int nt = 0; nt < 8; nt++) {
                    const int nq = nt >> 1, s2 = (nt & 1) * 2;
                    mma16816(acc[mt][nt], ah[mt], bl4[nq][s2], bl4[nq][s2+1]);
                }
            #pragma unroll
            for (int mt = 0; mt < 2; mt++)
                #pragma unroll
                for (int nt = 0; nt < 8; nt++) {
                    const int nq = nt >> 1, s2 = (nt & 1) * 2;
                    mma16816(acc[mt][nt], al4[mt], bh[nq][s2], bh[nq][s2+1]);
                }
        }
        slot = (slot + 1 == 3) ? 0 : slot + 1;
    }

    // ---- epilogue ----
    const int grbase = bm*128 + wm*32;
    const int gcbase = bn*128 + wn*64;
    #pragma unroll
    for (int mt = 0; mt < 2; mt++) {
        const int r0 = grbase + mt*16 + (lane >> 2);
        #pragma unroll
        for (int nt = 0; nt < 8; nt++) {
            const int gc = gcbase + nt*8 + (lane & 3)*2;
            float2 v0 = make_float2(acc[mt][nt][0], acc[mt][nt][1]);
            float2 v1 = make_float2(acc[mt][nt][2], acc[mt][nt][3]);
            if (EPI >= 1) {
                float2 bb = *(const float2*)(bias + gc);
                v0.x += bb.x; v0.y += bb.y; v1.x += bb.x; v1.y += bb.y;
            }
            if (EPI == 1) {
                const int third = gc >> 10, lc = gc & 1023;
                if (third == 0) {   // q: fold softmax scale + log2e
                    v0.x *= QSCALE; v0.y *= QSCALE; v1.x *= QSCALE; v1.y *= QSCALE;
                }
                __half* oh = outh + (size_t)third * ((size_t)M_ * C_);
                __half* ol = outl + (size_t)third * ((size_t)M_ * C_);
                uint32_t h0, l0;
                split2(v0.x, v0.y, h0, l0);
                *(uint32_t*)(oh + (size_t)r0 * 1024 + lc) = h0;
                *(uint32_t*)(ol + (size_t)r0 * 1024 + lc) = l0;
                split2(v1.x, v1.y, h0, l0);
                *(uint32_t*)(oh + (size_t)(r0+8) * 1024 + lc) = h0;
                *(uint32_t*)(ol + (size_t)(r0+8) * 1024 + lc) = l0;
            } else if (EPI == 2) {
                v0.x = gelu_exact(v0.x); v0.y = gelu_exact(v0.y);
                v1.x = gelu_exact(v1.x); v1.y = gelu_exact(v1.y);
                uint32_t h0, l0;
                split2(v0.x, v0.y, h0, l0);
                *(uint32_t*)(outh + (size_t)r0 * N + gc) = h0;
                *(uint32_t*)(outl + (size_t)r0 * N + gc) = l0;
                split2(v1.x, v1.y, h0, l0);
                *(uint32_t*)(outh + (size_t)(r0+8) * N + gc) = h0;
                *(uint32_t*)(outl + (size_t)(r0+8) * N + gc) = l0;
            } else if (EPI == 3) {
                float2 ra2 = *(const float2*)(resid + (size_t)r0 * N + gc);
                float2 rb2 = *(const float2*)(resid + (size_t)(r0+8) * N + gc);
                v0.x += ra2.x; v0.y += ra2.y; v1.x += rb2.x; v1.y += rb2.y;
                *(float2*)(outf + (size_t)r0 * N + gc) = v0;
                *(float2*)(outf + (size_t)(r0+8) * N + gc) = v1;
            } else {
                *(float2*)(outf + (size_t)r0 * N + gc) = v0;
                *(float2*)(outf + (size_t)(r0+8) * N + gc) = v1;
            }
        }
    }
}

// ================= flash attention (fp16 split inputs, 3-stage cp.async) =================
// Q tile 128, KV tile 64, DH=64. smem: Qh@0 Ql@16K (32KB), then 3 stages of 32KB:
// per stage: Kh@0 Kl@8K Vh@16K Vl@24K. Softmax in base-2 (q pre-scaled upstream).
#define ASTG 32768
#define AQSZ 32768
#define ATT_SMEM (AQSZ + 3*ASTG)

__global__ void __launch_bounds__(256, 1) attn_h(
    const __half* __restrict__ qkvh, const __half* __restrict__ qkvl,
    __half* __restrict__ yh, __half* __restrict__ yl)
{
    extern __shared__ char sm[];
    const uint32_t sb = smem_u32(sm);
    const int t = threadIdx.x, w = t >> 5, lane = t & 31;
    const int bhx = blockIdx.y, b = bhx >> 4, h = bhx & 15;
    const int q0 = blockIdx.x * 128;
    const size_t MC = (size_t)M_ * C_;
    const int NT = T_ / 64;   // 32 tiles

    const __half* qgh = qkvh + (size_t)(b*T_ + q0) * C_ + h*64;
    const __half* qgl = qkvl + (size_t)(b*T_ + q0) * C_ + h*64;
    const __half* kgh = qkvh + MC   + (size_t)(b*T_) * C_ + h*64;
    const __half* kgl = qkvl + MC   + (size_t)(b*T_) * C_ + h*64;
    const __half* vgh = qkvh + 2*MC + (size_t)(b*T_) * C_ + h*64;
    const __half* vgl = qkvl + 2*MC + (size_t)(b*T_) * C_ + h*64;

    // Q loads (group 0)
    {
        const int qr = t >> 1, qc = t & 1;
        #pragma unroll
        for (int i = 0; i < 4; i++) {
            const int c16 = qc*4 + i;
            const uint32_t d = (uint32_t)(qr*128 + ((c16 ^ (qr & 7)) << 4));
            CP_ASYNC16(sb + d,          qgh + (size_t)qr * C_ + c16*8);
            CP_ASYNC16(sb + 16384u + d, qgl + (size_t)qr * C_ + c16*8);
        }
    }
    CP_COMMIT;

    // KV stage loader
    const int kr = t >> 2, kc2 = (t & 3) * 2;
    auto load_kv = [&](int kt, int slot) {
        const uint32_t s0 = sb + AQSZ + (uint32_t)slot * ASTG;
        const size_t rowoff = (size_t)(kt*64 + kr) * C_;
        #pragma unroll
        for (int i = 0; i < 2; i++) {
            const int c16 = kc2 + i;
            const uint32_t d = (uint32_t)(kr*128 + ((c16 ^ (kr & 7)) << 4));
            CP_ASYNC16(s0 + d,          kgh + rowoff + c16*8);
            CP_ASYNC16(s0 + 8192u + d,  kgl + rowoff + c16*8);
            CP_ASYNC16(s0 + 16384u + d, vgh + rowoff + c16*8);
            CP_ASYNC16(s0 + 24576u + d, vgl + rowoff + c16*8);
        }
    };
    load_kv(0, 0); CP_COMMIT;
    load_kv(1, 1); CP_COMMIT;

    // ldmatrix lane geometry
    const int ra = lane & 15, ca = lane >> 4;
    const int rb = (lane & 7) + ((lane >> 4) << 3), cb = (lane >> 3) & 1;
    const int rv = (lane & 7) + (((lane >> 3) & 1) << 3), cv = lane >> 4;
    const int xr = lane & 7;

    CP_WAIT(2);           // Q (group 0) landed
    __syncthreads();
    uint32_t qh4[4][4], ql4[4][4];
    {
        const uint32_t qro = (uint32_t)((w*16 + ra) * 128);
        #pragma unroll
        for (int ks = 0; ks < 4; ks++) {
            const uint32_t off = qro + (uint32_t)(((ks*2 + ca) ^ xr) << 4);
            ldsm4(qh4[ks], sb + off);
            ldsm4(ql4[ks], sb + 16384u + off);
        }
    }

    float o_[8][4];
    #pragma unroll
    for (int i = 0; i < 8; i++)
        #pragma unroll
        for (int j = 0; j < 4; j++) o_[i][j] = 0.f;
    float m_a = -1e30f, m_b = -1e30f, l_a = 0.f, l_b = 0.f;

    int slot = 0;
    for (int kt = 0; kt < NT; kt++) {
        CP_WAIT(1);        // current stage landed; next may still be in flight
        __syncthreads();
        if (kt + 2 < NT) {
            int ns = slot + 2; if (ns >= 3) ns -= 3;
            load_kv(kt + 2, ns);
        }
        CP_COMMIT;
        const uint32_t st = sb + AQSZ + (uint32_t)slot * ASTG;

        // ---- S = Q K^T (3-pass), q pre-scaled by 0.125*log2e ----
        float sc[8][4];
        #pragma unroll
        for (int i = 0; i < 8; i++)
            #pragma unroll
            for (int j = 0; j < 4; j++) sc[i][j] = 0.f;
        #pragma unroll
        for (int ks = 0; ks < 4; ks++) {
            uint32_t kh4[4][4], kl4[4][4];
            #pragma unroll
            for (int nq = 0; nq < 4; nq++) {
                const uint32_t off = (uint32_t)((nq*16 + rb) * 128)
                                   + (uint32_t)(((ks*2 + cb) ^ xr) << 4);
                ldsm4(kh4[nq], st + off);
                ldsm4(kl4[nq], st + 8192u + off);
            }
            #pragma unroll
            for (int nt = 0; nt < 8; nt++) {
                const int nq = nt >> 1, s2 = (nt & 1) * 2;
                mma16816(sc[nt], qh4[ks], kh4[nq][s2], kh4[nq][s2+1]);
            }
            #pragma unroll
            for (int nt = 0; nt < 8; nt++) {
                const int nq = nt >> 1, s2 = (nt & 1) * 2;
                mma16816(sc[nt], qh4[ks], kl4[nq][s2], kl4[nq][s2+1]);
            }
            #pragma unroll
            for (int nt = 0; nt < 8; nt++) {
                const int nq = nt >> 1, s2 = (nt & 1) * 2;
                mma16816(sc[nt], ql4[ks], kh4[nq][s2], kh4[nq][s2+1]);
            }
        }

        // ---- online softmax (base-2) ----
        float mxa = -1e30f, mxb = -1e30f;
        #pragma unroll
        for (int nt = 0; nt < 8; nt++) {
            mxa = fmaxf(mxa, fmaxf(sc[nt][0], sc[nt][1]));
            mxb = fmaxf(mxb, fmaxf(sc[nt][2], sc[nt][3]));
        }
        mxa = fmaxf(mxa, __shfl_xor_sync(0xffffffffu, mxa, 1));
        mxa = fmaxf(mxa, __shfl_xor_sync(0xffffffffu, mxa, 2));
        mxb = fmaxf(mxb, __shfl_xor_sync(0xffffffffu, mxb, 1));
        mxb = fmaxf(mxb, __shfl_xor_sync(0xffffffffu, mxb, 2));
        const float nma = fmaxf(m_a, mxa), nmb = fmaxf(m_b, mxb);
        const float cfa = fex2(m_a - nma), cfb = fex2(m_b - nmb);
        m_a = nma; m_b = nmb;
        float rsa = 0.f, rsb = 0.f;
        #pragma unroll
        for (int nt = 0; nt < 8; nt++) {
            sc[nt][0] = fex2(sc[nt][0] - m_a); rsa += sc[nt][0];
            sc[nt][1] = fex2(sc[nt][1] - m_a); rsa += sc[nt][1];
            sc[nt][2] = fex2(sc[nt][2] - m_b); rsb += sc[nt][2];
            sc[nt][3] = fex2(sc[nt][3] - m_b); rsb += sc[nt][3];
        }
        rsa += __shfl_xor_sync(0xffffffffu, rsa, 1);
        rsa += __shfl_xor_sync(0xffffffffu, rsa, 2);
        rsb += __shfl_xor_sync(0xffffffffu, rsb, 1);
        rsb += __shfl_xor_sync(0xffffffffu, rsb, 2);
        l_a = l_a * cfa + rsa;
        l_b = l_b * cfb + rsb;
        #pragma unroll
        for (int dt = 0; dt < 8; dt++) {
            o_[dt][0] *= cfa; o_[dt][1] *= cfa; o_[dt][2] *= cfb; o_[dt][3] *= cfb;
        }

        // ---- O += P V (3-pass) ----
        #pragma unroll
        for (int ks = 0; ks < 4; ks++) {
            uint32_t ph[4], pl[4];
            split2(sc[2*ks][0],   sc[2*ks][1],   ph[0], pl[0]);
            split2(sc[2*ks][2],   sc[2*ks][3],   ph[1], pl[1]);
            split2(sc[2*ks+1][0], sc[2*ks+1][1], ph[2], pl[2]);
            split2(sc[2*ks+1][2], sc[2*ks+1][3], ph[3], pl[3]);
            uint32_t vh4[4][4], vl4[4][4];
            #pragma unroll
            for (int nq = 0; nq < 4; nq++) {
                const uint32_t off = (uint32_t)((ks*16 + rv) * 128)
                                   + (uint32_t)(((nq*2 + cv) ^ xr) << 4);
                ldsm4t(vh4[nq], st + 16384u + off);
                ldsm4t(vl4[nq], st + 24576u + off);
            }
            #pragma unroll
            for (int dt = 0; dt < 8; dt++) {
                const int nq = dt >> 1, s2 = (dt & 1) * 2;
                mma16816(o_[dt], ph, vh4[nq][s2], vh4[nq][s2+1]);
            }
            #pragma unroll
            for (int dt = 0; dt < 8; dt++) {
                const int nq = dt >> 1, s2 = (dt & 1) * 2;
                mma16816(o_[dt], ph, vl4[nq][s2], vl4[nq][s2+1]);
            }
            #pragma unroll
            for (int dt = 0; dt < 8; dt++) {
                const int nq = dt >> 1, s2 = (dt & 1) * 2;
                mma16816(o_[dt], pl, vh4[nq][s2], vh4[nq][s2+1]);
            }
        }
        slot = (slot + 1 == 3) ? 0 : slot + 1;
    }

    // ---- write y (split fp16) ----
    const float ia = 1.f / l_a, ib = 1.f / l_b;
    const int r0 = q0 + w*16 + (lane >> 2);
    __half* ybh = yh + (size_t)(b*T_ + r0) * C_ + h*64;
    __half* ybl = yl + (size_t)(b*T_ + r0) * C_ + h*64;
    #pragma unroll
    for (int dt = 0; dt < 8; dt++) {
        const int gc = dt*8 + (lane & 3)*2;
        uint32_t h0, l0;
        split2(o_[dt][0]*ia, o_[dt][1]*ia, h0, l0);
        *(uint32_t*)(ybh + gc) = h0;
        *(uint32_t*)(ybl + gc) = l0;
        split2(o_[dt][2]*ib, o_[dt][3]*ib, h0, l0);
        *(uint32_t*)(ybh + (size_t)8*C_ + gc) = h0;
        *(uint32_t*)(ybl + (size_t)8*C_ + gc) = l0;
    }
}

// ================= orchestration =================
extern "C" void kernel_launch(void* const* d_in, const int* in_sizes, int n_in,
                              void* d_out, int out_size)
{
    const float* seq  = (const float*)d_in[0];
    const float* pos  = (const float*)d_in[1];
    const float* Wq   = (const float*)d_in[2];
    const float* bq   = (const float*)d_in[3];
    const float* Wk   = (const float*)d_in[4];
    const float* bk   = (const float*)d_in[5];
    const float* Wv   = (const float*)d_in[6];
    const float* bv   = (const float*)d_in[7];
    const float* Wo   = (const float*)d_in[8];
    const float* bo   = (const float*)d_in[9];
    const float* ln1w = (const float*)d_in[10];
    const float* ln1b = (const float*)d_in[11];
    const float* ln2w = (const float*)d_in[12];
    const float* ln2b = (const float*)d_in[13];
    const float* W1   = (const float*)d_in[14];
    const float* b1   = (const float*)d_in[15];
    const float* W2   = (const float*)d_in[16];
    const float* b2   = (const float*)d_in[17];
    const float* lnfw = (const float*)d_in[18];
    const float* lnfb = (const float*)d_in[19];
    const float* Wh   = (const float*)d_in[20];
    float* out = (float*)d_out;

    float *px, *pbqkv;
    __half *phh, *phl, *pqkvh, *pqkvl, *pyh, *pyl, *puh, *pul, *pwh, *pwl;
    cudaGetSymbolAddress((void**)&px, g_x);
    cudaGetSymbolAddress((void**)&phh, g_hh);
    cudaGetSymbolAddress((void**)&phl, g_hl);
    cudaGetSymbolAddress((void**)&pqkvh, g_qkvh);
    cudaGetSymbolAddress((void**)&pqkvl, g_qkvl);
    cudaGetSymbolAddress((void**)&pyh, g_yh);
    cudaGetSymbolAddress((void**)&pyl, g_yl);
    cudaGetSymbolAddress((void**)&puh, g_uh);
    cudaGetSymbolAddress((void**)&pul, g_ul);
    cudaGetSymbolAddress((void**)&pwh, g_wh);
    cudaGetSymbolAddress((void**)&pwl, g_wl);
    cudaGetSymbolAddress((void**)&pbqkv, g_bqkv);

    cudaFuncSetAttribute(attn_h, cudaFuncAttributeMaxDynamicSharedMemorySize, ATT_SMEM);
    cudaFuncSetAttribute(gemm_h<0>, cudaFuncAttributeMaxDynamicSharedMemorySize, GEMM_SMEM);
    cudaFuncSetAttribute(gemm_h<1>, cudaFuncAttributeMaxDynamicSharedMemorySize, GEMM_SMEM);
    cudaFuncSetAttribute(gemm_h<2>, cudaFuncAttributeMaxDynamicSharedMemorySize, GEMM_SMEM);
    cudaFuncSetAttribute(gemm_h<3>, cudaFuncAttributeMaxDynamicSharedMemorySize, GEMM_SMEM);

    // ---- weight conversion: ONE launch ----
    conv_all<<<(int)(WTOT / 2048), 256>>>(Wq, Wk, Wv, Wo, W1, W2, Wh, pwh, pwl);
    packqkvb<<<L_*3*C_/256, 256>>>(bq, bk, bv, pbqkv);
    addpos_kernel<<<M_ * C_ / 4 / 256, 256>>>(seq, pos, px);

    dim3 gQKV(3*C_ / 128, M_ / 128);   // (24, 64)
    dim3 gC(C_ / 128, M_ / 128);       // (8, 64)
    dim3 gF(FF_ / 128, M_ / 128);      // (32, 64)
    dim3 gA(T_ / 128, B_ * H_);        // (16, 64)

    for (int l = 0; l < L_; l++) {
        const size_t wl = (size_t)l * WPL_;
        ln_split<<<M_, 256>>>(px, ln1w + l*C_, ln1b + l*C_, phh, phl);
        gemm_h<1><<<gQKV, 256, GEMM_SMEM>>>(phh, phl, pwh + wl, pwl + wl,
            pbqkv + l*3*C_, nullptr, nullptr, pqkvh, pqkvl, 3*C_, C_);
        attn_h<<<gA, 256, ATT_SMEM>>>(pqkvh, pqkvl, pyh, pyl);
        gemm_h<3><<<gC, 256, GEMM_SMEM>>>(pyh, pyl, pwh + wl + WOFF_WO, pwl + wl + WOFF_WO,
            bo + l*C_, px, px, nullptr, nullptr, C_, C_);
        ln_split<<<M_, 256>>>(px, ln2w + l*C_, ln2b + l*C_, phh, phl);
        gemm_h<2><<<gF, 256, GEMM_SMEM>>>(phh, phl, pwh + wl + WOFF_W1, pwl + wl + WOFF_W1,
            b1 + l*FF_, nullptr, nullptr, puh, pul, FF_, C_);
        gemm_h<3><<<gC, 256, GEMM_SMEM>>>(puh, pul, pwh + wl + WOFF_W2, pwl + wl + WOFF_W2,
            b2 + l*C_, px, px, nullptr, nullptr, C_, FF_);
    }

    ln_split<<<M_, 256>>>(px, lnfw, lnfb, phh, phl);
    gemm_h<0><<<gC, 256, GEMM_SMEM>>>(phh, phl, pwh + WHEAD_OFF, pwl + WHEAD_OFF,
        nullptr, nullptr, out, nullptr, nullptr, OUT_, C_);
}

// round 7
// speedup vs baseline: 3.4966x; 1.2780x over previous
#include <cuda_runtime.h>
#include <cuda_fp16.h>
#include <math.h>
#include <stdint.h>

#define L_ 8
#define H_ 16
#define T_ 2048
#define C_ 1024
#define OUT_ 1024
#define B_ 4
#define DH_ 64
#define FF_ 4096
#define M_ (B_*T_)   // 8192 rows

#define CC_ (C_*C_)                   // 1048576
#define WPL_ (12*CC_)                 // weights per layer (halves)
#define WOFF_WO  (3*CC_)
#define WOFF_W1  (4*CC_)
#define WOFF_W2  (8*CC_)
#define WHEAD_OFF ((size_t)L_*WPL_)   // 100663296
#define WTOT (WHEAD_OFF + CC_)        // 101711872

// q pre-scale: 0.125 (1/sqrt(DH)) * log2(e) -> softmax in base-2 domain
#define QSCALE 0.1803368801111204f

// ---------------- scratch (static device globals) ----------------
__device__ float g_x[M_*C_];
__device__ __align__(16) __half g_hh[M_*C_],  g_hl[M_*C_];
__device__ __align__(16) __half g_qkvh[3*M_*C_], g_qkvl[3*M_*C_];
__device__ __align__(16) __half g_yh[M_*C_];
__device__ __align__(16) __half g_uh[(size_t)M_*FF_];
__device__ __align__(16) __half g_wh[WTOT],   g_wl[WTOT];
__device__ float g_bqkv[L_*3*C_];

// ================= helpers =================
__device__ __forceinline__ uint32_t smem_u32(const void* p) {
    uint32_t a;
    asm("{ .reg .u64 t; cvta.to.shared.u64 t, %1; cvt.u32.u64 %0, t; }" : "=r"(a) : "l"(p));
    return a;
}
__device__ __forceinline__ void mma16816(float* c, const uint32_t* a, uint32_t b0, uint32_t b1) {
    asm volatile(
        "mma.sync.aligned.m16n8k16.row.col.f32.f16.f16.f32 "
        "{%0,%1,%2,%3}, {%4,%5,%6,%7}, {%8,%9}, {%0,%1,%2,%3};"
        : "+f"(c[0]), "+f"(c[1]), "+f"(c[2]), "+f"(c[3])
        : "r"(a[0]), "r"(a[1]), "r"(a[2]), "r"(a[3]), "r"(b0), "r"(b1));
}
__device__ __forceinline__ void ldsm4(uint32_t* r, uint32_t addr) {
    asm volatile("ldmatrix.sync.aligned.m8n8.x4.shared.b16 {%0,%1,%2,%3}, [%4];"
                 : "=r"(r[0]), "=r"(r[1]), "=r"(r[2]), "=r"(r[3]) : "r"(addr));
}
__device__ __forceinline__ void ldsm4t(uint32_t* r, uint32_t addr) {
    asm volatile("ldmatrix.sync.aligned.m8n8.x4.trans.shared.b16 {%0,%1,%2,%3}, [%4];"
                 : "=r"(r[0]), "=r"(r[1]), "=r"(r[2]), "=r"(r[3]) : "r"(addr));
}
#define CP_ASYNC16(dst, src) \
    asm volatile("cp.async.cg.shared.global [%0], [%1], 16;" :: "r"(dst), "l"(src))
#define CP_COMMIT asm volatile("cp.async.commit_group;" ::: "memory")
#define CP_WAIT(n) asm volatile("cp.async.wait_group %0;" :: "n"(n) : "memory")

__device__ __forceinline__ float fex2(float x) {
    float y;
    asm("ex2.approx.f32 %0, %1;" : "=f"(y) : "f"(x));
    return y;
}
__device__ __forceinline__ void split2(float x, float y, uint32_t& h, uint32_t& l) {
    __half2 hh = __floats2half2_rn(x, y);
    float2 hf = __half22float2(hh);
    __half2 ll = __floats2half2_rn(x - hf.x, y - hf.y);
    h = *(uint32_t*)&hh;
    l = *(uint32_t*)&ll;
}
__device__ __forceinline__ uint32_t pack_h2(float x, float y) {
    __half2 hh = __floats2half2_rn(x, y);
    return *(uint32_t*)&hh;
}
__device__ __forceinline__ float gelu_exact(float v) {
    return 0.5f * v * (1.0f + erff(v * 0.70710678118654752f));
}

// ================= fused weight conversion (single launch) =================
__global__ void __launch_bounds__(256) conv_all(
    const float* __restrict__ Wq, const float* __restrict__ Wk,
    const float* __restrict__ Wv, const float* __restrict__ Wo,
    const float* __restrict__ W1, const float* __restrict__ W2,
    const float* __restrict__ Whd,
    __half* __restrict__ dh, __half* __restrict__ dl)
{
    const size_t i = ((size_t)blockIdx.x * 256 + threadIdx.x) * 8;
    const float* src;
    if (i >= WHEAD_OFF) {
        src = Whd + (i - WHEAD_OFF);
    } else {
        const int l = (int)(i / WPL_);
        const size_t r = i % WPL_;
        if      (r <   (size_t)CC_)   src = Wq + (size_t)l*CC_   + r;
        else if (r < 2*(size_t)CC_)   src = Wk + (size_t)l*CC_   + (r -   CC_);
        else if (r < 3*(size_t)CC_)   src = Wv + (size_t)l*CC_   + (r - 2*CC_);
        else if (r < 4*(size_t)CC_)   src = Wo + (size_t)l*CC_   + (r - 3*CC_);
        else if (r < 8*(size_t)CC_)   src = W1 + (size_t)l*4*CC_ + (r - 4*CC_);
        else                          src = W2 + (size_t)l*4*CC_ + (r - 8*CC_);
    }
    float4 a = *(const float4*)(src), b = *(const float4*)(src + 4);
    uint32_t h[4], l4[4];
    split2(a.x, a.y, h[0], l4[0]); split2(a.z, a.w, h[1], l4[1]);
    split2(b.x, b.y, h[2], l4[2]); split2(b.z, b.w, h[3], l4[3]);
    *(uint4*)(dh + i) = make_uint4(h[0], h[1], h[2], h[3]);
    *(uint4*)(dl + i) = make_uint4(l4[0], l4[1], l4[2], l4[3]);
}
__global__ void __launch_bounds__(256) packqkvb(
    const float* __restrict__ bq, const float* __restrict__ bk,
    const float* __restrict__ bv, float* __restrict__ dst)
{
    int idx = blockIdx.x * 256 + threadIdx.x;      // L_*3072
    int l = idx / 3072, c = idx % 3072;
    float v = (c < 1024) ? bq[l*1024 + c] : (c < 2048) ? bk[l*1024 + c - 1024]
                                                        : bv[l*1024 + c - 2048];
    dst[idx] = v;
}

// ================= x = seq + pos =================
__global__ void __launch_bounds__(256) addpos_kernel(
    const float* __restrict__ seq, const float* __restrict__ pos, float* __restrict__ x)
{
    int i = blockIdx.x * 256 + threadIdx.x;
    float4 s = ((const float4*)seq)[i];
    float4 p = ((const float4*)pos)[i & (T_*C_/4 - 1)];
    s.x += p.x; s.y += p.y; s.z += p.z; s.w += p.w;
    ((float4*)x)[i] = s;
}

// ================= LayerNorm -> fp16 hi (+ optional lo) =================
__global__ void __launch_bounds__(256) ln_split(
    const float* __restrict__ x, const float* __restrict__ w,
    const float* __restrict__ b, __half* __restrict__ outh, __half* __restrict__ outl)
{
    const int row = blockIdx.x;
    const int t = threadIdx.x;
    const float4 v = *(const float4*)(x + (size_t)row * C_ + t * 4);
    float s  = v.x + v.y + v.z + v.w;
    float sq = v.x*v.x + v.y*v.y + v.z*v.z + v.w*v.w;
    #pragma unroll
    for (int off = 16; off; off >>= 1) {
        s  += __shfl_xor_sync(0xffffffffu, s,  off);
        sq += __shfl_xor_sync(0xffffffffu, sq, off);
    }
    __shared__ float rs_[8], rq_[8];
    if ((t & 31) == 0) { rs_[t >> 5] = s; rq_[t >> 5] = sq; }
    __syncthreads();
    s = 0.f; sq = 0.f;
    #pragma unroll
    for (int i = 0; i < 8; i++) { s += rs_[i]; sq += rq_[i]; }
    const float mu   = s * (1.0f / 1024.0f);
    const float var  = sq * (1.0f / 1024.0f) - mu * mu;
    const float rstd = rsqrtf(var + 1e-5f);
    const float4 wv = *(const float4*)(w + t * 4);
    const float4 bv = *(const float4*)(b + t * 4);
    float ox = (v.x - mu) * rstd * wv.x + bv.x;
    float oy = (v.y - mu) * rstd * wv.y + bv.y;
    float oz = (v.z - mu) * rstd * wv.z + bv.z;
    float ow = (v.w - mu) * rstd * wv.w + bv.w;
    uint32_t h0, l0, h1, l1;
    split2(ox, oy, h0, l0);
    split2(oz, ow, h1, l1);
    *(uint2*)(outh + (size_t)row * C_ + t * 4) = make_uint2(h0, h1);
    if (outl) *(uint2*)(outl + (size_t)row * C_ + t * 4) = make_uint2(l0, l1);
}

// ================= split-fp16 pipelined GEMM =================
// D[M,N] = A[M,K] @ W[N,K]^T.
// PASSES==2: Ah·Bh + Ah·Bl (A lo never read; stage 48KB).
// PASSES==3: + Al·Bh (stage 64KB) — used for head GEMM only.
// EPI: 0 = fp32 out, 1 = +bias -> qkv split out (q third scaled by QSCALE),
//      2 = +bias+GELU -> fp16 hi out, 3 = +bias+residual -> fp32 out

template <int EPI, int PASSES>
__global__ void __launch_bounds__(256, 1) gemm_h(
    const __half* __restrict__ Ah, const __half* __restrict__ Al,
    const __half* __restrict__ Wh, const __half* __restrict__ Wl,
    const float* __restrict__ bias, const float* __restrict__ resid,
    float* __restrict__ outf, __half* __restrict__ outh, __half* __restrict__ outl,
    int N, int K)
{
    constexpr uint32_t AL_OFF = 16384u;                          // PASSES==3 only
    constexpr uint32_t BH_OFF = (PASSES == 3) ? 32768u : 16384u;
    constexpr uint32_t BL_OFF = BH_OFF + 16384u;
    constexpr uint32_t STG    = (PASSES == 3) ? 65536u : 49152u;

    extern __shared__ char sm[];
    const uint32_t sb = smem_u32(sm);
    const int t = threadIdx.x, w = t >> 5, lane = t & 31;
    const int bm = blockIdx.y, bn = blockIdx.x;
    const int wm = w & 3, wn = w >> 2;

    const int crow = t >> 1, chalf = t & 1;
    const __half* agh = Ah + (size_t)(bm*128 + crow) * K + chalf*32;
    const __half* agl = (PASSES == 3) ? (Al + (size_t)(bm*128 + crow) * K + chalf*32) : nullptr;
    const __half* bgh = Wh + (size_t)(bn*128 + crow) * K + chalf*32;
    const __half* bgl = Wl + (size_t)(bn*128 + crow) * K + chalf*32;
    uint32_t dsto[4];
    #pragma unroll
    for (int i = 0; i < 4; i++) {
        int c16 = chalf*4 + i;
        dsto[i] = (uint32_t)(crow*128 + ((c16 ^ (crow & 7)) << 4));
    }
    auto load_stage = [&](int c, int slot) {
        const uint32_t s0 = sb + (uint32_t)slot * STG;
        const __half* a0 = agh + c*64;
        const __half* b0 = bgh + c*64;
        const __half* b1 = bgl + c*64;
        #pragma unroll
        for (int i = 0; i < 4; i++) CP_ASYNC16(s0 + dsto[i],          a0 + i*8);
        if (PASSES == 3) {
            const __half* a1 = agl + c*64;
            #pragma unroll
            for (int i = 0; i < 4; i++) CP_ASYNC16(s0 + AL_OFF + dsto[i], a1 + i*8);
        }
        #pragma unroll
        for (int i = 0; i < 4; i++) CP_ASYNC16(s0 + BH_OFF + dsto[i], b0 + i*8);
        #pragma unroll
        for (int i = 0; i < 4; i++) CP_ASYNC16(s0 + BL_OFF + dsto[i], b1 + i*8);
    };

    // ldmatrix lane geometry
    const int ra = lane & 15, ca = lane >> 4;
    const int rb = (lane & 7) + ((lane >> 4) << 3), cb = (lane >> 3) & 1;
    const int xr = lane & 7;
    const uint32_t aro = (uint32_t)((wm*32 + ra) * 128);
    const uint32_t bro = (uint32_t)((wn*64 + rb) * 128);

    float acc[2][8][4];
    #pragma unroll
    for (int i = 0; i < 2; i++)
        #pragma unroll
        for (int j = 0; j < 8; j++)
            #pragma unroll
            for (int r = 0; r < 4; r++) acc[i][j][r] = 0.f;

    load_stage(0, 0); CP_COMMIT;
    load_stage(1, 1); CP_COMMIT;

    const int NC = K >> 6;
    int slot = 0;
    for (int c = 0; c < NC; c++) {
        CP_WAIT(1);
        __syncthreads();
        if (c + 2 < NC) {
            int ns = slot + 2; if (ns >= 3) ns -= 3;
            load_stage(c + 2, ns);
        }
        CP_COMMIT;
        const uint32_t st = sb + (uint32_t)slot * STG;
        #pragma unroll
        for (int ks = 0; ks < 4; ks++) {
            const uint32_t kca = (uint32_t)(((ks*2 + ca) ^ xr) << 4);
            const uint32_t kcb = (uint32_t)(((ks*2 + cb) ^ xr) << 4);
            uint32_t ah[2][4], al4[2][4], bh[4][4], bl4[4][4];
            #pragma unroll
            for (int mt = 0; mt < 2; mt++) {
                ldsm4(ah[mt],  st + aro + mt*2048u + kca);
                if (PASSES == 3) ldsm4(al4[mt], st + AL_OFF + aro + mt*2048u + kca);
            }
            #pragma unroll
            for (int nq = 0; nq < 4; nq++) {
                ldsm4(bh[nq],  st + BH_OFF + bro + nq*2048u + kcb);
                ldsm4(bl4[nq], st + BL_OFF + bro + nq*2048u + kcb);
            }
            // pass-major: 16 independent accs between reuses
            #pragma unroll
            for (int mt = 0; mt < 2; mt++)
                #pragma unroll
                for (int nt = 0; nt < 8; nt++) {
                    const int nq = nt >> 1, s2 = (nt & 1) * 2;
                    mma16816(acc[mt][nt], ah[mt], bh[nq][s2], bh[nq][s2+1]);
                }
            #pragma unroll
            for (int mt = 0; mt < 2; mt++)
                #pragma unroll
                for (int nt = 0; nt < 8; nt++) {
                    const int nq = nt >> 1, s2 = (nt & 1) * 2;
                    mma16816(acc[mt][nt], ah[mt], bl4[nq][s2], bl4[nq][s2+1]);
                }
            if (PASSES == 3) {
                #pragma unroll
                for (int mt = 0; mt < 2; mt++)
                    #pragma unroll
                    for (int nt = 0; nt < 8; nt++) {
                        const int nq = nt >> 1, s2 = (nt & 1) * 2;
                        mma16816(acc[mt][nt], al4[mt], bh[nq][s2], bh[nq][s2+1]);
                    }
            }
        }
        slot = (slot + 1 == 3) ? 0 : slot + 1;
    }

    // ---- epilogue ----
    const int grbase = bm*128 + wm*32;
    const int gcbase = bn*128 + wn*64;
    #pragma unroll
    for (int mt = 0; mt < 2; mt++) {
        const int r0 = grbase + mt*16 + (lane >> 2);
        #pragma unroll
        for (int nt = 0; nt < 8; nt++) {
            const int gc = gcbase + nt*8 + (lane & 3)*2;
            float2 v0 = make_float2(acc[mt][nt][0], acc[mt][nt][1]);
            float2 v1 = make_float2(acc[mt][nt][2], acc[mt][nt][3]);
            if (EPI >= 1) {
                float2 bb = *(const float2*)(bias + gc);
                v0.x += bb.x; v0.y += bb.y; v1.x += bb.x; v1.y += bb.y;
            }
            if (EPI == 1) {
                const int third = gc >> 10, lc = gc & 1023;
                if (third == 0) {   // q: fold softmax scale + log2e
                    v0.x *= QSCALE; v0.y *= QSCALE; v1.x *= QSCALE; v1.y *= QSCALE;
                }
                __half* oh = outh + (size_t)third * ((size_t)M_ * C_);
                __half* ol = outl + (size_t)third * ((size_t)M_ * C_);
                uint32_t h0, l0;
                split2(v0.x, v0.y, h0, l0);
                *(uint32_t*)(oh + (size_t)r0 * 1024 + lc) = h0;
                *(uint32_t*)(ol + (size_t)r0 * 1024 + lc) = l0;
                split2(v1.x, v1.y, h0, l0);
                *(uint32_t*)(oh + (size_t)(r0+8) * 1024 + lc) = h0;
                *(uint32_t*)(ol + (size_t)(r0+8) * 1024 + lc) = l0;
            } else if (EPI == 2) {
                v0.x = gelu_exact(v0.x); v0.y = gelu_exact(v0.y);
                v1.x = gelu_exact(v1.x); v1.y = gelu_exact(v1.y);
                *(uint32_t*)(outh + (size_t)r0 * N + gc)     = pack_h2(v0.x, v0.y);
                *(uint32_t*)(outh + (size_t)(r0+8) * N + gc) = pack_h2(v1.x, v1.y);
            } else if (EPI == 3) {
                float2 ra2 = *(const float2*)(resid + (size_t)r0 * N + gc);
                float2 rb2 = *(const float2*)(resid + (size_t)(r0+8) * N + gc);
                v0.x += ra2.x; v0.y += ra2.y; v1.x += rb2.x; v1.y += rb2.y;
                *(float2*)(outf + (size_t)r0 * N + gc) = v0;
                *(float2*)(outf + (size_t)(r0+8) * N + gc) = v1;
            } else {
                *(float2*)(outf + (size_t)r0 * N + gc) = v0;
                *(float2*)(outf + (size_t)(r0+8) * N + gc) = v1;
            }
        }
    }
}

#define GEMM_SMEM2 (3*49152)
#define GEMM_SMEM3 (3*65536)

// ================= flash attention (fp16 split inputs, 3-stage cp.async) =================
// Q tile 128, KV tile 64, DH=64. smem: Qh@0 Ql@16K (32KB), then 3 stages of 32KB:
// per stage: Kh@0 Kl@8K Vh@16K Vl@24K. Softmax in base-2 (q pre-scaled upstream).
#define ASTG 32768
#define AQSZ 32768
#define ATT_SMEM (AQSZ + 3*ASTG)

__global__ void __launch_bounds__(256, 1) attn_h(
    const __half* __restrict__ qkvh, const __half* __restrict__ qkvl,
    __half* __restrict__ yh)
{
    extern __shared__ char sm[];
    const uint32_t sb = smem_u32(sm);
    const int t = threadIdx.x, w = t >> 5, lane = t & 31;
    const int bhx = blockIdx.y, b = bhx >> 4, h = bhx & 15;
    const int q0 = blockIdx.x * 128;
    const size_t MC = (size_t)M_ * C_;
    const int NT = T_ / 64;   // 32 tiles

    const __half* qgh = qkvh + (size_t)(b*T_ + q0) * C_ + h*64;
    const __half* qgl = qkvl + (size_t)(b*T_ + q0) * C_ + h*64;
    const __half* kgh = qkvh + MC   + (size_t)(b*T_) * C_ + h*64;
    const __half* kgl = qkvl + MC   + (size_t)(b*T_) * C_ + h*64;
    const __half* vgh = qkvh + 2*MC + (size_t)(b*T_) * C_ + h*64;
    const __half* vgl = qkvl + 2*MC + (size_t)(b*T_) * C_ + h*64;

    // Q loads (group 0)
    {
        const int qr = t >> 1, qc = t & 1;
        #pragma unroll
        for (int i = 0; i < 4; i++) {
            const int c16 = qc*4 + i;
            const uint32_t d = (uint32_t)(qr*128 + ((c16 ^ (qr & 7)) << 4));
            CP_ASYNC16(sb + d,          qgh + (size_t)qr * C_ + c16*8);
            CP_ASYNC16(sb + 16384u + d, qgl + (size_t)qr * C_ + c16*8);
        }
    }
    CP_COMMIT;

    // KV stage loader
    const int kr = t >> 2, kc2 = (t & 3) * 2;
    auto load_kv = [&](int kt, int slot) {
        const uint32_t s0 = sb + AQSZ + (uint32_t)slot * ASTG;
        const size_t rowoff = (size_t)(kt*64 + kr) * C_;
        #pragma unroll
        for (int i = 0; i < 2; i++) {
            const int c16 = kc2 + i;
            const uint32_t d = (uint32_t)(kr*128 + ((c16 ^ (kr & 7)) << 4));
            CP_ASYNC16(s0 + d,          kgh + rowoff + c16*8);
            CP_ASYNC16(s0 + 8192u + d,  kgl + rowoff + c16*8);
            CP_ASYNC16(s0 + 16384u + d, vgh + rowoff + c16*8);
            CP_ASYNC16(s0 + 24576u + d, vgl + rowoff + c16*8);
        }
    };
    load_kv(0, 0); CP_COMMIT;
    load_kv(1, 1); CP_COMMIT;

    // ldmatrix lane geometry
    const int ra = lane & 15, ca = lane >> 4;
    const int rb = (lane & 7) + ((lane >> 4) << 3), cb = (lane >> 3) & 1;
    const int rv = (lane & 7) + (((lane >> 3) & 1) << 3), cv = lane >> 4;
    const int xr = lane & 7;

    CP_WAIT(2);           // Q (group 0) landed
    __syncthreads();
    uint32_t qh4[4][4], ql4[4][4];
    {
        const uint32_t qro = (uint32_t)((w*16 + ra) * 128);
        #pragma unroll
        for (int ks = 0; ks < 4; ks++) {
            const uint32_t off = qro + (uint32_t)(((ks*2 + ca) ^ xr) << 4);
            ldsm4(qh4[ks], sb + off);
            ldsm4(ql4[ks], sb + 16384u + off);
        }
    }

    float o_[8][4];
    #pragma unroll
    for (int i = 0; i < 8; i++)
        #pragma unroll
        for (int j = 0; j < 4; j++) o_[i][j] = 0.f;
    float m_a = -1e30f, m_b = -1e30f, l_a = 0.f, l_b = 0.f;

    int slot = 0;
    for (int kt = 0; kt < NT; kt++) {
        CP_WAIT(1);        // current stage landed; next may still be in flight
        __syncthreads();
        if (kt + 2 < NT) {
            int ns = slot + 2; if (ns >= 3) ns -= 3;
            load_kv(kt + 2, ns);
        }
        CP_COMMIT;
        const uint32_t st = sb + AQSZ + (uint32_t)slot * ASTG;

        // ---- S = Q K^T (3-pass), q pre-scaled by 0.125*log2e ----
        float sc[8][4];
        #pragma unroll
        for (int i = 0; i < 8; i++)
            #pragma unroll
            for (int j = 0; j < 4; j++) sc[i][j] = 0.f;
        #pragma unroll
        for (int ks = 0; ks < 4; ks++) {
            uint32_t kh4[4][4], kl4[4][4];
            #pragma unroll
            for (int nq = 0; nq < 4; nq++) {
                const uint32_t off = (uint32_t)((nq*16 + rb) * 128)
                                   + (uint32_t)(((ks*2 + cb) ^ xr) << 4);
                ldsm4(kh4[nq], st + off);
                ldsm4(kl4[nq], st + 8192u + off);
            }
            #pragma unroll
            for (int nt = 0; nt < 8; nt++) {
                const int nq = nt >> 1, s2 = (nt & 1) * 2;
                mma16816(sc[nt], qh4[ks], kh4[nq][s2], kh4[nq][s2+1]);
            }
            #pragma unroll
            for (int nt = 0; nt < 8; nt++) {
                const int nq = nt >> 1, s2 = (nt & 1) * 2;
                mma16816(sc[nt], qh4[ks], kl4[nq][s2], kl4[nq][s2+1]);
            }
            #pragma unroll
            for (int nt = 0; nt < 8; nt++) {
                const int nq = nt >> 1, s2 = (nt & 1) * 2;
                mma16816(sc[nt], ql4[ks], kh4[nq][s2], kh4[nq][s2+1]);
            }
        }

        // ---- online softmax (base-2) ----
        float mxa = -1e30f, mxb = -1e30f;
        #pragma unroll
        for (int nt = 0; nt < 8; nt++) {
            mxa = fmaxf(mxa, fmaxf(sc[nt][0], sc[nt][1]));
            mxb = fmaxf(mxb, fmaxf(sc[nt][2], sc[nt][3]));
        }
        mxa = fmaxf(mxa, __shfl_xor_sync(0xffffffffu, mxa, 1));
        mxa = fmaxf(mxa, __shfl_xor_sync(0xffffffffu, mxa, 2));
        mxb = fmaxf(mxb, __shfl_xor_sync(0xffffffffu, mxb, 1));
        mxb = fmaxf(mxb, __shfl_xor_sync(0xffffffffu, mxb, 2));
        const float nma = fmaxf(m_a, mxa), nmb = fmaxf(m_b, mxb);
        const float cfa = fex2(m_a - nma), cfb = fex2(m_b - nmb);
        m_a = nma; m_b = nmb;
        float rsa = 0.f, rsb = 0.f;
        #pragma unroll
        for (int nt = 0; nt < 8; nt++) {
            sc[nt][0] = fex2(sc[nt][0] - m_a); rsa += sc[nt][0];
            sc[nt][1] = fex2(sc[nt][1] - m_a); rsa += sc[nt][1];
            sc[nt][2] = fex2(sc[nt][2] - m_b); rsb += sc[nt][2];
            sc[nt][3] = fex2(sc[nt][3] - m_b); rsb += sc[nt][3];
        }
        rsa += __shfl_xor_sync(0xffffffffu, rsa, 1);
        rsa += __shfl_xor_sync(0xffffffffu, rsa, 2);
        rsb += __shfl_xor_sync(0xffffffffu, rsb, 1);
        rsb += __shfl_xor_sync(0xffffffffu, rsb, 2);
        l_a = l_a * cfa + rsa;
        l_b = l_b * cfb + rsb;
        #pragma unroll
        for (int dt = 0; dt < 8; dt++) {
            o_[dt][0] *= cfa; o_[dt][1] *= cfa; o_[dt][2] *= cfb; o_[dt][3] *= cfb;
        }

        // ---- O += P V (3-pass) ----
        #pragma unroll
        for (int ks = 0; ks < 4; ks++) {
            uint32_t ph[4], pl[4];
            split2(sc[2*ks][0],   sc[2*ks][1],   ph[0], pl[0]);
            split2(sc[2*ks][2],   sc[2*ks][3],   ph[1], pl[1]);
            split2(sc[2*ks+1][0], sc[2*ks+1][1], ph[2], pl[2]);
            split2(sc[2*ks+1][2], sc[2*ks+1][3], ph[3], pl[3]);
            uint32_t vh4[4][4], vl4[4][4];
            #pragma unroll
            for (int nq = 0; nq < 4; nq++) {
                const uint32_t off = (uint32_t)((ks*16 + rv) * 128)
                                   + (uint32_t)(((nq*2 + cv) ^ xr) << 4);
                ldsm4t(vh4[nq], st + 16384u + off);
                ldsm4t(vl4[nq], st + 24576u + off);
            }
            #pragma unroll
            for (int dt = 0; dt < 8; dt++) {
                const int nq = dt >> 1, s2 = (dt & 1) * 2;
                mma16816(o_[dt], ph, vh4[nq][s2], vh4[nq][s2+1]);
            }
            #pragma unroll
            for (int dt = 0; dt < 8; dt++) {
                const int nq = dt >> 1, s2 = (dt & 1) * 2;
                mma16816(o_[dt], ph, vl4[nq][s2], vl4[nq][s2+1]);
            }
            #pragma unroll
            for (int dt = 0; dt < 8; dt++) {
                const int nq = dt >> 1, s2 = (dt & 1) * 2;
                mma16816(o_[dt], pl, vh4[nq][s2], vh4[nq][s2+1]);
            }
        }
        slot = (slot + 1 == 3) ? 0 : slot + 1;
    }

    // ---- write y (fp16 hi only; Wo GEMM is 2-pass) ----
    const float ia = 1.f / l_a, ib = 1.f / l_b;
    const int r0 = q0 + w*16 + (lane >> 2);
    __half* ybh = yh + (size_t)(b*T_ + r0) * C_ + h*64;
    #pragma unroll
    for (int dt = 0; dt < 8; dt++) {
        const int gc = dt*8 + (lane & 3)*2;
        *(uint32_t*)(ybh + gc)                 = pack_h2(o_[dt][0]*ia, o_[dt][1]*ia);
        *(uint32_t*)(ybh + (size_t)8*C_ + gc)  = pack_h2(o_[dt][2]*ib, o_[dt][3]*ib);
    }
}

// ================= orchestration =================
extern "C" void kernel_launch(void* const* d_in, const int* in_sizes, int n_in,
                              void* d_out, int out_size)
{
    const float* seq  = (const float*)d_in[0];
    const float* pos  = (const float*)d_in[1];
    const float* Wq   = (const float*)d_in[2];
    const float* bq   = (const float*)d_in[3];
    const float* Wk   = (const float*)d_in[4];
    const float* bk   = (const float*)d_in[5];
    const float* Wv   = (const float*)d_in[6];
    const float* bv   = (const float*)d_in[7];
    const float* Wo   = (const float*)d_in[8];
    const float* bo   = (const float*)d_in[9];
    const float* ln1w = (const float*)d_in[10];
    const float* ln1b = (const float*)d_in[11];
    const float* ln2w = (const float*)d_in[12];
    const float* ln2b = (const float*)d_in[13];
    const float* W1   = (const float*)d_in[14];
    const float* b1   = (const float*)d_in[15];
    const float* W2   = (const float*)d_in[16];
    const float* b2   = (const float*)d_in[17];
    const float* lnfw = (const float*)d_in[18];
    const float* lnfb = (const float*)d_in[19];
    const float* Wh   = (const float*)d_in[20];
    float* out = (float*)d_out;

    float *px, *pbqkv;
    __half *phh, *phl, *pqkvh, *pqkvl, *pyh, *puh, *pwh, *pwl;
    cudaGetSymbolAddress((void**)&px, g_x);
    cudaGetSymbolAddress((void**)&phh, g_hh);
    cudaGetSymbolAddress((void**)&phl, g_hl);
    cudaGetSymbolAddress((void**)&pqkvh, g_qkvh);
    cudaGetSymbolAddress((void**)&pqkvl, g_qkvl);
    cudaGetSymbolAddress((void**)&pyh, g_yh);
    cudaGetSymbolAddress((void**)&puh, g_uh);
    cudaGetSymbolAddress((void**)&pwh, g_wh);
    cudaGetSymbolAddress((void**)&pwl, g_wl);
    cudaGetSymbolAddress((void**)&pbqkv, g_bqkv);

    cudaFuncSetAttribute(attn_h, cudaFuncAttributeMaxDynamicSharedMemorySize, ATT_SMEM);
    cudaFuncSetAttribute((gemm_h<1,2>), cudaFuncAttributeMaxDynamicSharedMemorySize, GEMM_SMEM2);
    cudaFuncSetAttribute((gemm_h<2,2>), cudaFuncAttributeMaxDynamicSharedMemorySize, GEMM_SMEM2);
    cudaFuncSetAttribute((gemm_h<3,2>), cudaFuncAttributeMaxDynamicSharedMemorySize, GEMM_SMEM2);
    cudaFuncSetAttribute((gemm_h<0,3>), cudaFuncAttributeMaxDynamicSharedMemorySize, GEMM_SMEM3);

    // ---- weight conversion: ONE launch ----
    conv_all<<<(int)(WTOT / 2048), 256>>>(Wq, Wk, Wv, Wo, W1, W2, Wh, pwh, pwl);
    packqkvb<<<L_*3*C_/256, 256>>>(bq, bk, bv, pbqkv);
    addpos_kernel<<<M_ * C_ / 4 / 256, 256>>>(seq, pos, px);

    dim3 gQKV(3*C_ / 128, M_ / 128);   // (24, 64)
    dim3 gC(C_ / 128, M_ / 128);       // (8, 64)
    dim3 gF(FF_ / 128, M_ / 128);      // (32, 64)
    dim3 gA(T_ / 128, B_ * H_);        // (16, 64)

    for (int l = 0; l < L_; l++) {
        const size_t wl = (size_t)l * WPL_;
        ln_split<<<M_, 256>>>(px, ln1w + l*C_, ln1b + l*C_, phh, nullptr);
        gemm_h<1,2><<<gQKV, 256, GEMM_SMEM2>>>(phh, nullptr, pwh + wl, pwl + wl,
            pbqkv + l*3*C_, nullptr, nullptr, pqkvh, pqkvl, 3*C_, C_);
        attn_h<<<gA, 256, ATT_SMEM>>>(pqkvh, pqkvl, pyh);
        gemm_h<3,2><<<gC, 256, GEMM_SMEM2>>>(pyh, nullptr, pwh + wl + WOFF_WO, pwl + wl + WOFF_WO,
            bo + l*C_, px, px, nullptr, nullptr, C_, C_);
        ln_split<<<M_, 256>>>(px, ln2w + l*C_, ln2b + l*C_, phh, nullptr);
        gemm_h<2,2><<<gF, 256, GEMM_SMEM2>>>(phh, nullptr, pwh + wl + WOFF_W1, pwl + wl + WOFF_W1,
            b1 + l*FF_, nullptr, nullptr, puh, nullptr, FF_, C_);
        gemm_h<3,2><<<gC, 256, GEMM_SMEM2>>>(puh, nullptr, pwh + wl + WOFF_W2, pwl + wl + WOFF_W2,
            b2 + l*C_, px, px, nullptr, nullptr, C_, FF_);
    }

    // final LN needs lo for the 3-pass head GEMM
    ln_split<<<M_, 256>>>(px, lnfw, lnfb, phh, phl);
    gemm_h<0,3><<<gC, 256, GEMM_SMEM3>>>(phh, phl, pwh + WHEAD_OFF, pwl + WHEAD_OFF,
        nullptr, nullptr, out, nullptr, nullptr, OUT_, C_);
}

// round 8
// speedup vs baseline: 3.7306x; 1.0669x over previous
#include <cuda_runtime.h>
#include <cuda_fp16.h>
#include <math.h>
#include <stdint.h>

#define L_ 8
#define H_ 16
#define T_ 2048
#define C_ 1024
#define OUT_ 1024
#define B_ 4
#define DH_ 64
#define FF_ 4096
#define M_ (B_*T_)   // 8192 rows

#define CC_ (C_*C_)                   // 1048576
#define WPL_ (12*CC_)                 // weights per layer (halves)
#define WOFF_WO  (3*CC_)
#define WOFF_W1  (4*CC_)
#define WOFF_W2  (8*CC_)
#define WHEAD_OFF ((size_t)L_*WPL_)   // 100663296
#define WTOT (WHEAD_OFF + CC_)        // 101711872

// q pre-scale: 0.125 (1/sqrt(DH)) * log2(e) -> softmax in base-2 domain
#define QSCALE 0.1803368801111204f

// ---------------- scratch (static device globals) ----------------
__device__ float g_x[M_*C_];
__device__ __align__(16) __half g_hh[M_*C_],  g_hl[M_*C_];
__device__ __align__(16) __half g_qkvh[3*M_*C_], g_qkvl[3*M_*C_];
__device__ __align__(16) __half g_yh[M_*C_];
__device__ __align__(16) __half g_uh[(size_t)M_*FF_];
__device__ __align__(16) __half g_wh[WTOT],   g_wl[WTOT];
__device__ float g_bqkv[L_*3*C_];

// ================= helpers =================
__device__ __forceinline__ uint32_t smem_u32(const void* p) {
    uint32_t a;
    asm("{ .reg .u64 t; cvta.to.shared.u64 t, %1; cvt.u32.u64 %0, t; }" : "=r"(a) : "l"(p));
    return a;
}
__device__ __forceinline__ void mma16816(float* c, const uint32_t* a, uint32_t b0, uint32_t b1) {
    asm volatile(
        "mma.sync.aligned.m16n8k16.row.col.f32.f16.f16.f32 "
        "{%0,%1,%2,%3}, {%4,%5,%6,%7}, {%8,%9}, {%0,%1,%2,%3};"
        : "+f"(c[0]), "+f"(c[1]), "+f"(c[2]), "+f"(c[3])
        : "r"(a[0]), "r"(a[1]), "r"(a[2]), "r"(a[3]), "r"(b0), "r"(b1));
}
__device__ __forceinline__ void ldsm4(uint32_t* r, uint32_t addr) {
    asm volatile("ldmatrix.sync.aligned.m8n8.x4.shared.b16 {%0,%1,%2,%3}, [%4];"
                 : "=r"(r[0]), "=r"(r[1]), "=r"(r[2]), "=r"(r[3]) : "r"(addr));
}
__device__ __forceinline__ void ldsm4t(uint32_t* r, uint32_t addr) {
    asm volatile("ldmatrix.sync.aligned.m8n8.x4.trans.shared.b16 {%0,%1,%2,%3}, [%4];"
                 : "=r"(r[0]), "=r"(r[1]), "=r"(r[2]), "=r"(r[3]) : "r"(addr));
}
#define CP_ASYNC16(dst, src) \
    asm volatile("cp.async.cg.shared.global [%0], [%1], 16;" :: "r"(dst), "l"(src))
#define CP_COMMIT asm volatile("cp.async.commit_group;" ::: "memory")
#define CP_WAIT(n) asm volatile("cp.async.wait_group %0;" :: "n"(n) : "memory")

__device__ __forceinline__ float fex2(float x) {
    float y;
    asm("ex2.approx.f32 %0, %1;" : "=f"(y) : "f"(x));
    return y;
}
__device__ __forceinline__ void split2(float x, float y, uint32_t& h, uint32_t& l) {
    __half2 hh = __floats2half2_rn(x, y);
    float2 hf = __half22float2(hh);
    __half2 ll = __floats2half2_rn(x - hf.x, y - hf.y);
    h = *(uint32_t*)&hh;
    l = *(uint32_t*)&ll;
}
__device__ __forceinline__ uint32_t pack_h2(float x, float y) {
    __half2 hh = __floats2half2_rn(x, y);
    return *(uint32_t*)&hh;
}
__device__ __forceinline__ float gelu_exact(float v) {
    return 0.5f * v * (1.0f + erff(v * 0.70710678118654752f));
}

// ================= fused weight conversion (single launch) =================
__global__ void __launch_bounds__(256) conv_all(
    const float* __restrict__ Wq, const float* __restrict__ Wk,
    const float* __restrict__ Wv, const float* __restrict__ Wo,
    const float* __restrict__ W1, const float* __restrict__ W2,
    const float* __restrict__ Whd,
    __half* __restrict__ dh, __half* __restrict__ dl)
{
    const size_t i = ((size_t)blockIdx.x * 256 + threadIdx.x) * 8;
    const float* src;
    if (i >= WHEAD_OFF) {
        src = Whd + (i - WHEAD_OFF);
    } else {
        const int l = (int)(i / WPL_);
        const size_t r = i % WPL_;
        if      (r <   (size_t)CC_)   src = Wq + (size_t)l*CC_   + r;
        else if (r < 2*(size_t)CC_)   src = Wk + (size_t)l*CC_   + (r -   CC_);
        else if (r < 3*(size_t)CC_)   src = Wv + (size_t)l*CC_   + (r - 2*CC_);
        else if (r < 4*(size_t)CC_)   src = Wo + (size_t)l*CC_   + (r - 3*CC_);
        else if (r < 8*(size_t)CC_)   src = W1 + (size_t)l*4*CC_ + (r - 4*CC_);
        else                          src = W2 + (size_t)l*4*CC_ + (r - 8*CC_);
    }
    float4 a = *(const float4*)(src), b = *(const float4*)(src + 4);
    uint32_t h[4], l4[4];
    split2(a.x, a.y, h[0], l4[0]); split2(a.z, a.w, h[1], l4[1]);
    split2(b.x, b.y, h[2], l4[2]); split2(b.z, b.w, h[3], l4[3]);
    *(uint4*)(dh + i) = make_uint4(h[0], h[1], h[2], h[3]);
    *(uint4*)(dl + i) = make_uint4(l4[0], l4[1], l4[2], l4[3]);
}
__global__ void __launch_bounds__(256) packqkvb(
    const float* __restrict__ bq, const float* __restrict__ bk,
    const float* __restrict__ bv, float* __restrict__ dst)
{
    int idx = blockIdx.x * 256 + threadIdx.x;      // L_*3072
    int l = idx / 3072, c = idx % 3072;
    float v = (c < 1024) ? bq[l*1024 + c] : (c < 2048) ? bk[l*1024 + c - 1024]
                                                        : bv[l*1024 + c - 2048];
    dst[idx] = v;
}

// ================= x = seq + pos =================
__global__ void __launch_bounds__(256) addpos_kernel(
    const float* __restrict__ seq, const float* __restrict__ pos, float* __restrict__ x)
{
    int i = blockIdx.x * 256 + threadIdx.x;
    float4 s = ((const float4*)seq)[i];
    float4 p = ((const float4*)pos)[i & (T_*C_/4 - 1)];
    s.x += p.x; s.y += p.y; s.z += p.z; s.w += p.w;
    ((float4*)x)[i] = s;
}

// ================= LayerNorm -> fp16 hi (+ optional lo) =================
__global__ void __launch_bounds__(256) ln_split(
    const float* __restrict__ x, const float* __restrict__ w,
    const float* __restrict__ b, __half* __restrict__ outh, __half* __restrict__ outl)
{
    const int row = blockIdx.x;
    const int t = threadIdx.x;
    const float4 v = *(const float4*)(x + (size_t)row * C_ + t * 4);
    float s  = v.x + v.y + v.z + v.w;
    float sq = v.x*v.x + v.y*v.y + v.z*v.z + v.w*v.w;
    #pragma unroll
    for (int off = 16; off; off >>= 1) {
        s  += __shfl_xor_sync(0xffffffffu, s,  off);
        sq += __shfl_xor_sync(0xffffffffu, sq, off);
    }
    __shared__ float rs_[8], rq_[8];
    if ((t & 31) == 0) { rs_[t >> 5] = s; rq_[t >> 5] = sq; }
    __syncthreads();
    s = 0.f; sq = 0.f;
    #pragma unroll
    for (int i = 0; i < 8; i++) { s += rs_[i]; sq += rq_[i]; }
    const float mu   = s * (1.0f / 1024.0f);
    const float var  = sq * (1.0f / 1024.0f) - mu * mu;
    const float rstd = rsqrtf(var + 1e-5f);
    const float4 wv = *(const float4*)(w + t * 4);
    const float4 bv = *(const float4*)(b + t * 4);
    float ox = (v.x - mu) * rstd * wv.x + bv.x;
    float oy = (v.y - mu) * rstd * wv.y + bv.y;
    float oz = (v.z - mu) * rstd * wv.z + bv.z;
    float ow = (v.w - mu) * rstd * wv.w + bv.w;
    uint32_t h0, l0, h1, l1;
    split2(ox, oy, h0, l0);
    split2(oz, ow, h1, l1);
    *(uint2*)(outh + (size_t)row * C_ + t * 4) = make_uint2(h0, h1);
    if (outl) *(uint2*)(outl + (size_t)row * C_ + t * 4) = make_uint2(l0, l1);
}

// ================= split-fp16 pipelined GEMM =================
// D[M,N] = A[M,K] @ W[N,K]^T.
// PASSES==2: Ah·Bh + Ah·Bl (A lo never read; stage 48KB).
// PASSES==3: + Al·Bh (stage 64KB) — used for head GEMM only.
// EPI: 0 = fp32 out, 1 = +bias -> qkv out (q third: scaled, hi only; k/v: hi+lo),
//      2 = +bias+GELU -> fp16 hi out, 3 = +bias+residual -> fp32 out

template <int EPI, int PASSES>
__global__ void __launch_bounds__(256, 1) gemm_h(
    const __half* __restrict__ Ah, const __half* __restrict__ Al,
    const __half* __restrict__ Wh, const __half* __restrict__ Wl,
    const float* __restrict__ bias, const float* __restrict__ resid,
    float* __restrict__ outf, __half* __restrict__ outh, __half* __restrict__ outl,
    int N, int K)
{
    constexpr uint32_t AL_OFF = 16384u;                          // PASSES==3 only
    constexpr uint32_t BH_OFF = (PASSES == 3) ? 32768u : 16384u;
    constexpr uint32_t BL_OFF = BH_OFF + 16384u;
    constexpr uint32_t STG    = (PASSES == 3) ? 65536u : 49152u;

    extern __shared__ char sm[];
    const uint32_t sb = smem_u32(sm);
    const int t = threadIdx.x, w = t >> 5, lane = t & 31;
    const int bm = blockIdx.y, bn = blockIdx.x;
    const int wm = w & 3, wn = w >> 2;

    const int crow = t >> 1, chalf = t & 1;
    const __half* agh = Ah + (size_t)(bm*128 + crow) * K + chalf*32;
    const __half* agl = (PASSES == 3) ? (Al + (size_t)(bm*128 + crow) * K + chalf*32) : nullptr;
    const __half* bgh = Wh + (size_t)(bn*128 + crow) * K + chalf*32;
    const __half* bgl = Wl + (size_t)(bn*128 + crow) * K + chalf*32;
    uint32_t dsto[4];
    #pragma unroll
    for (int i = 0; i < 4; i++) {
        int c16 = chalf*4 + i;
        dsto[i] = (uint32_t)(crow*128 + ((c16 ^ (crow & 7)) << 4));
    }
    auto load_stage = [&](int c, int slot) {
        const uint32_t s0 = sb + (uint32_t)slot * STG;
        const __half* a0 = agh + c*64;
        const __half* b0 = bgh + c*64;
        const __half* b1 = bgl + c*64;
        #pragma unroll
        for (int i = 0; i < 4; i++) CP_ASYNC16(s0 + dsto[i],          a0 + i*8);
        if (PASSES == 3) {
            const __half* a1 = agl + c*64;
            #pragma unroll
            for (int i = 0; i < 4; i++) CP_ASYNC16(s0 + AL_OFF + dsto[i], a1 + i*8);
        }
        #pragma unroll
        for (int i = 0; i < 4; i++) CP_ASYNC16(s0 + BH_OFF + dsto[i], b0 + i*8);
        #pragma unroll
        for (int i = 0; i < 4; i++) CP_ASYNC16(s0 + BL_OFF + dsto[i], b1 + i*8);
    };

    // ldmatrix lane geometry
    const int ra = lane & 15, ca = lane >> 4;
    const int rb = (lane & 7) + ((lane >> 4) << 3), cb = (lane >> 3) & 1;
    const int xr = lane & 7;
    const uint32_t aro = (uint32_t)((wm*32 + ra) * 128);
    const uint32_t bro = (uint32_t)((wn*64 + rb) * 128);

    float acc[2][8][4];
    #pragma unroll
    for (int i = 0; i < 2; i++)
        #pragma unroll
        for (int j = 0; j < 8; j++)
            #pragma unroll
            for (int r = 0; r < 4; r++) acc[i][j][r] = 0.f;

    load_stage(0, 0); CP_COMMIT;
    load_stage(1, 1); CP_COMMIT;

    const int NC = K >> 6;
    int slot = 0;
    for (int c = 0; c < NC; c++) {
        CP_WAIT(1);
        __syncthreads();
        if (c + 2 < NC) {
            int ns = slot + 2; if (ns >= 3) ns -= 3;
            load_stage(c + 2, ns);
        }
        CP_COMMIT;
        const uint32_t st = sb + (uint32_t)slot * STG;
        #pragma unroll
        for (int ks = 0; ks < 4; ks++) {
            const uint32_t kca = (uint32_t)(((ks*2 + ca) ^ xr) << 4);
            const uint32_t kcb = (uint32_t)(((ks*2 + cb) ^ xr) << 4);
            uint32_t ah[2][4], al4[2][4], bh[4][4], bl4[4][4];
            #pragma unroll
            for (int mt = 0; mt < 2; mt++) {
                ldsm4(ah[mt],  st + aro + mt*2048u + kca);
                if (PASSES == 3) ldsm4(al4[mt], st + AL_OFF + aro + mt*2048u + kca);
            }
            #pragma unroll
            for (int nq = 0; nq < 4; nq++) {
                ldsm4(bh[nq],  st + BH_OFF + bro + nq*2048u + kcb);
                ldsm4(bl4[nq], st + BL_OFF + bro + nq*2048u + kcb);
            }
            // pass-major: 16 independent accs between reuses
            #pragma unroll
            for (int mt = 0; mt < 2; mt++)
                #pragma unroll
                for (int nt = 0; nt < 8; nt++) {
                    const int nq = nt >> 1, s2 = (nt & 1) * 2;
                    mma16816(acc[mt][nt], ah[mt], bh[nq][s2], bh[nq][s2+1]);
                }
            #pragma unroll
            for (int mt = 0; mt < 2; mt++)
                #pragma unroll
                for (int nt = 0; nt < 8; nt++) {
                    const int nq = nt >> 1, s2 = (nt & 1) * 2;
                    mma16816(acc[mt][nt], ah[mt], bl4[nq][s2], bl4[nq][s2+1]);
                }
            if (PASSES == 3) {
                #pragma unroll
                for (int mt = 0; mt < 2; mt++)
                    #pragma unroll
                    for (int nt = 0; nt < 8; nt++) {
                        const int nq = nt >> 1, s2 = (nt & 1) * 2;
                        mma16816(acc[mt][nt], al4[mt], bh[nq][s2], bh[nq][s2+1]);
                    }
            }
        }
        slot = (slot + 1 == 3) ? 0 : slot + 1;
    }

    // ---- epilogue ----
    const int grbase = bm*128 + wm*32;
    const int gcbase = bn*128 + wn*64;
    #pragma unroll
    for (int mt = 0; mt < 2; mt++) {
        const int r0 = grbase + mt*16 + (lane >> 2);
        #pragma unroll
        for (int nt = 0; nt < 8; nt++) {
            const int gc = gcbase + nt*8 + (lane & 3)*2;
            float2 v0 = make_float2(acc[mt][nt][0], acc[mt][nt][1]);
            float2 v1 = make_float2(acc[mt][nt][2], acc[mt][nt][3]);
            if (EPI >= 1) {
                float2 bb = *(const float2*)(bias + gc);
                v0.x += bb.x; v0.y += bb.y; v1.x += bb.x; v1.y += bb.y;
            }
            if (EPI == 1) {
                const int third = gc >> 10, lc = gc & 1023;
                __half* oh = outh + (size_t)third * ((size_t)M_ * C_);
                if (third == 0) {   // q: fold softmax scale + log2e; hi only (q_lo unused)
                    v0.x *= QSCALE; v0.y *= QSCALE; v1.x *= QSCALE; v1.y *= QSCALE;
                    *(uint32_t*)(oh + (size_t)r0 * 1024 + lc)     = pack_h2(v0.x, v0.y);
                    *(uint32_t*)(oh + (size_t)(r0+8) * 1024 + lc) = pack_h2(v1.x, v1.y);
                } else {            // k, v: hi + lo (attention keeps them split-exact)
                    __half* ol = outl + (size_t)third * ((size_t)M_ * C_);
                    uint32_t h0, l0;
                    split2(v0.x, v0.y, h0, l0);
                    *(uint32_t*)(oh + (size_t)r0 * 1024 + lc) = h0;
                    *(uint32_t*)(ol + (size_t)r0 * 1024 + lc) = l0;
                    split2(v1.x, v1.y, h0, l0);
                    *(uint32_t*)(oh + (size_t)(r0+8) * 1024 + lc) = h0;
                    *(uint32_t*)(ol + (size_t)(r0+8) * 1024 + lc) = l0;
                }
            } else if (EPI == 2) {
                v0.x = gelu_exact(v0.x); v0.y = gelu_exact(v0.y);
                v1.x = gelu_exact(v1.x); v1.y = gelu_exact(v1.y);
                *(uint32_t*)(outh + (size_t)r0 * N + gc)     = pack_h2(v0.x, v0.y);
                *(uint32_t*)(outh + (size_t)(r0+8) * N + gc) = pack_h2(v1.x, v1.y);
            } else if (EPI == 3) {
                float2 ra2 = *(const float2*)(resid + (size_t)r0 * N + gc);
                float2 rb2 = *(const float2*)(resid + (size_t)(r0+8) * N + gc);
                v0.x += ra2.x; v0.y += ra2.y; v1.x += rb2.x; v1.y += rb2.y;
                *(float2*)(outf + (size_t)r0 * N + gc) = v0;
                *(float2*)(outf + (size_t)(r0+8) * N + gc) = v1;
            } else {
                *(float2*)(outf + (size_t)r0 * N + gc) = v0;
                *(float2*)(outf + (size_t)(r0+8) * N + gc) = v1;
            }
        }
    }
}

#define GEMM_SMEM2 (3*49152)
#define GEMM_SMEM3 (3*65536)

// ================= flash attention (2-pass QK and PV, 3-stage cp.async) =================
// Q tile 128 (hi only), KV tile 64, DH=64.
// smem: Qh@0 (16KB), then 3 stages of 32KB: Kh@0 Kl@8K Vh@16K Vl@24K.
// Softmax in base-2 (q pre-scaled upstream).
// Passes: S = qh·kh + qh·kl ; O += ph·vh + ph·vl.
#define ASTG 32768
#define AQSZ 16384
#define ATT_SMEM (AQSZ + 3*ASTG)

__global__ void __launch_bounds__(256, 1) attn_h(
    const __half* __restrict__ qkvh, const __half* __restrict__ qkvl,
    __half* __restrict__ yh)
{
    extern __shared__ char sm[];
    const uint32_t sb = smem_u32(sm);
    const int t = threadIdx.x, w = t >> 5, lane = t & 31;
    const int bhx = blockIdx.y, b = bhx >> 4, h = bhx & 15;
    const int q0 = blockIdx.x * 128;
    const size_t MC = (size_t)M_ * C_;
    const int NT = T_ / 64;   // 32 tiles

    const __half* qgh = qkvh + (size_t)(b*T_ + q0) * C_ + h*64;
    const __half* kgh = qkvh + MC   + (size_t)(b*T_) * C_ + h*64;
    const __half* kgl = qkvl + MC   + (size_t)(b*T_) * C_ + h*64;
    const __half* vgh = qkvh + 2*MC + (size_t)(b*T_) * C_ + h*64;
    const __half* vgl = qkvl + 2*MC + (size_t)(b*T_) * C_ + h*64;

    // Q loads (hi only)
    {
        const int qr = t >> 1, qc = t & 1;
        #pragma unroll
        for (int i = 0; i < 4; i++) {
            const int c16 = qc*4 + i;
            const uint32_t d = (uint32_t)(qr*128 + ((c16 ^ (qr & 7)) << 4));
            CP_ASYNC16(sb + d, qgh + (size_t)qr * C_ + c16*8);
        }
    }
    CP_COMMIT;

    // KV stage loader
    const int kr = t >> 2, kc2 = (t & 3) * 2;
    auto load_kv = [&](int kt, int slot) {
        const uint32_t s0 = sb + AQSZ + (uint32_t)slot * ASTG;
        const size_t rowoff = (size_t)(kt*64 + kr) * C_;
        #pragma unroll
        for (int i = 0; i < 2; i++) {
            const int c16 = kc2 + i;
            const uint32_t d = (uint32_t)(kr*128 + ((c16 ^ (kr & 7)) << 4));
            CP_ASYNC16(s0 + d,          kgh + rowoff + c16*8);
            CP_ASYNC16(s0 + 8192u + d,  kgl + rowoff + c16*8);
            CP_ASYNC16(s0 + 16384u + d, vgh + rowoff + c16*8);
            CP_ASYNC16(s0 + 24576u + d, vgl + rowoff + c16*8);
        }
    };
    load_kv(0, 0); CP_COMMIT;
    load_kv(1, 1); CP_COMMIT;

    // ldmatrix lane geometry
    const int ra = lane & 15, ca = lane >> 4;
    const int rb = (lane & 7) + ((lane >> 4) << 3), cb = (lane >> 3) & 1;
    const int rv = (lane & 7) + (((lane >> 3) & 1) << 3), cv = lane >> 4;
    const int xr = lane & 7;

    CP_WAIT(2);           // Q (group 0) landed
    __syncthreads();
    uint32_t qh4[4][4];
    {
        const uint32_t qro = (uint32_t)((w*16 + ra) * 128);
        #pragma unroll
        for (int ks = 0; ks < 4; ks++) {
            const uint32_t off = qro + (uint32_t)(((ks*2 + ca) ^ xr) << 4);
            ldsm4(qh4[ks], sb + off);
        }
    }

    float o_[8][4];
    #pragma unroll
    for (int i = 0; i < 8; i++)
        #pragma unroll
        for (int j = 0; j < 4; j++) o_[i][j] = 0.f;
    float m_a = -1e30f, m_b = -1e30f, l_a = 0.f, l_b = 0.f;

    int slot = 0;
    for (int kt = 0; kt < NT; kt++) {
        CP_WAIT(1);        // current stage landed; next may still be in flight
        __syncthreads();
        if (kt + 2 < NT) {
            int ns = slot + 2; if (ns >= 3) ns -= 3;
            load_kv(kt + 2, ns);
        }
        CP_COMMIT;
        const uint32_t st = sb + AQSZ + (uint32_t)slot * ASTG;

        // ---- S = qh·(kh + kl) (2-pass) ----
        float sc[8][4];
        #pragma unroll
        for (int i = 0; i < 8; i++)
            #pragma unroll
            for (int j = 0; j < 4; j++) sc[i][j] = 0.f;
        #pragma unroll
        for (int ks = 0; ks < 4; ks++) {
            uint32_t kh4[4][4], kl4[4][4];
            #pragma unroll
            for (int nq = 0; nq < 4; nq++) {
                const uint32_t off = (uint32_t)((nq*16 + rb) * 128)
                                   + (uint32_t)(((ks*2 + cb) ^ xr) << 4);
                ldsm4(kh4[nq], st + off);
                ldsm4(kl4[nq], st + 8192u + off);
            }
            #pragma unroll
            for (int nt = 0; nt < 8; nt++) {
                const int nq = nt >> 1, s2 = (nt & 1) * 2;
                mma16816(sc[nt], qh4[ks], kh4[nq][s2], kh4[nq][s2+1]);
            }
            #pragma unroll
            for (int nt = 0; nt < 8; nt++) {
                const int nq = nt >> 1, s2 = (nt & 1) * 2;
                mma16816(sc[nt], qh4[ks], kl4[nq][s2], kl4[nq][s2+1]);
            }
        }

        // ---- online softmax (base-2) ----
        float mxa = -1e30f, mxb = -1e30f;
        #pragma unroll
        for (int nt = 0; nt < 8; nt++) {
            mxa = fmaxf(mxa, fmaxf(sc[nt][0], sc[nt][1]));
            mxb = fmaxf(mxb, fmaxf(sc[nt][2], sc[nt][3]));
        }
        mxa = fmaxf(mxa, __shfl_xor_sync(0xffffffffu, mxa, 1));
        mxa = fmaxf(mxa, __shfl_xor_sync(0xffffffffu, mxa, 2));
        mxb = fmaxf(mxb, __shfl_xor_sync(0xffffffffu, mxb, 1));
        mxb = fmaxf(mxb, __shfl_xor_sync(0xffffffffu, mxb, 2));
        const float nma = fmaxf(m_a, mxa), nmb = fmaxf(m_b, mxb);
        const float cfa = fex2(m_a - nma), cfb = fex2(m_b - nmb);
        m_a = nma; m_b = nmb;
        float rsa = 0.f, rsb = 0.f;
        #pragma unroll
        for (int nt = 0; nt < 8; nt++) {
            sc[nt][0] = fex2(sc[nt][0] - m_a); rsa += sc[nt][0];
            sc[nt][1] = fex2(sc[nt][1] - m_a); rsa += sc[nt][1];
            sc[nt][2] = fex2(sc[nt][2] - m_b); rsb += sc[nt][2];
            sc[nt][3] = fex2(sc[nt][3] - m_b); rsb += sc[nt][3];
        }
        rsa += __shfl_xor_sync(0xffffffffu, rsa, 1);
        rsa += __shfl_xor_sync(0xffffffffu, rsa, 2);
        rsb += __shfl_xor_sync(0xffffffffu, rsb, 1);
        rsb += __shfl_xor_sync(0xffffffffu, rsb, 2);
        l_a = l_a * cfa + rsa;
        l_b = l_b * cfb + rsb;
        #pragma unroll
        for (int dt = 0; dt < 8; dt++) {
            o_[dt][0] *= cfa; o_[dt][1] *= cfa; o_[dt][2] *= cfb; o_[dt][3] *= cfb;
        }

        // ---- O += ph·(vh + vl) (2-pass) ----
        #pragma unroll
        for (int ks = 0; ks < 4; ks++) {
            uint32_t ph[4];
            ph[0] = pack_h2(sc[2*ks][0],   sc[2*ks][1]);
            ph[1] = pack_h2(sc[2*ks][2],   sc[2*ks][3]);
            ph[2] = pack_h2(sc[2*ks+1][0], sc[2*ks+1][1]);
            ph[3] = pack_h2(sc[2*ks+1][2], sc[2*ks+1][3]);
            uint32_t vh4[4][4], vl4[4][4];
            #pragma unroll
            for (int nq = 0; nq < 4; nq++) {
                const uint32_t off = (uint32_t)((ks*16 + rv) * 128)
                                   + (uint32_t)(((nq*2 + cv) ^ xr) << 4);
                ldsm4t(vh4[nq], st + 16384u + off);
                ldsm4t(vl4[nq], st + 24576u + off);
            }
            #pragma unroll
            for (int dt = 0; dt < 8; dt++) {
                const int nq = dt >> 1, s2 = (dt & 1) * 2;
                mma16816(o_[dt], ph, vh4[nq][s2], vh4[nq][s2+1]);
            }
            #pragma unroll
            for (int dt = 0; dt < 8; dt++) {
                const int nq = dt >> 1, s2 = (dt & 1) * 2;
                mma16816(o_[dt], ph, vl4[nq][s2], vl4[nq][s2+1]);
            }
        }
        slot = (slot + 1 == 3) ? 0 : slot + 1;
    }

    // ---- write y (fp16 hi only; Wo GEMM is 2-pass) ----
    const float ia = 1.f / l_a, ib = 1.f / l_b;
    const int r0 = q0 + w*16 + (lane >> 2);
    __half* ybh = yh + (size_t)(b*T_ + r0) * C_ + h*64;
    #pragma unroll
    for (int dt = 0; dt < 8; dt++) {
        const int gc = dt*8 + (lane & 3)*2;
        *(uint32_t*)(ybh + gc)                 = pack_h2(o_[dt][0]*ia, o_[dt][1]*ia);
        *(uint32_t*)(ybh + (size_t)8*C_ + gc)  = pack_h2(o_[dt][2]*ib, o_[dt][3]*ib);
    }
}

// ================= orchestration =================
extern "C" void kernel_launch(void* const* d_in, const int* in_sizes, int n_in,
                              void* d_out, int out_size)
{
    const float* seq  = (const float*)d_in[0];
    const float* pos  = (const float*)d_in[1];
    const float* Wq   = (const float*)d_in[2];
    const float* bq   = (const float*)d_in[3];
    const float* Wk   = (const float*)d_in[4];
    const float* bk   = (const float*)d_in[5];
    const float* Wv   = (const float*)d_in[6];
    const float* bv   = (const float*)d_in[7];
    const float* Wo   = (const float*)d_in[8];
    const float* bo   = (const float*)d_in[9];
    const float* ln1w = (const float*)d_in[10];
    const float* ln1b = (const float*)d_in[11];
    const float* ln2w = (const float*)d_in[12];
    const float* ln2b = (const float*)d_in[13];
    const float* W1   = (const float*)d_in[14];
    const float* b1   = (const float*)d_in[15];
    const float* W2   = (const float*)d_in[16];
    const float* b2   = (const float*)d_in[17];
    const float* lnfw = (const float*)d_in[18];
    const float* lnfb = (const float*)d_in[19];
    const float* Wh   = (const float*)d_in[20];
    float* out = (float*)d_out;

    float *px, *pbqkv;
    __half *phh, *phl, *pqkvh, *pqkvl, *pyh, *puh, *pwh, *pwl;
    cudaGetSymbolAddress((void**)&px, g_x);
    cudaGetSymbolAddress((void**)&phh, g_hh);
    cudaGetSymbolAddress((void**)&phl, g_hl);
    cudaGetSymbolAddress((void**)&pqkvh, g_qkvh);
    cudaGetSymbolAddress((void**)&pqkvl, g_qkvl);
    cudaGetSymbolAddress((void**)&pyh, g_yh);
    cudaGetSymbolAddress((void**)&puh, g_uh);
    cudaGetSymbolAddress((void**)&pwh, g_wh);
    cudaGetSymbolAddress((void**)&pwl, g_wl);
    cudaGetSymbolAddress((void**)&pbqkv, g_bqkv);

    cudaFuncSetAttribute(attn_h, cudaFuncAttributeMaxDynamicSharedMemorySize, ATT_SMEM);
    cudaFuncSetAttribute((gemm_h<1,2>), cudaFuncAttributeMaxDynamicSharedMemorySize, GEMM_SMEM2);
    cudaFuncSetAttribute((gemm_h<2,2>), cudaFuncAttributeMaxDynamicSharedMemorySize, GEMM_SMEM2);
    cudaFuncSetAttribute((gemm_h<3,2>), cudaFuncAttributeMaxDynamicSharedMemorySize, GEMM_SMEM2);
    cudaFuncSetAttribute((gemm_h<0,3>), cudaFuncAttributeMaxDynamicSharedMemorySize, GEMM_SMEM3);

    // ---- weight conversion: ONE launch ----
    conv_all<<<(int)(WTOT / 2048), 256>>>(Wq, Wk, Wv, Wo, W1, W2, Wh, pwh, pwl);
    packqkvb<<<L_*3*C_/256, 256>>>(bq, bk, bv, pbqkv);
    addpos_kernel<<<M_ * C_ / 4 / 256, 256>>>(seq, pos, px);

    dim3 gQKV(3*C_ / 128, M_ / 128);   // (24, 64)
    dim3 gC(C_ / 128, M_ / 128);       // (8, 64)
    dim3 gF(FF_ / 128, M_ / 128);      // (32, 64)
    dim3 gA(T_ / 128, B_ * H_);        // (16, 64)

    for (int l = 0; l < L_; l++) {
        const size_t wl = (size_t)l * WPL_;
        ln_split<<<M_, 256>>>(px, ln1w + l*C_, ln1b + l*C_, phh, nullptr);
        gemm_h<1,2><<<gQKV, 256, GEMM_SMEM2>>>(phh, nullptr, pwh + wl, pwl + wl,
            pbqkv + l*3*C_, nullptr, nullptr, pqkvh, pqkvl, 3*C_, C_);
        attn_h<<<gA, 256, ATT_SMEM>>>(pqkvh, pqkvl, pyh);
        gemm_h<3,2><<<gC, 256, GEMM_SMEM2>>>(pyh, nullptr, pwh + wl + WOFF_WO, pwl + wl + WOFF_WO,
            bo + l*C_, px, px, nullptr, nullptr, C_, C_);
        ln_split<<<M_, 256>>>(px, ln2w + l*C_, ln2b + l*C_, phh, nullptr);
        gemm_h<2,2><<<gF, 256, GEMM_SMEM2>>>(phh, nullptr, pwh + wl + WOFF_W1, pwl + wl + WOFF_W1,
            b1 + l*FF_, nullptr, nullptr, puh, nullptr, FF_, C_);
        gemm_h<3,2><<<gC, 256, GEMM_SMEM2>>>(puh, nullptr, pwh + wl + WOFF_W2, pwl + wl + WOFF_W2,
            b2 + l*C_, px, px, nullptr, nullptr, C_, FF_);
    }

    // final LN needs lo for the 3-pass head GEMM
    ln_split<<<M_, 256>>>(px, lnfw, lnfb, phh, phl);
    gemm_h<0,3><<<gC, 256, GEMM_SMEM3>>>(phh, phl, pwh + WHEAD_OFF, pwl + WHEAD_OFF,
        nullptr, nullptr, out, nullptr, nullptr, OUT_, C_);
}

// round 9
// speedup vs baseline: 4.1325x; 1.1077x over previous
#include <cuda_runtime.h>
#include <cuda_fp16.h>
#include <math.h>
#include <stdint.h>

#define L_ 8
#define H_ 16
#define T_ 2048
#define C_ 1024
#define OUT_ 1024
#define B_ 4
#define DH_ 64
#define FF_ 4096
#define M_ (B_*T_)   // 8192 rows

#define CC_ (C_*C_)                   // 1048576
#define WPL_ (12*CC_)                 // weights per layer (halves)
#define WOFF_WO  (3*CC_)
#define WOFF_W1  (4*CC_)
#define WOFF_W2  (8*CC_)
#define WHEAD_OFF ((size_t)L_*WPL_)   // 100663296
#define WTOT (WHEAD_OFF + CC_)        // 101711872

// q pre-scale: 0.125 (1/sqrt(DH)) * log2(e) -> softmax in base-2 domain
#define QSCALE 0.1803368801111204f

// ---------------- scratch (static device globals) ----------------
__device__ float g_x[M_*C_];
__device__ __align__(16) __half g_hh[M_*C_],  g_hl[M_*C_];
__device__ __align__(16) __half g_qkvh[3*M_*C_], g_qkvl[3*M_*C_];
__device__ __align__(16) __half g_yh[M_*C_];
__device__ __align__(16) __half g_uh[(size_t)M_*FF_];
__device__ __align__(16) __half g_wh[WTOT],   g_wl[WTOT];
__device__ float g_bqkv[L_*3*C_];

// ================= helpers =================
__device__ __forceinline__ uint32_t smem_u32(const void* p) {
    uint32_t a;
    asm("{ .reg .u64 t; cvta.to.shared.u64 t, %1; cvt.u32.u64 %0, t; }" : "=r"(a) : "l"(p));
    return a;
}
__device__ __forceinline__ void mma16816(float* c, const uint32_t* a, uint32_t b0, uint32_t b1) {
    asm volatile(
        "mma.sync.aligned.m16n8k16.row.col.f32.f16.f16.f32 "
        "{%0,%1,%2,%3}, {%4,%5,%6,%7}, {%8,%9}, {%0,%1,%2,%3};"
        : "+f"(c[0]), "+f"(c[1]), "+f"(c[2]), "+f"(c[3])
        : "r"(a[0]), "r"(a[1]), "r"(a[2]), "r"(a[3]), "r"(b0), "r"(b1));
}
__device__ __forceinline__ void ldsm4(uint32_t* r, uint32_t addr) {
    asm volatile("ldmatrix.sync.aligned.m8n8.x4.shared.b16 {%0,%1,%2,%3}, [%4];"
                 : "=r"(r[0]), "=r"(r[1]), "=r"(r[2]), "=r"(r[3]) : "r"(addr));
}
__device__ __forceinline__ void ldsm4t(uint32_t* r, uint32_t addr) {
    asm volatile("ldmatrix.sync.aligned.m8n8.x4.trans.shared.b16 {%0,%1,%2,%3}, [%4];"
                 : "=r"(r[0]), "=r"(r[1]), "=r"(r[2]), "=r"(r[3]) : "r"(addr));
}
#define CP_ASYNC16(dst, src) \
    asm volatile("cp.async.cg.shared.global [%0], [%1], 16;" :: "r"(dst), "l"(src))
#define CP_COMMIT asm volatile("cp.async.commit_group;" ::: "memory")
#define CP_WAIT(n) asm volatile("cp.async.wait_group %0;" :: "n"(n) : "memory")

__device__ __forceinline__ float fex2(float x) {
    float y;
    asm("ex2.approx.f32 %0, %1;" : "=f"(y) : "f"(x));
    return y;
}
__device__ __forceinline__ void split2(float x, float y, uint32_t& h, uint32_t& l) {
    __half2 hh = __floats2half2_rn(x, y);
    float2 hf = __half22float2(hh);
    __half2 ll = __floats2half2_rn(x - hf.x, y - hf.y);
    h = *(uint32_t*)&hh;
    l = *(uint32_t*)&ll;
}
__device__ __forceinline__ uint32_t pack_h2(float x, float y) {
    __half2 hh = __floats2half2_rn(x, y);
    return *(uint32_t*)&hh;
}
__device__ __forceinline__ float gelu_exact(float v) {
    return 0.5f * v * (1.0f + erff(v * 0.70710678118654752f));
}

// ================= fused weight conversion (single launch) =================
__global__ void __launch_bounds__(256) conv_all(
    const float* __restrict__ Wq, const float* __restrict__ Wk,
    const float* __restrict__ Wv, const float* __restrict__ Wo,
    const float* __restrict__ W1, const float* __restrict__ W2,
    const float* __restrict__ Whd,
    __half* __restrict__ dh, __half* __restrict__ dl)
{
    const size_t i = ((size_t)blockIdx.x * 256 + threadIdx.x) * 8;
    const float* src;
    if (i >= WHEAD_OFF) {
        src = Whd + (i - WHEAD_OFF);
    } else {
        const int l = (int)(i / WPL_);
        const size_t r = i % WPL_;
        if      (r <   (size_t)CC_)   src = Wq + (size_t)l*CC_   + r;
        else if (r < 2*(size_t)CC_)   src = Wk + (size_t)l*CC_   + (r -   CC_);
        else if (r < 3*(size_t)CC_)   src = Wv + (size_t)l*CC_   + (r - 2*CC_);
        else if (r < 4*(size_t)CC_)   src = Wo + (size_t)l*CC_   + (r - 3*CC_);
        else if (r < 8*(size_t)CC_)   src = W1 + (size_t)l*4*CC_ + (r - 4*CC_);
        else                          src = W2 + (size_t)l*4*CC_ + (r - 8*CC_);
    }
    float4 a = *(const float4*)(src), b = *(const float4*)(src + 4);
    uint32_t h[4], l4[4];
    split2(a.x, a.y, h[0], l4[0]); split2(a.z, a.w, h[1], l4[1]);
    split2(b.x, b.y, h[2], l4[2]); split2(b.z, b.w, h[3], l4[3]);
    *(uint4*)(dh + i) = make_uint4(h[0], h[1], h[2], h[3]);
    *(uint4*)(dl + i) = make_uint4(l4[0], l4[1], l4[2], l4[3]);
}
__global__ void __launch_bounds__(256) packqkvb(
    const float* __restrict__ bq, const float* __restrict__ bk,
    const float* __restrict__ bv, float* __restrict__ dst)
{
    int idx = blockIdx.x * 256 + threadIdx.x;      // L_*3072
    int l = idx / 3072, c = idx % 3072;
    float v = (c < 1024) ? bq[l*1024 + c] : (c < 2048) ? bk[l*1024 + c - 1024]
                                                        : bv[l*1024 + c - 2048];
    dst[idx] = v;
}

// ================= x = seq + pos =================
__global__ void __launch_bounds__(256) addpos_kernel(
    const float* __restrict__ seq, const float* __restrict__ pos, float* __restrict__ x)
{
    int i = blockIdx.x * 256 + threadIdx.x;
    float4 s = ((const float4*)seq)[i];
    float4 p = ((const float4*)pos)[i & (T_*C_/4 - 1)];
    s.x += p.x; s.y += p.y; s.z += p.z; s.w += p.w;
    ((float4*)x)[i] = s;
}

// ================= LayerNorm -> fp16 hi (+ optional lo) =================
__global__ void __launch_bounds__(256) ln_split(
    const float* __restrict__ x, const float* __restrict__ w,
    const float* __restrict__ b, __half* __restrict__ outh, __half* __restrict__ outl)
{
    const int row = blockIdx.x;
    const int t = threadIdx.x;
    const float4 v = *(const float4*)(x + (size_t)row * C_ + t * 4);
    float s  = v.x + v.y + v.z + v.w;
    float sq = v.x*v.x + v.y*v.y + v.z*v.z + v.w*v.w;
    #pragma unroll
    for (int off = 16; off; off >>= 1) {
        s  += __shfl_xor_sync(0xffffffffu, s,  off);
        sq += __shfl_xor_sync(0xffffffffu, sq, off);
    }
    __shared__ float rs_[8], rq_[8];
    if ((t & 31) == 0) { rs_[t >> 5] = s; rq_[t >> 5] = sq; }
    __syncthreads();
    s = 0.f; sq = 0.f;
    #pragma unroll
    for (int i = 0; i < 8; i++) { s += rs_[i]; sq += rq_[i]; }
    const float mu   = s * (1.0f / 1024.0f);
    const float var  = sq * (1.0f / 1024.0f) - mu * mu;
    const float rstd = rsqrtf(var + 1e-5f);
    const float4 wv = *(const float4*)(w + t * 4);
    const float4 bv = *(const float4*)(b + t * 4);
    float ox = (v.x - mu) * rstd * wv.x + bv.x;
    float oy = (v.y - mu) * rstd * wv.y + bv.y;
    float oz = (v.z - mu) * rstd * wv.z + bv.z;
    float ow = (v.w - mu) * rstd * wv.w + bv.w;
    uint32_t h0, l0, h1, l1;
    split2(ox, oy, h0, l0);
    split2(oz, ow, h1, l1);
    *(uint2*)(outh + (size_t)row * C_ + t * 4) = make_uint2(h0, h1);
    if (outl) *(uint2*)(outl + (size_t)row * C_ + t * 4) = make_uint2(l0, l1);
}

// ================= 2-pass GEMM, 256x128 block, 64x64 warp tile =================
// D[M,N] = A[M,K] @ W[N,K]^T ; passes Ah·Bh + Ah·Bl. 3-stage cp.async.
// Stage 64KB: Ah[256x64]@0 (32K), Bh[128x64]@32K, Bl@48K.
// EPI: 1 = +bias -> qkv out (q: scaled hi; k/v: hi+lo), 2 = +bias+GELU -> hi out,
//      3 = +bias+residual -> fp32 out
#define GSTG2 65536u
#define GEMM_SMEM2 (3*65536)

template <int EPI>
__global__ void __launch_bounds__(256, 1) gemm_h2(
    const __half* __restrict__ Ah,
    const __half* __restrict__ Wh, const __half* __restrict__ Wl,
    const float* __restrict__ bias, const float* __restrict__ resid,
    float* __restrict__ outf, __half* __restrict__ outh, __half* __restrict__ outl,
    int N, int K)
{
    extern __shared__ char sm[];
    const uint32_t sb = smem_u32(sm);
    const int t = threadIdx.x, w = t >> 5, lane = t & 31;
    const int bm = blockIdx.y, bn = blockIdx.x;
    const int wm = w & 3, wn = w >> 2;          // warp tile: rows wm*64, cols wn*64

    // cp.async: thread -> row crow & crow+128 for A (4 chunks each), row crow for Bh/Bl (4 each)
    const int crow = t >> 1, chalf = t & 1;
    const __half* agh = Ah + (size_t)(bm*256 + crow) * K + chalf*32;
    const __half* bgh = Wh + (size_t)(bn*128 + crow) * K + chalf*32;
    const __half* bgl = Wl + (size_t)(bn*128 + crow) * K + chalf*32;
    uint32_t dsto[4];
    #pragma unroll
    for (int i = 0; i < 4; i++) {
        int c16 = chalf*4 + i;
        dsto[i] = (uint32_t)(crow*128 + ((c16 ^ (crow & 7)) << 4));
    }
    auto load_stage = [&](int c, int slot) {
        const uint32_t s0 = sb + (uint32_t)slot * GSTG2;
        const __half* a0 = agh + c*64;
        const __half* b0 = bgh + c*64;
        const __half* b1 = bgl + c*64;
        #pragma unroll
        for (int i = 0; i < 4; i++) CP_ASYNC16(s0 + dsto[i],           a0 + i*8);
        #pragma unroll
        for (int i = 0; i < 4; i++) CP_ASYNC16(s0 + 16384u + dsto[i],  a0 + (size_t)128*K + i*8);
        #pragma unroll
        for (int i = 0; i < 4; i++) CP_ASYNC16(s0 + 32768u + dsto[i],  b0 + i*8);
        #pragma unroll
        for (int i = 0; i < 4; i++) CP_ASYNC16(s0 + 49152u + dsto[i],  b1 + i*8);
    };

    // ldmatrix lane geometry
    const int ra = lane & 15, ca = lane >> 4;
    const int rb = (lane & 7) + ((lane >> 4) << 3), cb = (lane >> 3) & 1;
    const int xr = lane & 7;
    const uint32_t aro = (uint32_t)((wm*64 + ra) * 128);
    const uint32_t bro = (uint32_t)((wn*64 + rb) * 128);

    float acc[4][8][4];
    #pragma unroll
    for (int i = 0; i < 4; i++)
        #pragma unroll
        for (int j = 0; j < 8; j++)
            #pragma unroll
            for (int r = 0; r < 4; r++) acc[i][j][r] = 0.f;

    load_stage(0, 0); CP_COMMIT;
    load_stage(1, 1); CP_COMMIT;

    const int NC = K >> 6;
    int slot = 0;
    for (int c = 0; c < NC; c++) {
        CP_WAIT(1);
        __syncthreads();
        if (c + 2 < NC) {
            int ns = slot + 2; if (ns >= 3) ns -= 3;
            load_stage(c + 2, ns);
        }
        CP_COMMIT;
        const uint32_t st = sb + (uint32_t)slot * GSTG2;
        #pragma unroll
        for (int ks = 0; ks < 4; ks++) {
            const uint32_t kca = (uint32_t)(((ks*2 + ca) ^ xr) << 4);
            const uint32_t kcb = (uint32_t)(((ks*2 + cb) ^ xr) << 4);
            uint32_t ah[4][4], bh[4][4], bl4[4][4];
            #pragma unroll
            for (int mt = 0; mt < 4; mt++)
                ldsm4(ah[mt], st + aro + mt*2048u + kca);
            #pragma unroll
            for (int nq = 0; nq < 4; nq++) {
                ldsm4(bh[nq],  st + 32768u + bro + nq*2048u + kcb);
                ldsm4(bl4[nq], st + 49152u + bro + nq*2048u + kcb);
            }
            // pass-major: 32 independent accumulators between reuses
            #pragma unroll
            for (int mt = 0; mt < 4; mt++)
                #pragma unroll
                for (int nt = 0; nt < 8; nt++) {
                    const int nq = nt >> 1, s2 = (nt & 1) * 2;
                    mma16816(acc[mt][nt], ah[mt], bh[nq][s2], bh[nq][s2+1]);
                }
            #pragma unroll
            for (int mt = 0; mt < 4; mt++)
                #pragma unroll
                for (int nt = 0; nt < 8; nt++) {
                    const int nq = nt >> 1, s2 = (nt & 1) * 2;
                    mma16816(acc[mt][nt], ah[mt], bl4[nq][s2], bl4[nq][s2+1]);
                }
        }
        slot = (slot + 1 == 3) ? 0 : slot + 1;
    }

    // ---- epilogue ----
    const int grbase = bm*256 + wm*64;
    const int gcbase = bn*128 + wn*64;
    #pragma unroll
    for (int mt = 0; mt < 4; mt++) {
        const int r0 = grbase + mt*16 + (lane >> 2);
        #pragma unroll
        for (int nt = 0; nt < 8; nt++) {
            const int gc = gcbase + nt*8 + (lane & 3)*2;
            float2 v0 = make_float2(acc[mt][nt][0], acc[mt][nt][1]);
            float2 v1 = make_float2(acc[mt][nt][2], acc[mt][nt][3]);
            {
                float2 bb = *(const float2*)(bias + gc);
                v0.x += bb.x; v0.y += bb.y; v1.x += bb.x; v1.y += bb.y;
            }
            if (EPI == 1) {
                const int third = gc >> 10, lc = gc & 1023;
                __half* oh = outh + (size_t)third * ((size_t)M_ * C_);
                if (third == 0) {   // q: fold softmax scale + log2e; hi only
                    v0.x *= QSCALE; v0.y *= QSCALE; v1.x *= QSCALE; v1.y *= QSCALE;
                    *(uint32_t*)(oh + (size_t)r0 * 1024 + lc)     = pack_h2(v0.x, v0.y);
                    *(uint32_t*)(oh + (size_t)(r0+8) * 1024 + lc) = pack_h2(v1.x, v1.y);
                } else {            // k, v: hi + lo
                    __half* ol = outl + (size_t)third * ((size_t)M_ * C_);
                    uint32_t h0, l0;
                    split2(v0.x, v0.y, h0, l0);
                    *(uint32_t*)(oh + (size_t)r0 * 1024 + lc) = h0;
                    *(uint32_t*)(ol + (size_t)r0 * 1024 + lc) = l0;
                    split2(v1.x, v1.y, h0, l0);
                    *(uint32_t*)(oh + (size_t)(r0+8) * 1024 + lc) = h0;
                    *(uint32_t*)(ol + (size_t)(r0+8) * 1024 + lc) = l0;
                }
            } else if (EPI == 2) {
                v0.x = gelu_exact(v0.x); v0.y = gelu_exact(v0.y);
                v1.x = gelu_exact(v1.x); v1.y = gelu_exact(v1.y);
                *(uint32_t*)(outh + (size_t)r0 * N + gc)     = pack_h2(v0.x, v0.y);
                *(uint32_t*)(outh + (size_t)(r0+8) * N + gc) = pack_h2(v1.x, v1.y);
            } else {  // EPI == 3
                float2 ra2 = *(const float2*)(resid + (size_t)r0 * N + gc);
                float2 rb2 = *(const float2*)(resid + (size_t)(r0+8) * N + gc);
                v0.x += ra2.x; v0.y += ra2.y; v1.x += rb2.x; v1.y += rb2.y;
                *(float2*)(outf + (size_t)r0 * N + gc) = v0;
                *(float2*)(outf + (size_t)(r0+8) * N + gc) = v1;
            }
        }
    }
}

// ================= head GEMM: 3-pass, 128x128 block (round-8 geometry) =================
#define GSTG3 65536u
#define GEMM_SMEM3 (3*65536)

__global__ void __launch_bounds__(256, 1) gemm_head(
    const __half* __restrict__ Ah, const __half* __restrict__ Al,
    const __half* __restrict__ Wh, const __half* __restrict__ Wl,
    float* __restrict__ outf, int N, int K)
{
    extern __shared__ char sm[];
    const uint32_t sb = smem_u32(sm);
    const int t = threadIdx.x, w = t >> 5, lane = t & 31;
    const int bm = blockIdx.y, bn = blockIdx.x;
    const int wm = w & 3, wn = w >> 2;

    const int crow = t >> 1, chalf = t & 1;
    const __half* agh = Ah + (size_t)(bm*128 + crow) * K + chalf*32;
    const __half* agl = Al + (size_t)(bm*128 + crow) * K + chalf*32;
    const __half* bgh = Wh + (size_t)(bn*128 + crow) * K + chalf*32;
    const __half* bgl = Wl + (size_t)(bn*128 + crow) * K + chalf*32;
    uint32_t dsto[4];
    #pragma unroll
    for (int i = 0; i < 4; i++) {
        int c16 = chalf*4 + i;
        dsto[i] = (uint32_t)(crow*128 + ((c16 ^ (crow & 7)) << 4));
    }
    auto load_stage = [&](int c, int slot) {
        const uint32_t s0 = sb + (uint32_t)slot * GSTG3;
        #pragma unroll
        for (int i = 0; i < 4; i++) CP_ASYNC16(s0 + dsto[i],          agh + c*64 + i*8);
        #pragma unroll
        for (int i = 0; i < 4; i++) CP_ASYNC16(s0 + 16384u + dsto[i], agl + c*64 + i*8);
        #pragma unroll
        for (int i = 0; i < 4; i++) CP_ASYNC16(s0 + 32768u + dsto[i], bgh + c*64 + i*8);
        #pragma unroll
        for (int i = 0; i < 4; i++) CP_ASYNC16(s0 + 49152u + dsto[i], bgl + c*64 + i*8);
    };

    const int ra = lane & 15, ca = lane >> 4;
    const int rb = (lane & 7) + ((lane >> 4) << 3), cb = (lane >> 3) & 1;
    const int xr = lane & 7;
    const uint32_t aro = (uint32_t)((wm*32 + ra) * 128);
    const uint32_t bro = (uint32_t)((wn*64 + rb) * 128);

    float acc[2][8][4];
    #pragma unroll
    for (int i = 0; i < 2; i++)
        #pragma unroll
        for (int j = 0; j < 8; j++)
            #pragma unroll
            for (int r = 0; r < 4; r++) acc[i][j][r] = 0.f;

    load_stage(0, 0); CP_COMMIT;
    load_stage(1, 1); CP_COMMIT;

    const int NC = K >> 6;
    int slot = 0;
    for (int c = 0; c < NC; c++) {
        CP_WAIT(1);
        __syncthreads();
        if (c + 2 < NC) {
            int ns = slot + 2; if (ns >= 3) ns -= 3;
            load_stage(c + 2, ns);
        }
        CP_COMMIT;
        const uint32_t st = sb + (uint32_t)slot * GSTG3;
        #pragma unroll
        for (int ks = 0; ks < 4; ks++) {
            const uint32_t kca = (uint32_t)(((ks*2 + ca) ^ xr) << 4);
            const uint32_t kcb = (uint32_t)(((ks*2 + cb) ^ xr) << 4);
            uint32_t ah[2][4], al4[2][4], bh[4][4], bl4[4][4];
            #pragma unroll
            for (int mt = 0; mt < 2; mt++) {
                ldsm4(ah[mt],  st + aro + mt*2048u + kca);
                ldsm4(al4[mt], st + 16384u + aro + mt*2048u + kca);
            }
            #pragma unroll
            for (int nq = 0; nq < 4; nq++) {
                ldsm4(bh[nq],  st + 32768u + bro + nq*2048u + kcb);
                ldsm4(bl4[nq], st + 49152u + bro + nq*2048u + kcb);
            }
            #pragma unroll
            for (int mt = 0; mt < 2; mt++)
                #pragma unroll
                for (int nt = 0; nt < 8; nt++) {
                    const int nq = nt >> 1, s2 = (nt & 1) * 2;
                    mma16816(acc[mt][nt], ah[mt], bh[nq][s2], bh[nq][s2+1]);
                }
            #pragma unroll
            for (int mt = 0; mt < 2; mt++)
                #pragma unroll
                for (int nt = 0; nt < 8; nt++) {
                    const int nq = nt >> 1, s2 = (nt & 1) * 2;
                    mma16816(acc[mt][nt], ah[mt], bl4[nq][s2], bl4[nq][s2+1]);
                }
            #pragma unroll
            for (int mt = 0; mt < 2; mt++)
                #pragma unroll
                for (int nt = 0; nt < 8; nt++) {
                    const int nq = nt >> 1, s2 = (nt & 1) * 2;
                    mma16816(acc[mt][nt], al4[mt], bh[nq][s2], bh[nq][s2+1]);
                }
        }
        slot = (slot + 1 == 3) ? 0 : slot + 1;
    }

    const int grbase = bm*128 + wm*32;
    const int gcbase = bn*128 + wn*64;
    #pragma unroll
    for (int mt = 0; mt < 2; mt++) {
        const int r0 = grbase + mt*16 + (lane >> 2);
        #pragma unroll
        for (int nt = 0; nt < 8; nt++) {
            const int gc = gcbase + nt*8 + (lane & 3)*2;
            *(float2*)(outf + (size_t)r0 * N + gc) =
                make_float2(acc[mt][nt][0], acc[mt][nt][1]);
            *(float2*)(outf + (size_t)(r0+8) * N + gc) =
                make_float2(acc[mt][nt][2], acc[mt][nt][3]);
        }
    }
}

// ================= flash attention (2-pass QK and PV, 3-stage cp.async) =================
#define ASTG 32768
#define AQSZ 16384
#define ATT_SMEM (AQSZ + 3*ASTG)

__global__ void __launch_bounds__(256, 1) attn_h(
    const __half* __restrict__ qkvh, const __half* __restrict__ qkvl,
    __half* __restrict__ yh)
{
    extern __shared__ char sm[];
    const uint32_t sb = smem_u32(sm);
    const int t = threadIdx.x, w = t >> 5, lane = t & 31;
    const int bhx = blockIdx.y, b = bhx >> 4, h = bhx & 15;
    const int q0 = blockIdx.x * 128;
    const size_t MC = (size_t)M_ * C_;
    const int NT = T_ / 64;   // 32 tiles

    const __half* qgh = qkvh + (size_t)(b*T_ + q0) * C_ + h*64;
    const __half* kgh = qkvh + MC   + (size_t)(b*T_) * C_ + h*64;
    const __half* kgl = qkvl + MC   + (size_t)(b*T_) * C_ + h*64;
    const __half* vgh = qkvh + 2*MC + (size_t)(b*T_) * C_ + h*64;
    const __half* vgl = qkvl + 2*MC + (size_t)(b*T_) * C_ + h*64;

    // Q loads (hi only)
    {
        const int qr = t >> 1, qc = t & 1;
        #pragma unroll
        for (int i = 0; i < 4; i++) {
            const int c16 = qc*4 + i;
            const uint32_t d = (uint32_t)(qr*128 + ((c16 ^ (qr & 7)) << 4));
            CP_ASYNC16(sb + d, qgh + (size_t)qr * C_ + c16*8);
        }
    }
    CP_COMMIT;

    // KV stage loader
    const int kr = t >> 2, kc2 = (t & 3) * 2;
    auto load_kv = [&](int kt, int slot) {
        const uint32_t s0 = sb + AQSZ + (uint32_t)slot * ASTG;
        const size_t rowoff = (size_t)(kt*64 + kr) * C_;
        #pragma unroll
        for (int i = 0; i < 2; i++) {
            const int c16 = kc2 + i;
            const uint32_t d = (uint32_t)(kr*128 + ((c16 ^ (kr & 7)) << 4));
            CP_ASYNC16(s0 + d,          kgh + rowoff + c16*8);
            CP_ASYNC16(s0 + 8192u + d,  kgl + rowoff + c16*8);
            CP_ASYNC16(s0 + 16384u + d, vgh + rowoff + c16*8);
            CP_ASYNC16(s0 + 24576u + d, vgl + rowoff + c16*8);
        }
    };
    load_kv(0, 0); CP_COMMIT;
    load_kv(1, 1); CP_COMMIT;

    // ldmatrix lane geometry
    const int ra = lane & 15, ca = lane >> 4;
    const int rb = (lane & 7) + ((lane >> 4) << 3), cb = (lane >> 3) & 1;
    const int rv = (lane & 7) + (((lane >> 3) & 1) << 3), cv = lane >> 4;
    const int xr = lane & 7;

    CP_WAIT(2);           // Q (group 0) landed
    __syncthreads();
    uint32_t qh4[4][4];
    {
        const uint32_t qro = (uint32_t)((w*16 + ra) * 128);
        #pragma unroll
        for (int ks = 0; ks < 4; ks++) {
            const uint32_t off = qro + (uint32_t)(((ks*2 + ca) ^ xr) << 4);
            ldsm4(qh4[ks], sb + off);
        }
    }

    float o_[8][4];
    #pragma unroll
    for (int i = 0; i < 8; i++)
        #pragma unroll
        for (int j = 0; j < 4; j++) o_[i][j] = 0.f;
    float m_a = -1e30f, m_b = -1e30f, l_a = 0.f, l_b = 0.f;

    int slot = 0;
    for (int kt = 0; kt < NT; kt++) {
        CP_WAIT(1);
        __syncthreads();
        if (kt + 2 < NT) {
            int ns = slot + 2; if (ns >= 3) ns -= 3;
            load_kv(kt + 2, ns);
        }
        CP_COMMIT;
        const uint32_t st = sb + AQSZ + (uint32_t)slot * ASTG;

        // ---- S = qh·(kh + kl) (2-pass) ----
        float sc[8][4];
        #pragma unroll
        for (int i = 0; i < 8; i++)
            #pragma unroll
            for (int j = 0; j < 4; j++) sc[i][j] = 0.f;
        #pragma unroll
        for (int ks = 0; ks < 4; ks++) {
            uint32_t kh4[4][4], kl4[4][4];
            #pragma unroll
            for (int nq = 0; nq < 4; nq++) {
                const uint32_t off = (uint32_t)((nq*16 + rb) * 128)
                                   + (uint32_t)(((ks*2 + cb) ^ xr) << 4);
                ldsm4(kh4[nq], st + off);
                ldsm4(kl4[nq], st + 8192u + off);
            }
            #pragma unroll
            for (int nt = 0; nt < 8; nt++) {
                const int nq = nt >> 1, s2 = (nt & 1) * 2;
                mma16816(sc[nt], qh4[ks], kh4[nq][s2], kh4[nq][s2+1]);
            }
            #pragma unroll
            for (int nt = 0; nt < 8; nt++) {
                const int nq = nt >> 1, s2 = (nt & 1) * 2;
                mma16816(sc[nt], qh4[ks], kl4[nq][s2], kl4[nq][s2+1]);
            }
        }

        // ---- online softmax (base-2) ----
        float mxa = -1e30f, mxb = -1e30f;
        #pragma unroll
        for (int nt = 0; nt < 8; nt++) {
            mxa = fmaxf(mxa, fmaxf(sc[nt][0], sc[nt][1]));
            mxb = fmaxf(mxb, fmaxf(sc[nt][2], sc[nt][3]));
        }
        mxa = fmaxf(mxa, __shfl_xor_sync(0xffffffffu, mxa, 1));
        mxa = fmaxf(mxa, __shfl_xor_sync(0xffffffffu, mxa, 2));
        mxb = fmaxf(mxb, __shfl_xor_sync(0xffffffffu, mxb, 1));
        mxb = fmaxf(mxb, __shfl_xor_sync(0xffffffffu, mxb, 2));
        const float nma = fmaxf(m_a, mxa), nmb = fmaxf(m_b, mxb);
        const float cfa = fex2(m_a - nma), cfb = fex2(m_b - nmb);
        m_a = nma; m_b = nmb;
        float rsa = 0.f, rsb = 0.f;
        #pragma unroll
        for (int nt = 0; nt < 8; nt++) {
            sc[nt][0] = fex2(sc[nt][0] - m_a); rsa += sc[nt][0];
            sc[nt][1] = fex2(sc[nt][1] - m_a); rsa += sc[nt][1];
            sc[nt][2] = fex2(sc[nt][2] - m_b); rsb += sc[nt][2];
            sc[nt][3] = fex2(sc[nt][3] - m_b); rsb += sc[nt][3];
        }
        rsa += __shfl_xor_sync(0xffffffffu, rsa, 1);
        rsa += __shfl_xor_sync(0xffffffffu, rsa, 2);
        rsb += __shfl_xor_sync(0xffffffffu, rsb, 1);
        rsb += __shfl_xor_sync(0xffffffffu, rsb, 2);
        l_a = l_a * cfa + rsa;
        l_b = l_b * cfb + rsb;
        #pragma unroll
        for (int dt = 0; dt < 8; dt++) {
            o_[dt][0] *= cfa; o_[dt][1] *= cfa; o_[dt][2] *= cfb; o_[dt][3] *= cfb;
        }

        // ---- O += ph·(vh + vl) (2-pass) ----
        #pragma unroll
        for (int ks = 0; ks < 4; ks++) {
            uint32_t ph[4];
            ph[0] = pack_h2(sc[2*ks][0],   sc[2*ks][1]);
            ph[1] = pack_h2(sc[2*ks][2],   sc[2*ks][3]);
            ph[2] = pack_h2(sc[2*ks+1][0], sc[2*ks+1][1]);
            ph[3] = pack_h2(sc[2*ks+1][2], sc[2*ks+1][3]);
            uint32_t vh4[4][4], vl4[4][4];
            #pragma unroll
            for (int nq = 0; nq < 4; nq++) {
                const uint32_t off = (uint32_t)((ks*16 + rv) * 128)
                                   + (uint32_t)(((nq*2 + cv) ^ xr) << 4);
                ldsm4t(vh4[nq], st + 16384u + off);
                ldsm4t(vl4[nq], st + 24576u + off);
            }
            #pragma unroll
            for (int dt = 0; dt < 8; dt++) {
                const int nq = dt >> 1, s2 = (dt & 1) * 2;
                mma16816(o_[dt], ph, vh4[nq][s2], vh4[nq][s2+1]);
            }
            #pragma unroll
            for (int dt = 0; dt < 8; dt++) {
                const int nq = dt >> 1, s2 = (dt & 1) * 2;
                mma16816(o_[dt], ph, vl4[nq][s2], vl4[nq][s2+1]);
            }
        }
        slot = (slot + 1 == 3) ? 0 : slot + 1;
    }

    // ---- write y (fp16 hi only) ----
    const float ia = 1.f / l_a, ib = 1.f / l_b;
    const int r0 = q0 + w*16 + (lane >> 2);
    __half* ybh = yh + (size_t)(b*T_ + r0) * C_ + h*64;
    #pragma unroll
    for (int dt = 0; dt < 8; dt++) {
        const int gc = dt*8 + (lane & 3)*2;
        *(uint32_t*)(ybh + gc)                 = pack_h2(o_[dt][0]*ia, o_[dt][1]*ia);
        *(uint32_t*)(ybh + (size_t)8*C_ + gc)  = pack_h2(o_[dt][2]*ib, o_[dt][3]*ib);
    }
}

// ================= orchestration =================
extern "C" void kernel_launch(void* const* d_in, const int* in_sizes, int n_in,
                              void* d_out, int out_size)
{
    const float* seq  = (const float*)d_in[0];
    const float* pos  = (const float*)d_in[1];
    const float* Wq   = (const float*)d_in[2];
    const float* bq   = (const float*)d_in[3];
    const float* Wk   = (const float*)d_in[4];
    const float* bk   = (const float*)d_in[5];
    const float* Wv   = (const float*)d_in[6];
    const float* bv   = (const float*)d_in[7];
    const float* Wo   = (const float*)d_in[8];
    const float* bo   = (const float*)d_in[9];
    const float* ln1w = (const float*)d_in[10];
    const float* ln1b = (const float*)d_in[11];
    const float* ln2w = (const float*)d_in[12];
    const float* ln2b = (const float*)d_in[13];
    const float* W1   = (const float*)d_in[14];
    const float* b1   = (const float*)d_in[15];
    const float* W2   = (const float*)d_in[16];
    const float* b2   = (const float*)d_in[17];
    const float* lnfw = (const float*)d_in[18];
    const float* lnfb = (const float*)d_in[19];
    const float* Wh   = (const float*)d_in[20];
    float* out = (float*)d_out;

    float *px, *pbqkv;
    __half *phh, *phl, *pqkvh, *pqkvl, *pyh, *puh, *pwh, *pwl;
    cudaGetSymbolAddress((void**)&px, g_x);
    cudaGetSymbolAddress((void**)&phh, g_hh);
    cudaGetSymbolAddress((void**)&phl, g_hl);
    cudaGetSymbolAddress((void**)&pqkvh, g_qkvh);
    cudaGetSymbolAddress((void**)&pqkvl, g_qkvl);
    cudaGetSymbolAddress((void**)&pyh, g_yh);
    cudaGetSymbolAddress((void**)&puh, g_uh);
    cudaGetSymbolAddress((void**)&pwh, g_wh);
    cudaGetSymbolAddress((void**)&pwl, g_wl);
    cudaGetSymbolAddress((void**)&pbqkv, g_bqkv);

    cudaFuncSetAttribute(attn_h, cudaFuncAttributeMaxDynamicSharedMemorySize, ATT_SMEM);
    cudaFuncSetAttribute((gemm_h2<1>), cudaFuncAttributeMaxDynamicSharedMemorySize, GEMM_SMEM2);
    cudaFuncSetAttribute((gemm_h2<2>), cudaFuncAttributeMaxDynamicSharedMemorySize, GEMM_SMEM2);
    cudaFuncSetAttribute((gemm_h2<3>), cudaFuncAttributeMaxDynamicSharedMemorySize, GEMM_SMEM2);
    cudaFuncSetAttribute(gemm_head, cudaFuncAttributeMaxDynamicSharedMemorySize, GEMM_SMEM3);

    // ---- weight conversion: ONE launch ----
    conv_all<<<(int)(WTOT / 2048), 256>>>(Wq, Wk, Wv, Wo, W1, W2, Wh, pwh, pwl);
    packqkvb<<<L_*3*C_/256, 256>>>(bq, bk, bv, pbqkv);
    addpos_kernel<<<M_ * C_ / 4 / 256, 256>>>(seq, pos, px);

    dim3 gQKV(3*C_ / 128, M_ / 256);   // (24, 32)
    dim3 gC(C_ / 128, M_ / 256);       // (8, 32)
    dim3 gF(FF_ / 128, M_ / 256);      // (32, 32)
    dim3 gA(T_ / 128, B_ * H_);        // (16, 64)
    dim3 gHead(OUT_ / 128, M_ / 128);  // (8, 64)

    for (int l = 0; l < L_; l++) {
        const size_t wl = (size_t)l * WPL_;
        ln_split<<<M_, 256>>>(px, ln1w + l*C_, ln1b + l*C_, phh, nullptr);
        gemm_h2<1><<<gQKV, 256, GEMM_SMEM2>>>(phh, pwh + wl, pwl + wl,
            pbqkv + l*3*C_, nullptr, nullptr, pqkvh, pqkvl, 3*C_, C_);
        attn_h<<<gA, 256, ATT_SMEM>>>(pqkvh, pqkvl, pyh);
        gemm_h2<3><<<gC, 256, GEMM_SMEM2>>>(pyh, pwh + wl + WOFF_WO, pwl + wl + WOFF_WO,
            bo + l*C_, px, px, nullptr, nullptr, C_, C_);
        ln_split<<<M_, 256>>>(px, ln2w + l*C_, ln2b + l*C_, phh, nullptr);
        gemm_h2<2><<<gF, 256, GEMM_SMEM2>>>(phh, pwh + wl + WOFF_W1, pwl + wl + WOFF_W1,
            b1 + l*FF_, nullptr, nullptr, puh, nullptr, FF_, C_);
        gemm_h2<3><<<gC, 256, GEMM_SMEM2>>>(puh, pwh + wl + WOFF_W2, pwl + wl + WOFF_W2,
            b2 + l*C_, px, px, nullptr, nullptr, C_, FF_);
    }

    // final LN needs lo for the 3-pass head GEMM
    ln_split<<<M_, 256>>>(px, lnfw, lnfb, phh, phl);
    gemm_head<<<gHead, 256, GEMM_SMEM3>>>(phh, phl, pwh + WHEAD_OFF, pwl + WHEAD_OFF,
        out, OUT_, C_);
}

// round 10
// speedup vs baseline: 4.1528x; 1.0049x over previous
#include <cuda_runtime.h>
#include <cuda_fp16.h>
#include <math.h>
#include <stdint.h>

#define L_ 8
#define H_ 16
#define T_ 2048
#define C_ 1024
#define OUT_ 1024
#define B_ 4
#define DH_ 64
#define FF_ 4096
#define M_ (B_*T_)   // 8192 rows

#define CC_ (C_*C_)                   // 1048576
#define WPL_ (12*CC_)                 // weights per layer (halves)
#define WOFF_WO  (3*CC_)
#define WOFF_W1  (4*CC_)
#define WOFF_W2  (8*CC_)
#define WHEAD_OFF ((size_t)L_*WPL_)   // 100663296
#define WTOT (WHEAD_OFF + CC_)        // 101711872

// q pre-scale: 0.125 (1/sqrt(DH)) * log2(e) -> softmax in base-2 domain
#define QSCALE 0.1803368801111204f

// ---------------- scratch (static device globals) ----------------
__device__ float g_x[M_*C_];
__device__ __align__(16) __half g_hh[M_*C_],  g_hl[M_*C_];
__device__ __align__(16) __half g_qkvh[3*M_*C_], g_qkvl[3*M_*C_];
__device__ __align__(16) __half g_yh[M_*C_];
__device__ __align__(16) __half g_uh[(size_t)M_*FF_];
__device__ __align__(16) __half g_wh[WTOT],   g_wl[WTOT];
__device__ float g_bqkv[L_*3*C_];

// ================= helpers =================
__device__ __forceinline__ uint32_t smem_u32(const void* p) {
    uint32_t a;
    asm("{ .reg .u64 t; cvta.to.shared.u64 t, %1; cvt.u32.u64 %0, t; }" : "=r"(a) : "l"(p));
    return a;
}
__device__ __forceinline__ void mma16816(float* c, const uint32_t* a, uint32_t b0, uint32_t b1) {
    asm volatile(
        "mma.sync.aligned.m16n8k16.row.col.f32.f16.f16.f32 "
        "{%0,%1,%2,%3}, {%4,%5,%6,%7}, {%8,%9}, {%0,%1,%2,%3};"
        : "+f"(c[0]), "+f"(c[1]), "+f"(c[2]), "+f"(c[3])
        : "r"(a[0]), "r"(a[1]), "r"(a[2]), "r"(a[3]), "r"(b0), "r"(b1));
}
__device__ __forceinline__ void ldsm4(uint32_t* r, uint32_t addr) {
    asm volatile("ldmatrix.sync.aligned.m8n8.x4.shared.b16 {%0,%1,%2,%3}, [%4];"
                 : "=r"(r[0]), "=r"(r[1]), "=r"(r[2]), "=r"(r[3]) : "r"(addr));
}
__device__ __forceinline__ void ldsm4t(uint32_t* r, uint32_t addr) {
    asm volatile("ldmatrix.sync.aligned.m8n8.x4.trans.shared.b16 {%0,%1,%2,%3}, [%4];"
                 : "=r"(r[0]), "=r"(r[1]), "=r"(r[2]), "=r"(r[3]) : "r"(addr));
}
#define CP_ASYNC16(dst, src) \
    asm volatile("cp.async.cg.shared.global [%0], [%1], 16;" :: "r"(dst), "l"(src))
#define CP_COMMIT asm volatile("cp.async.commit_group;" ::: "memory")
#define CP_WAIT(n) asm volatile("cp.async.wait_group %0;" :: "n"(n) : "memory")

__device__ __forceinline__ float fex2(float x) {
    float y;
    asm("ex2.approx.f32 %0, %1;" : "=f"(y) : "f"(x));
    return y;
}
__device__ __forceinline__ void split2(float x, float y, uint32_t& h, uint32_t& l) {
    __half2 hh = __floats2half2_rn(x, y);
    float2 hf = __half22float2(hh);
    __half2 ll = __floats2half2_rn(x - hf.x, y - hf.y);
    h = *(uint32_t*)&hh;
    l = *(uint32_t*)&ll;
}
__device__ __forceinline__ uint32_t pack_h2(float x, float y) {
    __half2 hh = __floats2half2_rn(x, y);
    return *(uint32_t*)&hh;
}
__device__ __forceinline__ float gelu_exact(float v) {
    return 0.5f * v * (1.0f + erff(v * 0.70710678118654752f));
}

// ================= fused weight conversion (single launch) =================
__global__ void __launch_bounds__(256) conv_all(
    const float* __restrict__ Wq, const float* __restrict__ Wk,
    const float* __restrict__ Wv, const float* __restrict__ Wo,
    const float* __restrict__ W1, const float* __restrict__ W2,
    const float* __restrict__ Whd,
    __half* __restrict__ dh, __half* __restrict__ dl)
{
    const size_t i = ((size_t)blockIdx.x * 256 + threadIdx.x) * 8;
    const float* src;
    if (i >= WHEAD_OFF) {
        src = Whd + (i - WHEAD_OFF);
    } else {
        const int l = (int)(i / WPL_);
        const size_t r = i % WPL_;
        if      (r <   (size_t)CC_)   src = Wq + (size_t)l*CC_   + r;
        else if (r < 2*(size_t)CC_)   src = Wk + (size_t)l*CC_   + (r -   CC_);
        else if (r < 3*(size_t)CC_)   src = Wv + (size_t)l*CC_   + (r - 2*CC_);
        else if (r < 4*(size_t)CC_)   src = Wo + (size_t)l*CC_   + (r - 3*CC_);
        else if (r < 8*(size_t)CC_)   src = W1 + (size_t)l*4*CC_ + (r - 4*CC_);
        else                          src = W2 + (size_t)l*4*CC_ + (r - 8*CC_);
    }
    float4 a = *(const float4*)(src), b = *(const float4*)(src + 4);
    uint32_t h[4], l4[4];
    split2(a.x, a.y, h[0], l4[0]); split2(a.z, a.w, h[1], l4[1]);
    split2(b.x, b.y, h[2], l4[2]); split2(b.z, b.w, h[3], l4[3]);
    *(uint4*)(dh + i) = make_uint4(h[0], h[1], h[2], h[3]);
    *(uint4*)(dl + i) = make_uint4(l4[0], l4[1], l4[2], l4[3]);
}
__global__ void __launch_bounds__(256) packqkvb(
    const float* __restrict__ bq, const float* __restrict__ bk,
    const float* __restrict__ bv, float* __restrict__ dst)
{
    int idx = blockIdx.x * 256 + threadIdx.x;      // L_*3072
    int l = idx / 3072, c = idx % 3072;
    float v = (c < 1024) ? bq[l*1024 + c] : (c < 2048) ? bk[l*1024 + c - 1024]
                                                        : bv[l*1024 + c - 2048];
    dst[idx] = v;
}

// ================= x = seq + pos =================
__global__ void __launch_bounds__(256) addpos_kernel(
    const float* __restrict__ seq, const float* __restrict__ pos, float* __restrict__ x)
{
    int i = blockIdx.x * 256 + threadIdx.x;
    float4 s = ((const float4*)seq)[i];
    float4 p = ((const float4*)pos)[i & (T_*C_/4 - 1)];
    s.x += p.x; s.y += p.y; s.z += p.z; s.w += p.w;
    ((float4*)x)[i] = s;
}

// ================= LayerNorm -> fp16 hi (+ optional lo) =================
__global__ void __launch_bounds__(256) ln_split(
    const float* __restrict__ x, const float* __restrict__ w,
    const float* __restrict__ b, __half* __restrict__ outh, __half* __restrict__ outl)
{
    const int row = blockIdx.x;
    const int t = threadIdx.x;
    const float4 v = *(const float4*)(x + (size_t)row * C_ + t * 4);
    float s  = v.x + v.y + v.z + v.w;
    float sq = v.x*v.x + v.y*v.y + v.z*v.z + v.w*v.w;
    #pragma unroll
    for (int off = 16; off; off >>= 1) {
        s  += __shfl_xor_sync(0xffffffffu, s,  off);
        sq += __shfl_xor_sync(0xffffffffu, sq, off);
    }
    __shared__ float rs_[8], rq_[8];
    if ((t & 31) == 0) { rs_[t >> 5] = s; rq_[t >> 5] = sq; }
    __syncthreads();
    s = 0.f; sq = 0.f;
    #pragma unroll
    for (int i = 0; i < 8; i++) { s += rs_[i]; sq += rq_[i]; }
    const float mu   = s * (1.0f / 1024.0f);
    const float var  = sq * (1.0f / 1024.0f) - mu * mu;
    const float rstd = rsqrtf(var + 1e-5f);
    const float4 wv = *(const float4*)(w + t * 4);
    const float4 bv = *(const float4*)(b + t * 4);
    float ox = (v.x - mu) * rstd * wv.x + bv.x;
    float oy = (v.y - mu) * rstd * wv.y + bv.y;
    float oz = (v.z - mu) * rstd * wv.z + bv.z;
    float ow = (v.w - mu) * rstd * wv.w + bv.w;
    uint32_t h0, l0, h1, l1;
    split2(ox, oy, h0, l0);
    split2(oz, ow, h1, l1);
    *(uint2*)(outh + (size_t)row * C_ + t * 4) = make_uint2(h0, h1);
    if (outl) *(uint2*)(outl + (size_t)row * C_ + t * 4) = make_uint2(l0, l1);
}

// ================= 2-pass GEMM, 256x128 block, 64x64 warp tile =================
#define GSTG2 65536u
#define GEMM_SMEM2 (3*65536)

template <int EPI>
__global__ void __launch_bounds__(256, 1) gemm_h2(
    const __half* __restrict__ Ah,
    const __half* __restrict__ Wh, const __half* __restrict__ Wl,
    const float* __restrict__ bias, const float* __restrict__ resid,
    float* __restrict__ outf, __half* __restrict__ outh, __half* __restrict__ outl,
    int N, int K)
{
    extern __shared__ char sm[];
    const uint32_t sb = smem_u32(sm);
    const int t = threadIdx.x, w = t >> 5, lane = t & 31;
    const int bm = blockIdx.y, bn = blockIdx.x;
    const int wm = w & 3, wn = w >> 2;

    const int crow = t >> 1, chalf = t & 1;
    const __half* agh = Ah + (size_t)(bm*256 + crow) * K + chalf*32;
    const __half* bgh = Wh + (size_t)(bn*128 + crow) * K + chalf*32;
    const __half* bgl = Wl + (size_t)(bn*128 + crow) * K + chalf*32;
    uint32_t dsto[4];
    #pragma unroll
    for (int i = 0; i < 4; i++) {
        int c16 = chalf*4 + i;
        dsto[i] = (uint32_t)(crow*128 + ((c16 ^ (crow & 7)) << 4));
    }
    auto load_stage = [&](int c, int slot) {
        const uint32_t s0 = sb + (uint32_t)slot * GSTG2;
        const __half* a0 = agh + c*64;
        const __half* b0 = bgh + c*64;
        const __half* b1 = bgl + c*64;
        #pragma unroll
        for (int i = 0; i < 4; i++) CP_ASYNC16(s0 + dsto[i],           a0 + i*8);
        #pragma unroll
        for (int i = 0; i < 4; i++) CP_ASYNC16(s0 + 16384u + dsto[i],  a0 + (size_t)128*K + i*8);
        #pragma unroll
        for (int i = 0; i < 4; i++) CP_ASYNC16(s0 + 32768u + dsto[i],  b0 + i*8);
        #pragma unroll
        for (int i = 0; i < 4; i++) CP_ASYNC16(s0 + 49152u + dsto[i],  b1 + i*8);
    };

    const int ra = lane & 15, ca = lane >> 4;
    const int rb = (lane & 7) + ((lane >> 4) << 3), cb = (lane >> 3) & 1;
    const int xr = lane & 7;
    const uint32_t aro = (uint32_t)((wm*64 + ra) * 128);
    const uint32_t bro = (uint32_t)((wn*64 + rb) * 128);

    float acc[4][8][4];
    #pragma unroll
    for (int i = 0; i < 4; i++)
        #pragma unroll
        for (int j = 0; j < 8; j++)
            #pragma unroll
            for (int r = 0; r < 4; r++) acc[i][j][r] = 0.f;

    load_stage(0, 0); CP_COMMIT;
    load_stage(1, 1); CP_COMMIT;

    const int NC = K >> 6;
    int slot = 0;
    for (int c = 0; c < NC; c++) {
        CP_WAIT(1);
        __syncthreads();
        if (c + 2 < NC) {
            int ns = slot + 2; if (ns >= 3) ns -= 3;
            load_stage(c + 2, ns);
        }
        CP_COMMIT;
        const uint32_t st = sb + (uint32_t)slot * GSTG2;
        #pragma unroll
        for (int ks = 0; ks < 4; ks++) {
            const uint32_t kca = (uint32_t)(((ks*2 + ca) ^ xr) << 4);
            const uint32_t kcb = (uint32_t)(((ks*2 + cb) ^ xr) << 4);
            uint32_t ah[4][4], bh[4][4], bl4[4][4];
            #pragma unroll
            for (int mt = 0; mt < 4; mt++)
                ldsm4(ah[mt], st + aro + mt*2048u + kca);
            #pragma unroll
            for (int nq = 0; nq < 4; nq++) {
                ldsm4(bh[nq],  st + 32768u + bro + nq*2048u + kcb);
                ldsm4(bl4[nq], st + 49152u + bro + nq*2048u + kcb);
            }
            #pragma unroll
            for (int mt = 0; mt < 4; mt++)
                #pragma unroll
                for (int nt = 0; nt < 8; nt++) {
                    const int nq = nt >> 1, s2 = (nt & 1) * 2;
                    mma16816(acc[mt][nt], ah[mt], bh[nq][s2], bh[nq][s2+1]);
                }
            #pragma unroll
            for (int mt = 0; mt < 4; mt++)
                #pragma unroll
                for (int nt = 0; nt < 8; nt++) {
                    const int nq = nt >> 1, s2 = (nt & 1) * 2;
                    mma16816(acc[mt][nt], ah[mt], bl4[nq][s2], bl4[nq][s2+1]);
                }
        }
        slot = (slot + 1 == 3) ? 0 : slot + 1;
    }

    // ---- epilogue ----
    const int grbase = bm*256 + wm*64;
    const int gcbase = bn*128 + wn*64;
    #pragma unroll
    for (int mt = 0; mt < 4; mt++) {
        const int r0 = grbase + mt*16 + (lane >> 2);
        #pragma unroll
        for (int nt = 0; nt < 8; nt++) {
            const int gc = gcbase + nt*8 + (lane & 3)*2;
            float2 v0 = make_float2(acc[mt][nt][0], acc[mt][nt][1]);
            float2 v1 = make_float2(acc[mt][nt][2], acc[mt][nt][3]);
            {
                float2 bb = *(const float2*)(bias + gc);
                v0.x += bb.x; v0.y += bb.y; v1.x += bb.x; v1.y += bb.y;
            }
            if (EPI == 1) {
                const int third = gc >> 10, lc = gc & 1023;
                __half* oh = outh + (size_t)third * ((size_t)M_ * C_);
                if (third == 0) {
                    v0.x *= QSCALE; v0.y *= QSCALE; v1.x *= QSCALE; v1.y *= QSCALE;
                    *(uint32_t*)(oh + (size_t)r0 * 1024 + lc)     = pack_h2(v0.x, v0.y);
                    *(uint32_t*)(oh + (size_t)(r0+8) * 1024 + lc) = pack_h2(v1.x, v1.y);
                } else {
                    __half* ol = outl + (size_t)third * ((size_t)M_ * C_);
                    uint32_t h0, l0;
                    split2(v0.x, v0.y, h0, l0);
                    *(uint32_t*)(oh + (size_t)r0 * 1024 + lc) = h0;
                    *(uint32_t*)(ol + (size_t)r0 * 1024 + lc) = l0;
                    split2(v1.x, v1.y, h0, l0);
                    *(uint32_t*)(oh + (size_t)(r0+8) * 1024 + lc) = h0;
                    *(uint32_t*)(ol + (size_t)(r0+8) * 1024 + lc) = l0;
                }
            } else if (EPI == 2) {
                v0.x = gelu_exact(v0.x); v0.y = gelu_exact(v0.y);
                v1.x = gelu_exact(v1.x); v1.y = gelu_exact(v1.y);
                *(uint32_t*)(outh + (size_t)r0 * N + gc)     = pack_h2(v0.x, v0.y);
                *(uint32_t*)(outh + (size_t)(r0+8) * N + gc) = pack_h2(v1.x, v1.y);
            } else {  // EPI == 3
                float2 ra2 = *(const float2*)(resid + (size_t)r0 * N + gc);
                float2 rb2 = *(const float2*)(resid + (size_t)(r0+8) * N + gc);
                v0.x += ra2.x; v0.y += ra2.y; v1.x += rb2.x; v1.y += rb2.y;
                *(float2*)(outf + (size_t)r0 * N + gc) = v0;
                *(float2*)(outf + (size_t)(r0+8) * N + gc) = v1;
            }
        }
    }
}

// ================= head GEMM: 3-pass, 128x128 block =================
#define GSTG3 65536u
#define GEMM_SMEM3 (3*65536)

__global__ void __launch_bounds__(256, 1) gemm_head(
    const __half* __restrict__ Ah, const __half* __restrict__ Al,
    const __half* __restrict__ Wh, const __half* __restrict__ Wl,
    float* __restrict__ outf, int N, int K)
{
    extern __shared__ char sm[];
    const uint32_t sb = smem_u32(sm);
    const int t = threadIdx.x, w = t >> 5, lane = t & 31;
    const int bm = blockIdx.y, bn = blockIdx.x;
    const int wm = w & 3, wn = w >> 2;

    const int crow = t >> 1, chalf = t & 1;
    const __half* agh = Ah + (size_t)(bm*128 + crow) * K + chalf*32;
    const __half* agl = Al + (size_t)(bm*128 + crow) * K + chalf*32;
    const __half* bgh = Wh + (size_t)(bn*128 + crow) * K + chalf*32;
    const __half* bgl = Wl + (size_t)(bn*128 + crow) * K + chalf*32;
    uint32_t dsto[4];
    #pragma unroll
    for (int i = 0; i < 4; i++) {
        int c16 = chalf*4 + i;
        dsto[i] = (uint32_t)(crow*128 + ((c16 ^ (crow & 7)) << 4));
    }
    auto load_stage = [&](int c, int slot) {
        const uint32_t s0 = sb + (uint32_t)slot * GSTG3;
        #pragma unroll
        for (int i = 0; i < 4; i++) CP_ASYNC16(s0 + dsto[i],          agh + c*64 + i*8);
        #pragma unroll
        for (int i = 0; i < 4; i++) CP_ASYNC16(s0 + 16384u + dsto[i], agl + c*64 + i*8);
        #pragma unroll
        for (int i = 0; i < 4; i++) CP_ASYNC16(s0 + 32768u + dsto[i], bgh + c*64 + i*8);
        #pragma unroll
        for (int i = 0; i < 4; i++) CP_ASYNC16(s0 + 49152u + dsto[i], bgl + c*64 + i*8);
    };

    const int ra = lane & 15, ca = lane >> 4;
    const int rb = (lane & 7) + ((lane >> 4) << 3), cb = (lane >> 3) & 1;
    const int xr = lane & 7;
    const uint32_t aro = (uint32_t)((wm*32 + ra) * 128);
    const uint32_t bro = (uint32_t)((wn*64 + rb) * 128);

    float acc[2][8][4];
    #pragma unroll
    for (int i = 0; i < 2; i++)
        #pragma unroll
        for (int j = 0; j < 8; j++)
            #pragma unroll
            for (int r = 0; r < 4; r++) acc[i][j][r] = 0.f;

    load_stage(0, 0); CP_COMMIT;
    load_stage(1, 1); CP_COMMIT;

    const int NC = K >> 6;
    int slot = 0;
    for (int c = 0; c < NC; c++) {
        CP_WAIT(1);
        __syncthreads();
        if (c + 2 < NC) {
            int ns = slot + 2; if (ns >= 3) ns -= 3;
            load_stage(c + 2, ns);
        }
        CP_COMMIT;
        const uint32_t st = sb + (uint32_t)slot * GSTG3;
        #pragma unroll
        for (int ks = 0; ks < 4; ks++) {
            const uint32_t kca = (uint32_t)(((ks*2 + ca) ^ xr) << 4);
            const uint32_t kcb = (uint32_t)(((ks*2 + cb) ^ xr) << 4);
            uint32_t ah[2][4], al4[2][4], bh[4][4], bl4[4][4];
            #pragma unroll
            for (int mt = 0; mt < 2; mt++) {
                ldsm4(ah[mt],  st + aro + mt*2048u + kca);
                ldsm4(al4[mt], st + 16384u + aro + mt*2048u + kca);
            }
            #pragma unroll
            for (int nq = 0; nq < 4; nq++) {
                ldsm4(bh[nq],  st + 32768u + bro + nq*2048u + kcb);
                ldsm4(bl4[nq], st + 49152u + bro + nq*2048u + kcb);
            }
            #pragma unroll
            for (int mt = 0; mt < 2; mt++)
                #pragma unroll
                for (int nt = 0; nt < 8; nt++) {
                    const int nq = nt >> 1, s2 = (nt & 1) * 2;
                    mma16816(acc[mt][nt], ah[mt], bh[nq][s2], bh[nq][s2+1]);
                }
            #pragma unroll
            for (int mt = 0; mt < 2; mt++)
                #pragma unroll
                for (int nt = 0; nt < 8; nt++) {
                    const int nq = nt >> 1, s2 = (nt & 1) * 2;
                    mma16816(acc[mt][nt], ah[mt], bl4[nq][s2], bl4[nq][s2+1]);
                }
            #pragma unroll
            for (int mt = 0; mt < 2; mt++)
                #pragma unroll
                for (int nt = 0; nt < 8; nt++) {
                    const int nq = nt >> 1, s2 = (nt & 1) * 2;
                    mma16816(acc[mt][nt], al4[mt], bh[nq][s2], bh[nq][s2+1]);
                }
        }
        slot = (slot + 1 == 3) ? 0 : slot + 1;
    }

    const int grbase = bm*128 + wm*32;
    const int gcbase = bn*128 + wn*64;
    #pragma unroll
    for (int mt = 0; mt < 2; mt++) {
        const int r0 = grbase + mt*16 + (lane >> 2);
        #pragma unroll
        for (int nt = 0; nt < 8; nt++) {
            const int gc = gcbase + nt*8 + (lane & 3)*2;
            *(float2*)(outf + (size_t)r0 * N + gc) =
                make_float2(acc[mt][nt][0], acc[mt][nt][1]);
            *(float2*)(outf + (size_t)(r0+8) * N + gc) =
                make_float2(acc[mt][nt][2], acc[mt][nt][3]);
        }
    }
}

// ================= flash attention: Q tile 256, 64x64 warp tile =================
// 8 warps, each warp 32 Q rows. KV tile 64. 2-pass QK and PV.
// smem: Qh[256x64]@0 (32KB), then 3 stages of 32KB: Kh@0 Kl@8K Vh@16K Vl@24K.
#define ASTG 32768
#define AQSZ 32768
#define ATT_SMEM (AQSZ + 3*ASTG)

__global__ void __launch_bounds__(256, 1) attn_h(
    const __half* __restrict__ qkvh, const __half* __restrict__ qkvl,
    __half* __restrict__ yh)
{
    extern __shared__ char sm[];
    const uint32_t sb = smem_u32(sm);
    const int t = threadIdx.x, w = t >> 5, lane = t & 31;
    const int bhx = blockIdx.y, b = bhx >> 4, h = bhx & 15;
    const int q0 = blockIdx.x * 256;
    const size_t MC = (size_t)M_ * C_;
    const int NT = T_ / 64;   // 32 tiles

    const __half* qgh = qkvh + (size_t)(b*T_ + q0) * C_ + h*64;
    const __half* kgh = qkvh + MC   + (size_t)(b*T_) * C_ + h*64;
    const __half* kgl = qkvl + MC   + (size_t)(b*T_) * C_ + h*64;
    const __half* vgh = qkvh + 2*MC + (size_t)(b*T_) * C_ + h*64;
    const __half* vgl = qkvl + 2*MC + (size_t)(b*T_) * C_ + h*64;

    // Q loads (hi only): each thread loads one full row (8 x 16B)
    {
        const int qr = t;
        const __half* qrow = qgh + (size_t)qr * C_;
        #pragma unroll
        for (int i = 0; i < 8; i++) {
            const uint32_t d = (uint32_t)(qr*128 + ((i ^ (qr & 7)) << 4));
            CP_ASYNC16(sb + d, qrow + i*8);
        }
    }
    CP_COMMIT;

    // KV stage loader
    const int kr = t >> 2, kc2 = (t & 3) * 2;
    auto load_kv = [&](int kt, int slot) {
        const uint32_t s0 = sb + AQSZ + (uint32_t)slot * ASTG;
        const size_t rowoff = (size_t)(kt*64 + kr) * C_;
        #pragma unroll
        for (int i = 0; i < 2; i++) {
            const int c16 = kc2 + i;
            const uint32_t d = (uint32_t)(kr*128 + ((c16 ^ (kr & 7)) << 4));
            CP_ASYNC16(s0 + d,          kgh + rowoff + c16*8);
            CP_ASYNC16(s0 + 8192u + d,  kgl + rowoff + c16*8);
            CP_ASYNC16(s0 + 16384u + d, vgh + rowoff + c16*8);
            CP_ASYNC16(s0 + 24576u + d, vgl + rowoff + c16*8);
        }
    };
    load_kv(0, 0); CP_COMMIT;
    load_kv(1, 1); CP_COMMIT;

    // ldmatrix lane geometry
    const int ra = lane & 15, ca = lane >> 4;
    const int rb = (lane & 7) + ((lane >> 4) << 3), cb = (lane >> 3) & 1;
    const int rv = (lane & 7) + (((lane >> 3) & 1) << 3), cv = lane >> 4;
    const int xr = lane & 7;

    CP_WAIT(2);           // Q landed
    __syncthreads();
    uint32_t qh4[4][2][4];   // [ks][mt][regs]
    {
        #pragma unroll
        for (int mt = 0; mt < 2; mt++) {
            const uint32_t qro = (uint32_t)((w*32 + mt*16 + ra) * 128);
            #pragma unroll
            for (int ks = 0; ks < 4; ks++) {
                const uint32_t off = qro + (uint32_t)(((ks*2 + ca) ^ xr) << 4);
                ldsm4(qh4[ks][mt], sb + off);
            }
        }
    }

    float o_[2][8][4];    // [mt][dim-tile][regs]
    #pragma unroll
    for (int mt = 0; mt < 2; mt++)
        #pragma unroll
        for (int i = 0; i < 8; i++)
            #pragma unroll
            for (int j = 0; j < 4; j++) o_[mt][i][j] = 0.f;
    float m_a[2] = {-1e30f, -1e30f}, m_b[2] = {-1e30f, -1e30f};
    float l_a[2] = {0.f, 0.f},       l_b[2] = {0.f, 0.f};

    int slot = 0;
    for (int kt = 0; kt < NT; kt++) {
        CP_WAIT(1);
        __syncthreads();
        if (kt + 2 < NT) {
            int ns = slot + 2; if (ns >= 3) ns -= 3;
            load_kv(kt + 2, ns);
        }
        CP_COMMIT;
        const uint32_t st = sb + AQSZ + (uint32_t)slot * ASTG;

        // ---- S = qh·(kh + kl) (2-pass), warp tile 32x64 ----
        float sc[2][8][4];
        #pragma unroll
        for (int mt = 0; mt < 2; mt++)
            #pragma unroll
            for (int i = 0; i < 8; i++)
                #pragma unroll
                for (int j = 0; j < 4; j++) sc[mt][i][j] = 0.f;
        #pragma unroll
        for (int ks = 0; ks < 4; ks++) {
            uint32_t kh4[4][4], kl4[4][4];
            #pragma unroll
            for (int nq = 0; nq < 4; nq++) {
                const uint32_t off = (uint32_t)((nq*16 + rb) * 128)
                                   + (uint32_t)(((ks*2 + cb) ^ xr) << 4);
                ldsm4(kh4[nq], st + off);
                ldsm4(kl4[nq], st + 8192u + off);
            }
            #pragma unroll
            for (int mt = 0; mt < 2; mt++)
                #pragma unroll
                for (int nt = 0; nt < 8; nt++) {
                    const int nq = nt >> 1, s2 = (nt & 1) * 2;
                    mma16816(sc[mt][nt], qh4[ks][mt], kh4[nq][s2], kh4[nq][s2+1]);
                }
            #pragma unroll
            for (int mt = 0; mt < 2; mt++)
                #pragma unroll
                for (int nt = 0; nt < 8; nt++) {
                    const int nq = nt >> 1, s2 = (nt & 1) * 2;
                    mma16816(sc[mt][nt], qh4[ks][mt], kl4[nq][s2], kl4[nq][s2+1]);
                }
        }

        // ---- online softmax (base-2), per mt tile ----
        #pragma unroll
        for (int mt = 0; mt < 2; mt++) {
            float mxa = -1e30f, mxb = -1e30f;
            #pragma unroll
            for (int nt = 0; nt < 8; nt++) {
                mxa = fmaxf(mxa, fmaxf(sc[mt][nt][0], sc[mt][nt][1]));
                mxb = fmaxf(mxb, fmaxf(sc[mt][nt][2], sc[mt][nt][3]));
            }
            mxa = fmaxf(mxa, __shfl_xor_sync(0xffffffffu, mxa, 1));
            mxa = fmaxf(mxa, __shfl_xor_sync(0xffffffffu, mxa, 2));
            mxb = fmaxf(mxb, __shfl_xor_sync(0xffffffffu, mxb, 1));
            mxb = fmaxf(mxb, __shfl_xor_sync(0xffffffffu, mxb, 2));
            const float nma = fmaxf(m_a[mt], mxa), nmb = fmaxf(m_b[mt], mxb);
            const float cfa = fex2(m_a[mt] - nma), cfb = fex2(m_b[mt] - nmb);
            m_a[mt] = nma; m_b[mt] = nmb;
            float rsa = 0.f, rsb = 0.f;
            #pragma unroll
            for (int nt = 0; nt < 8; nt++) {
                sc[mt][nt][0] = fex2(sc[mt][nt][0] - nma); rsa += sc[mt][nt][0];
                sc[mt][nt][1] = fex2(sc[mt][nt][1] - nma); rsa += sc[mt][nt][1];
                sc[mt][nt][2] = fex2(sc[mt][nt][2] - nmb); rsb += sc[mt][nt][2];
                sc[mt][nt][3] = fex2(sc[mt][nt][3] - nmb); rsb += sc[mt][nt][3];
            }
            rsa += __shfl_xor_sync(0xffffffffu, rsa, 1);
            rsa += __shfl_xor_sync(0xffffffffu, rsa, 2);
            rsb += __shfl_xor_sync(0xffffffffu, rsb, 1);
            rsb += __shfl_xor_sync(0xffffffffu, rsb, 2);
            l_a[mt] = l_a[mt] * cfa + rsa;
            l_b[mt] = l_b[mt] * cfb + rsb;
            #pragma unroll
            for (int dt = 0; dt < 8; dt++) {
                o_[mt][dt][0] *= cfa; o_[mt][dt][1] *= cfa;
                o_[mt][dt][2] *= cfb; o_[mt][dt][3] *= cfb;
            }
        }

        // ---- O += ph·(vh + vl) (2-pass) ----
        #pragma unroll
        for (int ks = 0; ks < 4; ks++) {
            uint32_t ph[2][4];
            #pragma unroll
            for (int mt = 0; mt < 2; mt++) {
                ph[mt][0] = pack_h2(sc[mt][2*ks][0],   sc[mt][2*ks][1]);
                ph[mt][1] = pack_h2(sc[mt][2*ks][2],   sc[mt][2*ks][3]);
                ph[mt][2] = pack_h2(sc[mt][2*ks+1][0], sc[mt][2*ks+1][1]);
                ph[mt][3] = pack_h2(sc[mt][2*ks+1][2], sc[mt][2*ks+1][3]);
            }
            uint32_t vh4[4][4], vl4[4][4];
            #pragma unroll
            for (int nq = 0; nq < 4; nq++) {
                const uint32_t off = (uint32_t)((ks*16 + rv) * 128)
                                   + (uint32_t)(((nq*2 + cv) ^ xr) << 4);
                ldsm4t(vh4[nq], st + 16384u + off);
                ldsm4t(vl4[nq], st + 24576u + off);
            }
            #pragma unroll
            for (int mt = 0; mt < 2; mt++)
                #pragma unroll
                for (int dt = 0; dt < 8; dt++) {
                    const int nq = dt >> 1, s2 = (dt & 1) * 2;
                    mma16816(o_[mt][dt], ph[mt], vh4[nq][s2], vh4[nq][s2+1]);
                }
            #pragma unroll
            for (int mt = 0; mt < 2; mt++)
                #pragma unroll
                for (int dt = 0; dt < 8; dt++) {
                    const int nq = dt >> 1, s2 = (dt & 1) * 2;
                    mma16816(o_[mt][dt], ph[mt], vl4[nq][s2], vl4[nq][s2+1]);
                }
        }
        slot = (slot + 1 == 3) ? 0 : slot + 1;
    }

    // ---- write y (fp16 hi only) ----
    #pragma unroll
    for (int mt = 0; mt < 2; mt++) {
        const float ia = 1.f / l_a[mt], ib = 1.f / l_b[mt];
        const int r0 = q0 + w*32 + mt*16 + (lane >> 2);
        __half* ybh = yh + (size_t)(b*T_ + r0) * C_ + h*64;
        #pragma unroll
        for (int dt = 0; dt < 8; dt++) {
            const int gc = dt*8 + (lane & 3)*2;
            *(uint32_t*)(ybh + gc)                = pack_h2(o_[mt][dt][0]*ia, o_[mt][dt][1]*ia);
            *(uint32_t*)(ybh + (size_t)8*C_ + gc) = pack_h2(o_[mt][dt][2]*ib, o_[mt][dt][3]*ib);
        }
    }
}

// ================= orchestration =================
extern "C" void kernel_launch(void* const* d_in, const int* in_sizes, int n_in,
                              void* d_out, int out_size)
{
    const float* seq  = (const float*)d_in[0];
    const float* pos  = (const float*)d_in[1];
    const float* Wq   = (const float*)d_in[2];
    const float* bq   = (const float*)d_in[3];
    const float* Wk   = (const float*)d_in[4];
    const float* bk   = (const float*)d_in[5];
    const float* Wv   = (const float*)d_in[6];
    const float* bv   = (const float*)d_in[7];
    const float* Wo   = (const float*)d_in[8];
    const float* bo   = (const float*)d_in[9];
    const float* ln1w = (const float*)d_in[10];
    const float* ln1b = (const float*)d_in[11];
    const float* ln2w = (const float*)d_in[12];
    const float* ln2b = (const float*)d_in[13];
    const float* W1   = (const float*)d_in[14];
    const float* b1   = (const float*)d_in[15];
    const float* W2   = (const float*)d_in[16];
    const float* b2   = (const float*)d_in[17];
    const float* lnfw = (const float*)d_in[18];
    const float* lnfb = (const float*)d_in[19];
    const float* Wh   = (const float*)d_in[20];
    float* out = (float*)d_out;

    float *px, *pbqkv;
    __half *phh, *phl, *pqkvh, *pqkvl, *pyh, *puh, *pwh, *pwl;
    cudaGetSymbolAddress((void**)&px, g_x);
    cudaGetSymbolAddress((void**)&phh, g_hh);
    cudaGetSymbolAddress((void**)&phl, g_hl);
    cudaGetSymbolAddress((void**)&pqkvh, g_qkvh);
    cudaGetSymbolAddress((void**)&pqkvl, g_qkvl);
    cudaGetSymbolAddress((void**)&pyh, g_yh);
    cudaGetSymbolAddress((void**)&puh, g_uh);
    cudaGetSymbolAddress((void**)&pwh, g_wh);
    cudaGetSymbolAddress((void**)&pwl, g_wl);
    cudaGetSymbolAddress((void**)&pbqkv, g_bqkv);

    cudaFuncSetAttribute(attn_h, cudaFuncAttributeMaxDynamicSharedMemorySize, ATT_SMEM);
    cudaFuncSetAttribute((gemm_h2<1>), cudaFuncAttributeMaxDynamicSharedMemorySize, GEMM_SMEM2);
    cudaFuncSetAttribute((gemm_h2<2>), cudaFuncAttributeMaxDynamicSharedMemorySize, GEMM_SMEM2);
    cudaFuncSetAttribute((gemm_h2<3>), cudaFuncAttributeMaxDynamicSharedMemorySize, GEMM_SMEM2);
    cudaFuncSetAttribute(gemm_head, cudaFuncAttributeMaxDynamicSharedMemorySize, GEMM_SMEM3);

    // ---- weight conversion: ONE launch ----
    conv_all<<<(int)(WTOT / 2048), 256>>>(Wq, Wk, Wv, Wo, W1, W2, Wh, pwh, pwl);
    packqkvb<<<L_*3*C_/256, 256>>>(bq, bk, bv, pbqkv);
    addpos_kernel<<<M_ * C_ / 4 / 256, 256>>>(seq, pos, px);

    dim3 gQKV(3*C_ / 128, M_ / 256);   // (24, 32)
    dim3 gC(C_ / 128, M_ / 256);       // (8, 32)
    dim3 gF(FF_ / 128, M_ / 256);      // (32, 32)
    dim3 gA(T_ / 256, B_ * H_);        // (8, 64)
    dim3 gHead(OUT_ / 128, M_ / 128);  // (8, 64)

    for (int l = 0; l < L_; l++) {
        const size_t wl = (size_t)l * WPL_;
        ln_split<<<M_, 256>>>(px, ln1w + l*C_, ln1b + l*C_, phh, nullptr);
        gemm_h2<1><<<gQKV, 256, GEMM_SMEM2>>>(phh, pwh + wl, pwl + wl,
            pbqkv + l*3*C_, nullptr, nullptr, pqkvh, pqkvl, 3*C_, C_);
        attn_h<<<gA, 256, ATT_SMEM>>>(pqkvh, pqkvl, pyh);
        gemm_h2<3><<<gC, 256, GEMM_SMEM2>>>(pyh, pwh + wl + WOFF_WO, pwl + wl + WOFF_WO,
            bo + l*C_, px, px, nullptr, nullptr, C_, C_);
        ln_split<<<M_, 256>>>(px, ln2w + l*C_, ln2b + l*C_, phh, nullptr);
        gemm_h2<2><<<gF, 256, GEMM_SMEM2>>>(phh, pwh + wl + WOFF_W1, pwl + wl + WOFF_W1,
            b1 + l*FF_, nullptr, nullptr, puh, nullptr, FF_, C_);
        gemm_h2<3><<<gC, 256, GEMM_SMEM2>>>(puh, pwh + wl + WOFF_W2, pwl + wl + WOFF_W2,
            b2 + l*C_, px, px, nullptr, nullptr, C_, FF_);
    }

    // final LN needs lo for the 3-pass head GEMM
    ln_split<<<M_, 256>>>(px, lnfw, lnfb, phh, phl);
    gemm_head<<<gHead, 256, GEMM_SMEM3>>>(phh, phl, pwh + WHEAD_OFF, pwl + WHEAD_OFF,
        out, OUT_, C_);
}

// round 11
// speedup vs baseline: 5.7565x; 1.3862x over previous
#include <cuda_runtime.h>
#include <cuda_fp16.h>
#include <math.h>
#include <stdint.h>

#define L_ 8
#define H_ 16
#define T_ 2048
#define C_ 1024
#define OUT_ 1024
#define B_ 4
#define DH_ 64
#define FF_ 4096
#define M_ (B_*T_)   // 8192 rows

#define CC_ (C_*C_)                   // 1048576
#define WPL_ (12*CC_)                 // weights per layer (halves)
#define WOFF_WO  (3*CC_)
#define WOFF_W1  (4*CC_)
#define WOFF_W2  (8*CC_)
#define WHEAD_OFF ((size_t)L_*WPL_)   // 100663296
#define WTOT (WHEAD_OFF + CC_)        // 101711872

// q pre-scale: 0.125 (1/sqrt(DH)) * log2(e) -> softmax in base-2 domain
#define QSCALE 0.1803368801111204f

// ---------------- scratch (static device globals) ----------------
__device__ float g_x[M_*C_];
__device__ __align__(16) __half g_hh[M_*C_],  g_hl[M_*C_];
__device__ __align__(16) __half g_qkvh[3*M_*C_], g_qkvl[3*M_*C_];
__device__ __align__(16) __half g_yh[M_*C_];
__device__ __align__(16) __half g_uh[(size_t)M_*FF_];
__device__ __align__(16) __half g_wh[WTOT],   g_wl[WTOT];
__device__ float g_bqkv[L_*3*C_];

// ================= helpers =================
__device__ __forceinline__ uint32_t smem_u32(const void* p) {
    uint32_t a;
    asm("{ .reg .u64 t; cvta.to.shared.u64 t, %1; cvt.u32.u64 %0, t; }" : "=r"(a) : "l"(p));
    return a;
}
__device__ __forceinline__ void mma16816(float* c, const uint32_t* a, uint32_t b0, uint32_t b1) {
    asm volatile(
        "mma.sync.aligned.m16n8k16.row.col.f32.f16.f16.f32 "
        "{%0,%1,%2,%3}, {%4,%5,%6,%7}, {%8,%9}, {%0,%1,%2,%3};"
        : "+f"(c[0]), "+f"(c[1]), "+f"(c[2]), "+f"(c[3])
        : "r"(a[0]), "r"(a[1]), "r"(a[2]), "r"(a[3]), "r"(b0), "r"(b1));
}
__device__ __forceinline__ void ldsm4(uint32_t* r, uint32_t addr) {
    asm volatile("ldmatrix.sync.aligned.m8n8.x4.shared.b16 {%0,%1,%2,%3}, [%4];"
                 : "=r"(r[0]), "=r"(r[1]), "=r"(r[2]), "=r"(r[3]) : "r"(addr));
}
__device__ __forceinline__ void ldsm4t(uint32_t* r, uint32_t addr) {
    asm volatile("ldmatrix.sync.aligned.m8n8.x4.trans.shared.b16 {%0,%1,%2,%3}, [%4];"
                 : "=r"(r[0]), "=r"(r[1]), "=r"(r[2]), "=r"(r[3]) : "r"(addr));
}
#define CP_ASYNC16(dst, src) \
    asm volatile("cp.async.cg.shared.global [%0], [%1], 16;" :: "r"(dst), "l"(src))
#define CP_COMMIT asm volatile("cp.async.commit_group;" ::: "memory")
#define CP_WAIT(n) asm volatile("cp.async.wait_group %0;" :: "n"(n) : "memory")

__device__ __forceinline__ float fex2(float x) {
    float y;
    asm("ex2.approx.f32 %0, %1;" : "=f"(y) : "f"(x));
    return y;
}
__device__ __forceinline__ void split2(float x, float y, uint32_t& h, uint32_t& l) {
    __half2 hh = __floats2half2_rn(x, y);
    float2 hf = __half22float2(hh);
    __half2 ll = __floats2half2_rn(x - hf.x, y - hf.y);
    h = *(uint32_t*)&hh;
    l = *(uint32_t*)&ll;
}
__device__ __forceinline__ uint32_t pack_h2(float x, float y) {
    __half2 hh = __floats2half2_rn(x, y);
    return *(uint32_t*)&hh;
}
__device__ __forceinline__ float gelu_exact(float v) {
    return 0.5f * v * (1.0f + erff(v * 0.70710678118654752f));
}

// ================= fused weight conversion (single launch) =================
// hi for everything; lo only for the head weights (only 3-pass consumer).
__global__ void __launch_bounds__(256) conv_all(
    const float* __restrict__ Wq, const float* __restrict__ Wk,
    const float* __restrict__ Wv, const float* __restrict__ Wo,
    const float* __restrict__ W1, const float* __restrict__ W2,
    const float* __restrict__ Whd,
    __half* __restrict__ dh, __half* __restrict__ dl)
{
    const size_t i = ((size_t)blockIdx.x * 256 + threadIdx.x) * 8;
    const float* src;
    if (i >= WHEAD_OFF) {
        src = Whd + (i - WHEAD_OFF);
    } else {
        const int l = (int)(i / WPL_);
        const size_t r = i % WPL_;
        if      (r <   (size_t)CC_)   src = Wq + (size_t)l*CC_   + r;
        else if (r < 2*(size_t)CC_)   src = Wk + (size_t)l*CC_   + (r -   CC_);
        else if (r < 3*(size_t)CC_)   src = Wv + (size_t)l*CC_   + (r - 2*CC_);
        else if (r < 4*(size_t)CC_)   src = Wo + (size_t)l*CC_   + (r - 3*CC_);
        else if (r < 8*(size_t)CC_)   src = W1 + (size_t)l*4*CC_ + (r - 4*CC_);
        else                          src = W2 + (size_t)l*4*CC_ + (r - 8*CC_);
    }
    float4 a = *(const float4*)(src), b = *(const float4*)(src + 4);
    uint32_t h[4], l4[4];
    split2(a.x, a.y, h[0], l4[0]); split2(a.z, a.w, h[1], l4[1]);
    split2(b.x, b.y, h[2], l4[2]); split2(b.z, b.w, h[3], l4[3]);
    *(uint4*)(dh + i) = make_uint4(h[0], h[1], h[2], h[3]);
    if (i >= WHEAD_OFF)
        *(uint4*)(dl + i) = make_uint4(l4[0], l4[1], l4[2], l4[3]);
}
__global__ void __launch_bounds__(256) packqkvb(
    const float* __restrict__ bq, const float* __restrict__ bk,
    const float* __restrict__ bv, float* __restrict__ dst)
{
    int idx = blockIdx.x * 256 + threadIdx.x;      // L_*3072
    int l = idx / 3072, c = idx % 3072;
    float v = (c < 1024) ? bq[l*1024 + c] : (c < 2048) ? bk[l*1024 + c - 1024]
                                                        : bv[l*1024 + c - 2048];
    dst[idx] = v;
}

// ================= x = seq + pos =================
__global__ void __launch_bounds__(256) addpos_kernel(
    const float* __restrict__ seq, const float* __restrict__ pos, float* __restrict__ x)
{
    int i = blockIdx.x * 256 + threadIdx.x;
    float4 s = ((const float4*)seq)[i];
    float4 p = ((const float4*)pos)[i & (T_*C_/4 - 1)];
    s.x += p.x; s.y += p.y; s.z += p.z; s.w += p.w;
    ((float4*)x)[i] = s;
}

// ================= LayerNorm -> fp16 hi (+ optional lo) =================
__global__ void __launch_bounds__(256) ln_split(
    const float* __restrict__ x, const float* __restrict__ w,
    const float* __restrict__ b, __half* __restrict__ outh, __half* __restrict__ outl)
{
    const int row = blockIdx.x;
    const int t = threadIdx.x;
    const float4 v = *(const float4*)(x + (size_t)row * C_ + t * 4);
    float s  = v.x + v.y + v.z + v.w;
    float sq = v.x*v.x + v.y*v.y + v.z*v.z + v.w*v.w;
    #pragma unroll
    for (int off = 16; off; off >>= 1) {
        s  += __shfl_xor_sync(0xffffffffu, s,  off);
        sq += __shfl_xor_sync(0xffffffffu, sq, off);
    }
    __shared__ float rs_[8], rq_[8];
    if ((t & 31) == 0) { rs_[t >> 5] = s; rq_[t >> 5] = sq; }
    __syncthreads();
    s = 0.f; sq = 0.f;
    #pragma unroll
    for (int i = 0; i < 8; i++) { s += rs_[i]; sq += rq_[i]; }
    const float mu   = s * (1.0f / 1024.0f);
    const float var  = sq * (1.0f / 1024.0f) - mu * mu;
    const float rstd = rsqrtf(var + 1e-5f);
    const float4 wv = *(const float4*)(w + t * 4);
    const float4 bv = *(const float4*)(b + t * 4);
    float ox = (v.x - mu) * rstd * wv.x + bv.x;
    float oy = (v.y - mu) * rstd * wv.y + bv.y;
    float oz = (v.z - mu) * rstd * wv.z + bv.z;
    float ow = (v.w - mu) * rstd * wv.w + bv.w;
    uint32_t h0, l0, h1, l1;
    split2(ox, oy, h0, l0);
    split2(oz, ow, h1, l1);
    *(uint2*)(outh + (size_t)row * C_ + t * 4) = make_uint2(h0, h1);
    if (outl) *(uint2*)(outl + (size_t)row * C_ + t * 4) = make_uint2(l0, l1);
}

// ================= 1-pass fp16 GEMM, 256x128 block, 64x64 warp tile =================
// D[M,N] = A_hi[M,K] @ W_hi[N,K]^T. 3-stage cp.async.
// Stage 48KB: Ah[256x64]@0 (32K), Bh[128x64]@32K (16K).
#define GSTG2 49152u
#define GEMM_SMEM2 (3*49152)

template <int EPI>
__global__ void __launch_bounds__(256, 1) gemm_h2(
    const __half* __restrict__ Ah,
    const __half* __restrict__ Wh,
    const float* __restrict__ bias, const float* __restrict__ resid,
    float* __restrict__ outf, __half* __restrict__ outh, __half* __restrict__ outl,
    int N, int K)
{
    extern __shared__ char sm[];
    const uint32_t sb = smem_u32(sm);
    const int t = threadIdx.x, w = t >> 5, lane = t & 31;
    const int bm = blockIdx.y, bn = blockIdx.x;
    const int wm = w & 3, wn = w >> 2;

    const int crow = t >> 1, chalf = t & 1;
    const __half* agh = Ah + (size_t)(bm*256 + crow) * K + chalf*32;
    const __half* bgh = Wh + (size_t)(bn*128 + crow) * K + chalf*32;
    uint32_t dsto[4];
    #pragma unroll
    for (int i = 0; i < 4; i++) {
        int c16 = chalf*4 + i;
        dsto[i] = (uint32_t)(crow*128 + ((c16 ^ (crow & 7)) << 4));
    }
    auto load_stage = [&](int c, int slot) {
        const uint32_t s0 = sb + (uint32_t)slot * GSTG2;
        const __half* a0 = agh + c*64;
        const __half* b0 = bgh + c*64;
        #pragma unroll
        for (int i = 0; i < 4; i++) CP_ASYNC16(s0 + dsto[i],           a0 + i*8);
        #pragma unroll
        for (int i = 0; i < 4; i++) CP_ASYNC16(s0 + 16384u + dsto[i],  a0 + (size_t)128*K + i*8);
        #pragma unroll
        for (int i = 0; i < 4; i++) CP_ASYNC16(s0 + 32768u + dsto[i],  b0 + i*8);
    };

    const int ra = lane & 15, ca = lane >> 4;
    const int rb = (lane & 7) + ((lane >> 4) << 3), cb = (lane >> 3) & 1;
    const int xr = lane & 7;
    const uint32_t aro = (uint32_t)((wm*64 + ra) * 128);
    const uint32_t bro = (uint32_t)((wn*64 + rb) * 128);

    float acc[4][8][4];
    #pragma unroll
    for (int i = 0; i < 4; i++)
        #pragma unroll
        for (int j = 0; j < 8; j++)
            #pragma unroll
            for (int r = 0; r < 4; r++) acc[i][j][r] = 0.f;

    load_stage(0, 0); CP_COMMIT;
    load_stage(1, 1); CP_COMMIT;

    const int NC = K >> 6;
    int slot = 0;
    for (int c = 0; c < NC; c++) {
        CP_WAIT(1);
        __syncthreads();
        if (c + 2 < NC) {
            int ns = slot + 2; if (ns >= 3) ns -= 3;
            load_stage(c + 2, ns);
        }
        CP_COMMIT;
        const uint32_t st = sb + (uint32_t)slot * GSTG2;
        #pragma unroll
        for (int ks = 0; ks < 4; ks++) {
            const uint32_t kca = (uint32_t)(((ks*2 + ca) ^ xr) << 4);
            const uint32_t kcb = (uint32_t)(((ks*2 + cb) ^ xr) << 4);
            uint32_t ah[4][4], bh[4][4];
            #pragma unroll
            for (int mt = 0; mt < 4; mt++)
                ldsm4(ah[mt], st + aro + mt*2048u + kca);
            #pragma unroll
            for (int nq = 0; nq < 4; nq++)
                ldsm4(bh[nq], st + 32768u + bro + nq*2048u + kcb);
            #pragma unroll
            for (int mt = 0; mt < 4; mt++)
                #pragma unroll
                for (int nt = 0; nt < 8; nt++) {
                    const int nq = nt >> 1, s2 = (nt & 1) * 2;
                    mma16816(acc[mt][nt], ah[mt], bh[nq][s2], bh[nq][s2+1]);
                }
        }
        slot = (slot + 1 == 3) ? 0 : slot + 1;
    }

    // ---- epilogue ----
    const int grbase = bm*256 + wm*64;
    const int gcbase = bn*128 + wn*64;
    #pragma unroll
    for (int mt = 0; mt < 4; mt++) {
        const int r0 = grbase + mt*16 + (lane >> 2);
        #pragma unroll
        for (int nt = 0; nt < 8; nt++) {
            const int gc = gcbase + nt*8 + (lane & 3)*2;
            float2 v0 = make_float2(acc[mt][nt][0], acc[mt][nt][1]);
            float2 v1 = make_float2(acc[mt][nt][2], acc[mt][nt][3]);
            {
                float2 bb = *(const float2*)(bias + gc);
                v0.x += bb.x; v0.y += bb.y; v1.x += bb.x; v1.y += bb.y;
            }
            if (EPI == 1) {
                const int third = gc >> 10, lc = gc & 1023;
                __half* oh = outh + (size_t)third * ((size_t)M_ * C_);
                if (third == 0) {
                    v0.x *= QSCALE; v0.y *= QSCALE; v1.x *= QSCALE; v1.y *= QSCALE;
                    *(uint32_t*)(oh + (size_t)r0 * 1024 + lc)     = pack_h2(v0.x, v0.y);
                    *(uint32_t*)(oh + (size_t)(r0+8) * 1024 + lc) = pack_h2(v1.x, v1.y);
                } else {
                    __half* ol = outl + (size_t)third * ((size_t)M_ * C_);
                    uint32_t h0, l0;
                    split2(v0.x, v0.y, h0, l0);
                    *(uint32_t*)(oh + (size_t)r0 * 1024 + lc) = h0;
                    *(uint32_t*)(ol + (size_t)r0 * 1024 + lc) = l0;
                    split2(v1.x, v1.y, h0, l0);
                    *(uint32_t*)(oh + (size_t)(r0+8) * 1024 + lc) = h0;
                    *(uint32_t*)(ol + (size_t)(r0+8) * 1024 + lc) = l0;
                }
            } else if (EPI == 2) {
                v0.x = gelu_exact(v0.x); v0.y = gelu_exact(v0.y);
                v1.x = gelu_exact(v1.x); v1.y = gelu_exact(v1.y);
                *(uint32_t*)(outh + (size_t)r0 * N + gc)     = pack_h2(v0.x, v0.y);
                *(uint32_t*)(outh + (size_t)(r0+8) * N + gc) = pack_h2(v1.x, v1.y);
            } else {  // EPI == 3
                float2 ra2 = *(const float2*)(resid + (size_t)r0 * N + gc);
                float2 rb2 = *(const float2*)(resid + (size_t)(r0+8) * N + gc);
                v0.x += ra2.x; v0.y += ra2.y; v1.x += rb2.x; v1.y += rb2.y;
                *(float2*)(outf + (size_t)r0 * N + gc) = v0;
                *(float2*)(outf + (size_t)(r0+8) * N + gc) = v1;
            }
        }
    }
}

// ================= head GEMM: 3-pass, 128x128 block =================
#define GSTG3 65536u
#define GEMM_SMEM3 (3*65536)

__global__ void __launch_bounds__(256, 1) gemm_head(
    const __half* __restrict__ Ah, const __half* __restrict__ Al,
    const __half* __restrict__ Wh, const __half* __restrict__ Wl,
    float* __restrict__ outf, int N, int K)
{
    extern __shared__ char sm[];
    const uint32_t sb = smem_u32(sm);
    const int t = threadIdx.x, w = t >> 5, lane = t & 31;
    const int bm = blockIdx.y, bn = blockIdx.x;
    const int wm = w & 3, wn = w >> 2;

    const int crow = t >> 1, chalf = t & 1;
    const __half* agh = Ah + (size_t)(bm*128 + crow) * K + chalf*32;
    const __half* agl = Al + (size_t)(bm*128 + crow) * K + chalf*32;
    const __half* bgh = Wh + (size_t)(bn*128 + crow) * K + chalf*32;
    const __half* bgl = Wl + (size_t)(bn*128 + crow) * K + chalf*32;
    uint32_t dsto[4];
    #pragma unroll
    for (int i = 0; i < 4; i++) {
        int c16 = chalf*4 + i;
        dsto[i] = (uint32_t)(crow*128 + ((c16 ^ (crow & 7)) << 4));
    }
    auto load_stage = [&](int c, int slot) {
        const uint32_t s0 = sb + (uint32_t)slot * GSTG3;
        #pragma unroll
        for (int i = 0; i < 4; i++) CP_ASYNC16(s0 + dsto[i],          agh + c*64 + i*8);
        #pragma unroll
        for (int i = 0; i < 4; i++) CP_ASYNC16(s0 + 16384u + dsto[i], agl + c*64 + i*8);
        #pragma unroll
        for (int i = 0; i < 4; i++) CP_ASYNC16(s0 + 32768u + dsto[i], bgh + c*64 + i*8);
        #pragma unroll
        for (int i = 0; i < 4; i++) CP_ASYNC16(s0 + 49152u + dsto[i], bgl + c*64 + i*8);
    };

    const int ra = lane & 15, ca = lane >> 4;
    const int rb = (lane & 7) + ((lane >> 4) << 3), cb = (lane >> 3) & 1;
    const int xr = lane & 7;
    const uint32_t aro = (uint32_t)((wm*32 + ra) * 128);
    const uint32_t bro = (uint32_t)((wn*64 + rb) * 128);

    float acc[2][8][4];
    #pragma unroll
    for (int i = 0; i < 2; i++)
        #pragma unroll
        for (int j = 0; j < 8; j++)
            #pragma unroll
            for (int r = 0; r < 4; r++) acc[i][j][r] = 0.f;

    load_stage(0, 0); CP_COMMIT;
    load_stage(1, 1); CP_COMMIT;

    const int NC = K >> 6;
    int slot = 0;
    for (int c = 0; c < NC; c++) {
        CP_WAIT(1);
        __syncthreads();
        if (c + 2 < NC) {
            int ns = slot + 2; if (ns >= 3) ns -= 3;
            load_stage(c + 2, ns);
        }
        CP_COMMIT;
        const uint32_t st = sb + (uint32_t)slot * GSTG3;
        #pragma unroll
        for (int ks = 0; ks < 4; ks++) {
            const uint32_t kca = (uint32_t)(((ks*2 + ca) ^ xr) << 4);
            const uint32_t kcb = (uint32_t)(((ks*2 + cb) ^ xr) << 4);
            uint32_t ah[2][4], al4[2][4], bh[4][4], bl4[4][4];
            #pragma unroll
            for (int mt = 0; mt < 2; mt++) {
                ldsm4(ah[mt],  st + aro + mt*2048u + kca);
                ldsm4(al4[mt], st + 16384u + aro + mt*2048u + kca);
            }
            #pragma unroll
            for (int nq = 0; nq < 4; nq++) {
                ldsm4(bh[nq],  st + 32768u + bro + nq*2048u + kcb);
                ldsm4(bl4[nq], st + 49152u + bro + nq*2048u + kcb);
            }
            #pragma unroll
            for (int mt = 0; mt < 2; mt++)
                #pragma unroll
                for (int nt = 0; nt < 8; nt++) {
                    const int nq = nt >> 1, s2 = (nt & 1) * 2;
                    mma16816(acc[mt][nt], ah[mt], bh[nq][s2], bh[nq][s2+1]);
                }
            #pragma unroll
            for (int mt = 0; mt < 2; mt++)
                #pragma unroll
                for (int nt = 0; nt < 8; nt++) {
                    const int nq = nt >> 1, s2 = (nt & 1) * 2;
                    mma16816(acc[mt][nt], ah[mt], bl4[nq][s2], bl4[nq][s2+1]);
                }
            #pragma unroll
            for (int mt = 0; mt < 2; mt++)
                #pragma unroll
                for (int nt = 0; nt < 8; nt++) {
                    const int nq = nt >> 1, s2 = (nt & 1) * 2;
                    mma16816(acc[mt][nt], al4[mt], bh[nq][s2], bh[nq][s2+1]);
                }
        }
        slot = (slot + 1 == 3) ? 0 : slot + 1;
    }

    const int grbase = bm*128 + wm*32;
    const int gcbase = bn*128 + wn*64;
    #pragma unroll
    for (int mt = 0; mt < 2; mt++) {
        const int r0 = grbase + mt*16 + (lane >> 2);
        #pragma unroll
        for (int nt = 0; nt < 8; nt++) {
            const int gc = gcbase + nt*8 + (lane & 3)*2;
            *(float2*)(outf + (size_t)r0 * N + gc) =
                make_float2(acc[mt][nt][0], acc[mt][nt][1]);
            *(float2*)(outf + (size_t)(r0+8) * N + gc) =
                make_float2(acc[mt][nt][2], acc[mt][nt][3]);
        }
    }
}

// ================= flash attention: Q tile 256, 64x64 warp tile =================
// (unchanged from round 10)
#define ASTG 32768
#define AQSZ 32768
#define ATT_SMEM (AQSZ + 3*ASTG)

__global__ void __launch_bounds__(256, 1) attn_h(
    const __half* __restrict__ qkvh, const __half* __restrict__ qkvl,
    __half* __restrict__ yh)
{
    extern __shared__ char sm[];
    const uint32_t sb = smem_u32(sm);
    const int t = threadIdx.x, w = t >> 5, lane = t & 31;
    const int bhx = blockIdx.y, b = bhx >> 4, h = bhx & 15;
    const int q0 = blockIdx.x * 256;
    const size_t MC = (size_t)M_ * C_;
    const int NT = T_ / 64;   // 32 tiles

    const __half* qgh = qkvh + (size_t)(b*T_ + q0) * C_ + h*64;
    const __half* kgh = qkvh + MC   + (size_t)(b*T_) * C_ + h*64;
    const __half* kgl = qkvl + MC   + (size_t)(b*T_) * C_ + h*64;
    const __half* vgh = qkvh + 2*MC + (size_t)(b*T_) * C_ + h*64;
    const __half* vgl = qkvl + 2*MC + (size_t)(b*T_) * C_ + h*64;

    // Q loads (hi only): each thread loads one full row (8 x 16B)
    {
        const int qr = t;
        const __half* qrow = qgh + (size_t)qr * C_;
        #pragma unroll
        for (int i = 0; i < 8; i++) {
            const uint32_t d = (uint32_t)(qr*128 + ((i ^ (qr & 7)) << 4));
            CP_ASYNC16(sb + d, qrow + i*8);
        }
    }
    CP_COMMIT;

    // KV stage loader
    const int kr = t >> 2, kc2 = (t & 3) * 2;
    auto load_kv = [&](int kt, int slot) {
        const uint32_t s0 = sb + AQSZ + (uint32_t)slot * ASTG;
        const size_t rowoff = (size_t)(kt*64 + kr) * C_;
        #pragma unroll
        for (int i = 0; i < 2; i++) {
            const int c16 = kc2 + i;
            const uint32_t d = (uint32_t)(kr*128 + ((c16 ^ (kr & 7)) << 4));
            CP_ASYNC16(s0 + d,          kgh + rowoff + c16*8);
            CP_ASYNC16(s0 + 8192u + d,  kgl + rowoff + c16*8);
            CP_ASYNC16(s0 + 16384u + d, vgh + rowoff + c16*8);
            CP_ASYNC16(s0 + 24576u + d, vgl + rowoff + c16*8);
        }
    };
    load_kv(0, 0); CP_COMMIT;
    load_kv(1, 1); CP_COMMIT;

    const int ra = lane & 15, ca = lane >> 4;
    const int rb = (lane & 7) + ((lane >> 4) << 3), cb = (lane >> 3) & 1;
    const int rv = (lane & 7) + (((lane >> 3) & 1) << 3), cv = lane >> 4;
    const int xr = lane & 7;

    CP_WAIT(2);           // Q landed
    __syncthreads();
    uint32_t qh4[4][2][4];   // [ks][mt][regs]
    {
        #pragma unroll
        for (int mt = 0; mt < 2; mt++) {
            const uint32_t qro = (uint32_t)((w*32 + mt*16 + ra) * 128);
            #pragma unroll
            for (int ks = 0; ks < 4; ks++) {
                const uint32_t off = qro + (uint32_t)(((ks*2 + ca) ^ xr) << 4);
                ldsm4(qh4[ks][mt], sb + off);
            }
        }
    }

    float o_[2][8][4];
    #pragma unroll
    for (int mt = 0; mt < 2; mt++)
        #pragma unroll
        for (int i = 0; i < 8; i++)
            #pragma unroll
            for (int j = 0; j < 4; j++) o_[mt][i][j] = 0.f;
    float m_a[2] = {-1e30f, -1e30f}, m_b[2] = {-1e30f, -1e30f};
    float l_a[2] = {0.f, 0.f},       l_b[2] = {0.f, 0.f};

    int slot = 0;
    for (int kt = 0; kt < NT; kt++) {
        CP_WAIT(1);
        __syncthreads();
        if (kt + 2 < NT) {
            int ns = slot + 2; if (ns >= 3) ns -= 3;
            load_kv(kt + 2, ns);
        }
        CP_COMMIT;
        const uint32_t st = sb + AQSZ + (uint32_t)slot * ASTG;

        // ---- S = qh·(kh + kl) (2-pass), warp tile 32x64 ----
        float sc[2][8][4];
        #pragma unroll
        for (int mt = 0; mt < 2; mt++)
            #pragma unroll
            for (int i = 0; i < 8; i++)
                #pragma unroll
                for (int j = 0; j < 4; j++) sc[mt][i][j] = 0.f;
        #pragma unroll
        for (int ks = 0; ks < 4; ks++) {
            uint32_t kh4[4][4], kl4[4][4];
            #pragma unroll
            for (int nq = 0; nq < 4; nq++) {
                const uint32_t off = (uint32_t)((nq*16 + rb) * 128)
                                   + (uint32_t)(((ks*2 + cb) ^ xr) << 4);
                ldsm4(kh4[nq], st + off);
                ldsm4(kl4[nq], st + 8192u + off);
            }
            #pragma unroll
            for (int mt = 0; mt < 2; mt++)
                #pragma unroll
                for (int nt = 0; nt < 8; nt++) {
                    const int nq = nt >> 1, s2 = (nt & 1) * 2;
                    mma16816(sc[mt][nt], qh4[ks][mt], kh4[nq][s2], kh4[nq][s2+1]);
                }
            #pragma unroll
            for (int mt = 0; mt < 2; mt++)
                #pragma unroll
                for (int nt = 0; nt < 8; nt++) {
                    const int nq = nt >> 1, s2 = (nt & 1) * 2;
                    mma16816(sc[mt][nt], qh4[ks][mt], kl4[nq][s2], kl4[nq][s2+1]);
                }
        }

        // ---- online softmax (base-2), per mt tile ----
        #pragma unroll
        for (int mt = 0; mt < 2; mt++) {
            float mxa = -1e30f, mxb = -1e30f;
            #pragma unroll
            for (int nt = 0; nt < 8; nt++) {
                mxa = fmaxf(mxa, fmaxf(sc[mt][nt][0], sc[mt][nt][1]));
                mxb = fmaxf(mxb, fmaxf(sc[mt][nt][2], sc[mt][nt][3]));
            }
            mxa = fmaxf(mxa, __shfl_xor_sync(0xffffffffu, mxa, 1));
            mxa = fmaxf(mxa, __shfl_xor_sync(0xffffffffu, mxa, 2));
            mxb = fmaxf(mxb, __shfl_xor_sync(0xffffffffu, mxb, 1));
            mxb = fmaxf(mxb, __shfl_xor_sync(0xffffffffu, mxb, 2));
            const float nma = fmaxf(m_a[mt], mxa), nmb = fmaxf(m_b[mt], mxb);
            const float cfa = fex2(m_a[mt] - nma), cfb = fex2(m_b[mt] - nmb);
            m_a[mt] = nma; m_b[mt] = nmb;
            float rsa = 0.f, rsb = 0.f;
            #pragma unroll
            for (int nt = 0; nt < 8; nt++) {
                sc[mt][nt][0] = fex2(sc[mt][nt][0] - nma); rsa += sc[mt][nt][0];
                sc[mt][nt][1] = fex2(sc[mt][nt][1] - nma); rsa += sc[mt][nt][1];
                sc[mt][nt][2] = fex2(sc[mt][nt][2] - nmb); rsb += sc[mt][nt][2];
                sc[mt][nt][3] = fex2(sc[mt][nt][3] - nmb); rsb += sc[mt][nt][3];
            }
            rsa += __shfl_xor_sync(0xffffffffu, rsa, 1);
            rsa += __shfl_xor_sync(0xffffffffu, rsa, 2);
            rsb += __shfl_xor_sync(0xffffffffu, rsb, 1);
            rsb += __shfl_xor_sync(0xffffffffu, rsb, 2);
            l_a[mt] = l_a[mt] * cfa + rsa;
            l_b[mt] = l_b[mt] * cfb + rsb;
            #pragma unroll
            for (int dt = 0; dt < 8; dt++) {
                o_[mt][dt][0] *= cfa; o_[mt][dt][1] *= cfa;
                o_[mt][dt][2] *= cfb; o_[mt][dt][3] *= cfb;
            }
        }

        // ---- O += ph·(vh + vl) (2-pass) ----
        #pragma unroll
        for (int ks = 0; ks < 4; ks++) {
            uint32_t ph[2][4];
            #pragma unroll
            for (int mt = 0; mt < 2; mt++) {
                ph[mt][0] = pack_h2(sc[mt][2*ks][0],   sc[mt][2*ks][1]);
                ph[mt][1] = pack_h2(sc[mt][2*ks][2],   sc[mt][2*ks][3]);
                ph[mt][2] = pack_h2(sc[mt][2*ks+1][0], sc[mt][2*ks+1][1]);
                ph[mt][3] = pack_h2(sc[mt][2*ks+1][2], sc[mt][2*ks+1][3]);
            }
            uint32_t vh4[4][4], vl4[4][4];
            #pragma unroll
            for (int nq = 0; nq < 4; nq++) {
                const uint32_t off = (uint32_t)((ks*16 + rv) * 128)
                                   + (uint32_t)(((nq*2 + cv) ^ xr) << 4);
                ldsm4t(vh4[nq], st + 16384u + off);
                ldsm4t(vl4[nq], st + 24576u + off);
            }
            #pragma unroll
            for (int mt = 0; mt < 2; mt++)
                #pragma unroll
                for (int dt = 0; dt < 8; dt++) {
                    const int nq = dt >> 1, s2 = (dt & 1) * 2;
                    mma16816(o_[mt][dt], ph[mt], vh4[nq][s2], vh4[nq][s2+1]);
                }
            #pragma unroll
            for (int mt = 0; mt < 2; mt++)
                #pragma unroll
                for (int dt = 0; dt < 8; dt++) {
                    const int nq = dt >> 1, s2 = (dt & 1) * 2;
                    mma16816(o_[mt][dt], ph[mt], vl4[nq][s2], vl4[nq][s2+1]);
                }
        }
        slot = (slot + 1 == 3) ? 0 : slot + 1;
    }

    // ---- write y (fp16 hi only) ----
    #pragma unroll
    for (int mt = 0; mt < 2; mt++) {
        const float ia = 1.f / l_a[mt], ib = 1.f / l_b[mt];
        const int r0 = q0 + w*32 + mt*16 + (lane >> 2);
        __half* ybh = yh + (size_t)(b*T_ + r0) * C_ + h*64;
        #pragma unroll
        for (int dt = 0; dt < 8; dt++) {
            const int gc = dt*8 + (lane & 3)*2;
            *(uint32_t*)(ybh + gc)                = pack_h2(o_[mt][dt][0]*ia, o_[mt][dt][1]*ia);
            *(uint32_t*)(ybh + (size_t)8*C_ + gc) = pack_h2(o_[mt][dt][2]*ib, o_[mt][dt][3]*ib);
        }
    }
}

// ================= orchestration =================
extern "C" void kernel_launch(void* const* d_in, const int* in_sizes, int n_in,
                              void* d_out, int out_size)
{
    const float* seq  = (const float*)d_in[0];
    const float* pos  = (const float*)d_in[1];
    const float* Wq   = (const float*)d_in[2];
    const float* bq   = (const float*)d_in[3];
    const float* Wk   = (const float*)d_in[4];
    const float* bk   = (const float*)d_in[5];
    const float* Wv   = (const float*)d_in[6];
    const float* bv   = (const float*)d_in[7];
    const float* Wo   = (const float*)d_in[8];
    const float* bo   = (const float*)d_in[9];
    const float* ln1w = (const float*)d_in[10];
    const float* ln1b = (const float*)d_in[11];
    const float* ln2w = (const float*)d_in[12];
    const float* ln2b = (const float*)d_in[13];
    const float* W1   = (const float*)d_in[14];
    const float* b1   = (const float*)d_in[15];
    const float* W2   = (const float*)d_in[16];
    const float* b2   = (const float*)d_in[17];
    const float* lnfw = (const float*)d_in[18];
    const float* lnfb = (const float*)d_in[19];
    const float* Wh   = (const float*)d_in[20];
    float* out = (float*)d_out;

    float *px, *pbqkv;
    __half *phh, *phl, *pqkvh, *pqkvl, *pyh, *puh, *pwh, *pwl;
    cudaGetSymbolAddress((void**)&px, g_x);
    cudaGetSymbolAddress((void**)&phh, g_hh);
    cudaGetSymbolAddress((void**)&phl, g_hl);
    cudaGetSymbolAddress((void**)&pqkvh, g_qkvh);
    cudaGetSymbolAddress((void**)&pqkvl, g_qkvl);
    cudaGetSymbolAddress((void**)&pyh, g_yh);
    cudaGetSymbolAddress((void**)&puh, g_uh);
    cudaGetSymbolAddress((void**)&pwh, g_wh);
    cudaGetSymbolAddress((void**)&pwl, g_wl);
    cudaGetSymbolAddress((void**)&pbqkv, g_bqkv);

    cudaFuncSetAttribute(attn_h, cudaFuncAttributeMaxDynamicSharedMemorySize, ATT_SMEM);
    cudaFuncSetAttribute((gemm_h2<1>), cudaFuncAttributeMaxDynamicSharedMemorySize, GEMM_SMEM2);
    cudaFuncSetAttribute((gemm_h2<2>), cudaFuncAttributeMaxDynamicSharedMemorySize, GEMM_SMEM2);
    cudaFuncSetAttribute((gemm_h2<3>), cudaFuncAttributeMaxDynamicSharedMemorySize, GEMM_SMEM2);
    cudaFuncSetAttribute(gemm_head, cudaFuncAttributeMaxDynamicSharedMemorySize, GEMM_SMEM3);

    // ---- weight conversion: ONE launch ----
    conv_all<<<(int)(WTOT / 2048), 256>>>(Wq, Wk, Wv, Wo, W1, W2, Wh, pwh, pwl);
    packqkvb<<<L_*3*C_/256, 256>>>(bq, bk, bv, pbqkv);
    addpos_kernel<<<M_ * C_ / 4 / 256, 256>>>(seq, pos, px);

    dim3 gQKV(3*C_ / 128, M_ / 256);   // (24, 32)
    dim3 gC(C_ / 128, M_ / 256);       // (8, 32)
    dim3 gF(FF_ / 128, M_ / 256);      // (32, 32)
    dim3 gA(T_ / 256, B_ * H_);        // (8, 64)
    dim3 gHead(OUT_ / 128, M_ / 128);  // (8, 64)

    for (int l = 0; l < L_; l++) {
        const size_t wl = (size_t)l * WPL_;
        ln_split<<<M_, 256>>>(px, ln1w + l*C_, ln1b + l*C_, phh, nullptr);
        gemm_h2<1><<<gQKV, 256, GEMM_SMEM2>>>(phh, pwh + wl,
            pbqkv + l*3*C_, nullptr, nullptr, pqkvh, pqkvl, 3*C_, C_);
        attn_h<<<gA, 256, ATT_SMEM>>>(pqkvh, pqkvl, pyh);
        gemm_h2<3><<<gC, 256, GEMM_SMEM2>>>(pyh, pwh + wl + WOFF_WO,
            bo + l*C_, px, px, nullptr, nullptr, C_, C_);
        ln_split<<<M_, 256>>>(px, ln2w + l*C_, ln2b + l*C_, phh, nullptr);
        gemm_h2<2><<<gF, 256, GEMM_SMEM2>>>(phh, pwh + wl + WOFF_W1,
            b1 + l*FF_, nullptr, nullptr, puh, nullptr, FF_, C_);
        gemm_h2<3><<<gC, 256, GEMM_SMEM2>>>(puh, pwh + wl + WOFF_W2,
            b2 + l*C_, px, px, nullptr, nullptr, C_, FF_);
    }

    // final LN needs lo for the 3-pass head GEMM
    ln_split<<<M_, 256>>>(px, lnfw, lnfb, phh, phl);
    gemm_head<<<gHead, 256, GEMM_SMEM3>>>(phh, phl, pwh + WHEAD_OFF, pwl + WHEAD_OFF,
        out, OUT_, C_);
}

// round 12
// speedup vs baseline: 6.6031x; 1.1471x over previous
#include <cuda_runtime.h>
#include <cuda_fp16.h>
#include <math.h>
#include <stdint.h>

#define L_ 8
#define H_ 16
#define T_ 2048
#define C_ 1024
#define OUT_ 1024
#define B_ 4
#define DH_ 64
#define FF_ 4096
#define M_ (B_*T_)   // 8192 rows

#define CC_ (C_*C_)                   // 1048576
#define WPL_ (12*CC_)                 // weights per layer (halves)
#define WOFF_WO  (3*CC_)
#define WOFF_W1  (4*CC_)
#define WOFF_W2  (8*CC_)
#define WHEAD_OFF ((size_t)L_*WPL_)   // 100663296
#define WTOT (WHEAD_OFF + CC_)        // 101711872

// q pre-scale: 0.125 (1/sqrt(DH)) * log2(e) -> softmax in base-2 domain
#define QSCALE 0.1803368801111204f

// ---------------- scratch (static device globals) ----------------
__device__ float g_x[M_*C_];
__device__ __align__(16) __half g_hh[M_*C_],  g_hl[M_*C_];
__device__ __align__(16) __half g_qkvh[3*M_*C_];
__device__ __align__(16) __half g_yh[M_*C_];
__device__ __align__(16) __half g_uh[(size_t)M_*FF_];
__device__ __align__(16) __half g_wh[WTOT],   g_wl[WTOT];
__device__ float g_bqkv[L_*3*C_];

// ================= helpers =================
__device__ __forceinline__ uint32_t smem_u32(const void* p) {
    uint32_t a;
    asm("{ .reg .u64 t; cvta.to.shared.u64 t, %1; cvt.u32.u64 %0, t; }" : "=r"(a) : "l"(p));
    return a;
}
__device__ __forceinline__ void mma16816(float* c, const uint32_t* a, uint32_t b0, uint32_t b1) {
    asm volatile(
        "mma.sync.aligned.m16n8k16.row.col.f32.f16.f16.f32 "
        "{%0,%1,%2,%3}, {%4,%5,%6,%7}, {%8,%9}, {%0,%1,%2,%3};"
        : "+f"(c[0]), "+f"(c[1]), "+f"(c[2]), "+f"(c[3])
        : "r"(a[0]), "r"(a[1]), "r"(a[2]), "r"(a[3]), "r"(b0), "r"(b1));
}
__device__ __forceinline__ void ldsm4(uint32_t* r, uint32_t addr) {
    asm volatile("ldmatrix.sync.aligned.m8n8.x4.shared.b16 {%0,%1,%2,%3}, [%4];"
                 : "=r"(r[0]), "=r"(r[1]), "=r"(r[2]), "=r"(r[3]) : "r"(addr));
}
__device__ __forceinline__ void ldsm4t(uint32_t* r, uint32_t addr) {
    asm volatile("ldmatrix.sync.aligned.m8n8.x4.trans.shared.b16 {%0,%1,%2,%3}, [%4];"
                 : "=r"(r[0]), "=r"(r[1]), "=r"(r[2]), "=r"(r[3]) : "r"(addr));
}
#define CP_ASYNC16(dst, src) \
    asm volatile("cp.async.cg.shared.global [%0], [%1], 16;" :: "r"(dst), "l"(src))
#define CP_COMMIT asm volatile("cp.async.commit_group;" ::: "memory")
#define CP_WAIT(n) asm volatile("cp.async.wait_group %0;" :: "n"(n) : "memory")

__device__ __forceinline__ float fex2(float x) {
    float y;
    asm("ex2.approx.f32 %0, %1;" : "=f"(y) : "f"(x));
    return y;
}
__device__ __forceinline__ void split2(float x, float y, uint32_t& h, uint32_t& l) {
    __half2 hh = __floats2half2_rn(x, y);
    float2 hf = __half22float2(hh);
    __half2 ll = __floats2half2_rn(x - hf.x, y - hf.y);
    h = *(uint32_t*)&hh;
    l = *(uint32_t*)&ll;
}
__device__ __forceinline__ uint32_t pack_h2(float x, float y) {
    __half2 hh = __floats2half2_rn(x, y);
    return *(uint32_t*)&hh;
}
__device__ __forceinline__ float gelu_exact(float v) {
    return 0.5f * v * (1.0f + erff(v * 0.70710678118654752f));
}

// ================= fused weight conversion (single launch) =================
// hi for everything; lo only for the head weights (only 3-pass consumer).
__global__ void __launch_bounds__(256) conv_all(
    const float* __restrict__ Wq, const float* __restrict__ Wk,
    const float* __restrict__ Wv, const float* __restrict__ Wo,
    const float* __restrict__ W1, const float* __restrict__ W2,
    const float* __restrict__ Whd,
    __half* __restrict__ dh, __half* __restrict__ dl)
{
    const size_t i = ((size_t)blockIdx.x * 256 + threadIdx.x) * 8;
    const float* src;
    if (i >= WHEAD_OFF) {
        src = Whd + (i - WHEAD_OFF);
    } else {
        const int l = (int)(i / WPL_);
        const size_t r = i % WPL_;
        if      (r <   (size_t)CC_)   src = Wq + (size_t)l*CC_   + r;
        else if (r < 2*(size_t)CC_)   src = Wk + (size_t)l*CC_   + (r -   CC_);
        else if (r < 3*(size_t)CC_)   src = Wv + (size_t)l*CC_   + (r - 2*CC_);
        else if (r < 4*(size_t)CC_)   src = Wo + (size_t)l*CC_   + (r - 3*CC_);
        else if (r < 8*(size_t)CC_)   src = W1 + (size_t)l*4*CC_ + (r - 4*CC_);
        else                          src = W2 + (size_t)l*4*CC_ + (r - 8*CC_);
    }
    float4 a = *(const float4*)(src), b = *(const float4*)(src + 4);
    uint32_t h[4], l4[4];
    split2(a.x, a.y, h[0], l4[0]); split2(a.z, a.w, h[1], l4[1]);
    split2(b.x, b.y, h[2], l4[2]); split2(b.z, b.w, h[3], l4[3]);
    *(uint4*)(dh + i) = make_uint4(h[0], h[1], h[2], h[3]);
    if (i >= WHEAD_OFF)
        *(uint4*)(dl + i) = make_uint4(l4[0], l4[1], l4[2], l4[3]);
}
__global__ void __launch_bounds__(256) packqkvb(
    const float* __restrict__ bq, const float* __restrict__ bk,
    const float* __restrict__ bv, float* __restrict__ dst)
{
    int idx = blockIdx.x * 256 + threadIdx.x;      // L_*3072
    int l = idx / 3072, c = idx % 3072;
    float v = (c < 1024) ? bq[l*1024 + c] : (c < 2048) ? bk[l*1024 + c - 1024]
                                                        : bv[l*1024 + c - 2048];
    dst[idx] = v;
}

// ================= x = seq + pos =================
__global__ void __launch_bounds__(256) addpos_kernel(
    const float* __restrict__ seq, const float* __restrict__ pos, float* __restrict__ x)
{
    int i = blockIdx.x * 256 + threadIdx.x;
    float4 s = ((const float4*)seq)[i];
    float4 p = ((const float4*)pos)[i & (T_*C_/4 - 1)];
    s.x += p.x; s.y += p.y; s.z += p.z; s.w += p.w;
    ((float4*)x)[i] = s;
}

// ================= LayerNorm -> fp16 hi (+ optional lo) =================
__global__ void __launch_bounds__(256) ln_split(
    const float* __restrict__ x, const float* __restrict__ w,
    const float* __restrict__ b, __half* __restrict__ outh, __half* __restrict__ outl)
{
    const int row = blockIdx.x;
    const int t = threadIdx.x;
    const float4 v = *(const float4*)(x + (size_t)row * C_ + t * 4);
    float s  = v.x + v.y + v.z + v.w;
    float sq = v.x*v.x + v.y*v.y + v.z*v.z + v.w*v.w;
    #pragma unroll
    for (int off = 16; off; off >>= 1) {
        s  += __shfl_xor_sync(0xffffffffu, s,  off);
        sq += __shfl_xor_sync(0xffffffffu, sq, off);
    }
    __shared__ float rs_[8], rq_[8];
    if ((t & 31) == 0) { rs_[t >> 5] = s; rq_[t >> 5] = sq; }
    __syncthreads();
    s = 0.f; sq = 0.f;
    #pragma unroll
    for (int i = 0; i < 8; i++) { s += rs_[i]; sq += rq_[i]; }
    const float mu   = s * (1.0f / 1024.0f);
    const float var  = sq * (1.0f / 1024.0f) - mu * mu;
    const float rstd = rsqrtf(var + 1e-5f);
    const float4 wv = *(const float4*)(w + t * 4);
    const float4 bv = *(const float4*)(b + t * 4);
    float ox = (v.x - mu) * rstd * wv.x + bv.x;
    float oy = (v.y - mu) * rstd * wv.y + bv.y;
    float oz = (v.z - mu) * rstd * wv.z + bv.z;
    float ow = (v.w - mu) * rstd * wv.w + bv.w;
    uint32_t h0, l0, h1, l1;
    split2(ox, oy, h0, l0);
    split2(oz, ow, h1, l1);
    *(uint2*)(outh + (size_t)row * C_ + t * 4) = make_uint2(h0, h1);
    if (outl) *(uint2*)(outl + (size_t)row * C_ + t * 4) = make_uint2(l0, l1);
}

// ================= 1-pass fp16 GEMM, 256x128 block, 64x64 warp tile =================
// D[M,N] = A_hi[M,K] @ W_hi[N,K]^T. 3-stage cp.async.
// Stage 48KB: Ah[256x64]@0 (32K), Bh[128x64]@32K (16K).
#define GSTG2 49152u
#define GEMM_SMEM2 (3*49152)

template <int EPI>
__global__ void __launch_bounds__(256, 1) gemm_h2(
    const __half* __restrict__ Ah,
    const __half* __restrict__ Wh,
    const float* __restrict__ bias, const float* __restrict__ resid,
    float* __restrict__ outf, __half* __restrict__ outh,
    int N, int K)
{
    extern __shared__ char sm[];
    const uint32_t sb = smem_u32(sm);
    const int t = threadIdx.x, w = t >> 5, lane = t & 31;
    const int bm = blockIdx.y, bn = blockIdx.x;
    const int wm = w & 3, wn = w >> 2;

    const int crow = t >> 1, chalf = t & 1;
    const __half* agh = Ah + (size_t)(bm*256 + crow) * K + chalf*32;
    const __half* bgh = Wh + (size_t)(bn*128 + crow) * K + chalf*32;
    uint32_t dsto[4];
    #pragma unroll
    for (int i = 0; i < 4; i++) {
        int c16 = chalf*4 + i;
        dsto[i] = (uint32_t)(crow*128 + ((c16 ^ (crow & 7)) << 4));
    }
    auto load_stage = [&](int c, int slot) {
        const uint32_t s0 = sb + (uint32_t)slot * GSTG2;
        const __half* a0 = agh + c*64;
        const __half* b0 = bgh + c*64;
        #pragma unroll
        for (int i = 0; i < 4; i++) CP_ASYNC16(s0 + dsto[i],           a0 + i*8);
        #pragma unroll
        for (int i = 0; i < 4; i++) CP_ASYNC16(s0 + 16384u + dsto[i],  a0 + (size_t)128*K + i*8);
        #pragma unroll
        for (int i = 0; i < 4; i++) CP_ASYNC16(s0 + 32768u + dsto[i],  b0 + i*8);
    };

    const int ra = lane & 15, ca = lane >> 4;
    const int rb = (lane & 7) + ((lane >> 4) << 3), cb = (lane >> 3) & 1;
    const int xr = lane & 7;
    const uint32_t aro = (uint32_t)((wm*64 + ra) * 128);
    const uint32_t bro = (uint32_t)((wn*64 + rb) * 128);

    float acc[4][8][4];
    #pragma unroll
    for (int i = 0; i < 4; i++)
        #pragma unroll
        for (int j = 0; j < 8; j++)
            #pragma unroll
            for (int r = 0; r < 4; r++) acc[i][j][r] = 0.f;

    load_stage(0, 0); CP_COMMIT;
    load_stage(1, 1); CP_COMMIT;

    const int NC = K >> 6;
    int slot = 0;
    for (int c = 0; c < NC; c++) {
        CP_WAIT(1);
        __syncthreads();
        if (c + 2 < NC) {
            int ns = slot + 2; if (ns >= 3) ns -= 3;
            load_stage(c + 2, ns);
        }
        CP_COMMIT;
        const uint32_t st = sb + (uint32_t)slot * GSTG2;
        #pragma unroll
        for (int ks = 0; ks < 4; ks++) {
            const uint32_t kca = (uint32_t)(((ks*2 + ca) ^ xr) << 4);
            const uint32_t kcb = (uint32_t)(((ks*2 + cb) ^ xr) << 4);
            uint32_t ah[4][4], bh[4][4];
            #pragma unroll
            for (int mt = 0; mt < 4; mt++)
                ldsm4(ah[mt], st + aro + mt*2048u + kca);
            #pragma unroll
            for (int nq = 0; nq < 4; nq++)
                ldsm4(bh[nq], st + 32768u + bro + nq*2048u + kcb);
            #pragma unroll
            for (int mt = 0; mt < 4; mt++)
                #pragma unroll
                for (int nt = 0; nt < 8; nt++) {
                    const int nq = nt >> 1, s2 = (nt & 1) * 2;
                    mma16816(acc[mt][nt], ah[mt], bh[nq][s2], bh[nq][s2+1]);
                }
        }
        slot = (slot + 1 == 3) ? 0 : slot + 1;
    }

    // ---- epilogue ----
    const int grbase = bm*256 + wm*64;
    const int gcbase = bn*128 + wn*64;
    #pragma unroll
    for (int mt = 0; mt < 4; mt++) {
        const int r0 = grbase + mt*16 + (lane >> 2);
        #pragma unroll
        for (int nt = 0; nt < 8; nt++) {
            const int gc = gcbase + nt*8 + (lane & 3)*2;
            float2 v0 = make_float2(acc[mt][nt][0], acc[mt][nt][1]);
            float2 v1 = make_float2(acc[mt][nt][2], acc[mt][nt][3]);
            {
                float2 bb = *(const float2*)(bias + gc);
                v0.x += bb.x; v0.y += bb.y; v1.x += bb.x; v1.y += bb.y;
            }
            if (EPI == 1) {
                const int third = gc >> 10, lc = gc & 1023;
                __half* oh = outh + (size_t)third * ((size_t)M_ * C_);
                if (third == 0) {
                    v0.x *= QSCALE; v0.y *= QSCALE; v1.x *= QSCALE; v1.y *= QSCALE;
                }
                *(uint32_t*)(oh + (size_t)r0 * 1024 + lc)     = pack_h2(v0.x, v0.y);
                *(uint32_t*)(oh + (size_t)(r0+8) * 1024 + lc) = pack_h2(v1.x, v1.y);
            } else if (EPI == 2) {
                v0.x = gelu_exact(v0.x); v0.y = gelu_exact(v0.y);
                v1.x = gelu_exact(v1.x); v1.y = gelu_exact(v1.y);
                *(uint32_t*)(outh + (size_t)r0 * N + gc)     = pack_h2(v0.x, v0.y);
                *(uint32_t*)(outh + (size_t)(r0+8) * N + gc) = pack_h2(v1.x, v1.y);
            } else {  // EPI == 3
                float2 ra2 = *(const float2*)(resid + (size_t)r0 * N + gc);
                float2 rb2 = *(const float2*)(resid + (size_t)(r0+8) * N + gc);
                v0.x += ra2.x; v0.y += ra2.y; v1.x += rb2.x; v1.y += rb2.y;
                *(float2*)(outf + (size_t)r0 * N + gc) = v0;
                *(float2*)(outf + (size_t)(r0+8) * N + gc) = v1;
            }
        }
    }
}

// ================= head GEMM: 3-pass, 128x128 block =================
#define GSTG3 65536u
#define GEMM_SMEM3 (3*65536)

__global__ void __launch_bounds__(256, 1) gemm_head(
    const __half* __restrict__ Ah, const __half* __restrict__ Al,
    const __half* __restrict__ Wh, const __half* __restrict__ Wl,
    float* __restrict__ outf, int N, int K)
{
    extern __shared__ char sm[];
    const uint32_t sb = smem_u32(sm);
    const int t = threadIdx.x, w = t >> 5, lane = t & 31;
    const int bm = blockIdx.y, bn = blockIdx.x;
    const int wm = w & 3, wn = w >> 2;

    const int crow = t >> 1, chalf = t & 1;
    const __half* agh = Ah + (size_t)(bm*128 + crow) * K + chalf*32;
    const __half* agl = Al + (size_t)(bm*128 + crow) * K + chalf*32;
    const __half* bgh = Wh + (size_t)(bn*128 + crow) * K + chalf*32;
    const __half* bgl = Wl + (size_t)(bn*128 + crow) * K + chalf*32;
    uint32_t dsto[4];
    #pragma unroll
    for (int i = 0; i < 4; i++) {
        int c16 = chalf*4 + i;
        dsto[i] = (uint32_t)(crow*128 + ((c16 ^ (crow & 7)) << 4));
    }
    auto load_stage = [&](int c, int slot) {
        const uint32_t s0 = sb + (uint32_t)slot * GSTG3;
        #pragma unroll
        for (int i = 0; i < 4; i++) CP_ASYNC16(s0 + dsto[i],          agh + c*64 + i*8);
        #pragma unroll
        for (int i = 0; i < 4; i++) CP_ASYNC16(s0 + 16384u + dsto[i], agl + c*64 + i*8);
        #pragma unroll
        for (int i = 0; i < 4; i++) CP_ASYNC16(s0 + 32768u + dsto[i], bgh + c*64 + i*8);
        #pragma unroll
        for (int i = 0; i < 4; i++) CP_ASYNC16(s0 + 49152u + dsto[i], bgl + c*64 + i*8);
    };

    const int ra = lane & 15, ca = lane >> 4;
    const int rb = (lane & 7) + ((lane >> 4) << 3), cb = (lane >> 3) & 1;
    const int xr = lane & 7;
    const uint32_t aro = (uint32_t)((wm*32 + ra) * 128);
    const uint32_t bro = (uint32_t)((wn*64 + rb) * 128);

    float acc[2][8][4];
    #pragma unroll
    for (int i = 0; i < 2; i++)
        #pragma unroll
        for (int j = 0; j < 8; j++)
            #pragma unroll
            for (int r = 0; r < 4; r++) acc[i][j][r] = 0.f;

    load_stage(0, 0); CP_COMMIT;
    load_stage(1, 1); CP_COMMIT;

    const int NC = K >> 6;
    int slot = 0;
    for (int c = 0; c < NC; c++) {
        CP_WAIT(1);
        __syncthreads();
        if (c + 2 < NC) {
            int ns = slot + 2; if (ns >= 3) ns -= 3;
            load_stage(c + 2, ns);
        }
        CP_COMMIT;
        const uint32_t st = sb + (uint32_t)slot * GSTG3;
        #pragma unroll
        for (int ks = 0; ks < 4; ks++) {
            const uint32_t kca = (uint32_t)(((ks*2 + ca) ^ xr) << 4);
            const uint32_t kcb = (uint32_t)(((ks*2 + cb) ^ xr) << 4);
            uint32_t ah[2][4], al4[2][4], bh[4][4], bl4[4][4];
            #pragma unroll
            for (int mt = 0; mt < 2; mt++) {
                ldsm4(ah[mt],  st + aro + mt*2048u + kca);
                ldsm4(al4[mt], st + 16384u + aro + mt*2048u + kca);
            }
            #pragma unroll
            for (int nq = 0; nq < 4; nq++) {
                ldsm4(bh[nq],  st + 32768u + bro + nq*2048u + kcb);
                ldsm4(bl4[nq], st + 49152u + bro + nq*2048u + kcb);
            }
            #pragma unroll
            for (int mt = 0; mt < 2; mt++)
                #pragma unroll
                for (int nt = 0; nt < 8; nt++) {
                    const int nq = nt >> 1, s2 = (nt & 1) * 2;
                    mma16816(acc[mt][nt], ah[mt], bh[nq][s2], bh[nq][s2+1]);
                }
            #pragma unroll
            for (int mt = 0; mt < 2; mt++)
                #pragma unroll
                for (int nt = 0; nt < 8; nt++) {
                    const int nq = nt >> 1, s2 = (nt & 1) * 2;
                    mma16816(acc[mt][nt], ah[mt], bl4[nq][s2], bl4[nq][s2+1]);
                }
            #pragma unroll
            for (int mt = 0; mt < 2; mt++)
                #pragma unroll
                for (int nt = 0; nt < 8; nt++) {
                    const int nq = nt >> 1, s2 = (nt & 1) * 2;
                    mma16816(acc[mt][nt], al4[mt], bh[nq][s2], bh[nq][s2+1]);
                }
        }
        slot = (slot + 1 == 3) ? 0 : slot + 1;
    }

    const int grbase = bm*128 + wm*32;
    const int gcbase = bn*128 + wn*64;
    #pragma unroll
    for (int mt = 0; mt < 2; mt++) {
        const int r0 = grbase + mt*16 + (lane >> 2);
        #pragma unroll
        for (int nt = 0; nt < 8; nt++) {
            const int gc = gcbase + nt*8 + (lane & 3)*2;
            *(float2*)(outf + (size_t)r0 * N + gc) =
                make_float2(acc[mt][nt][0], acc[mt][nt][1]);
            *(float2*)(outf + (size_t)(r0+8) * N + gc) =
                make_float2(acc[mt][nt][2], acc[mt][nt][3]);
        }
    }
}

// ================= flash attention: 1-pass fp16, Q tile 256, 64x64 warp tile =================
// 8 warps, each warp 32 Q rows. KV tile 64.
// smem: Qh[256x64]@0 (32KB), then 3 stages of 16KB: Kh@0 Vh@8K.
#define ASTG 16384
#define AQSZ 32768
#define ATT_SMEM (AQSZ + 3*ASTG)

__global__ void __launch_bounds__(256, 1) attn_h(
    const __half* __restrict__ qkvh, __half* __restrict__ yh)
{
    extern __shared__ char sm[];
    const uint32_t sb = smem_u32(sm);
    const int t = threadIdx.x, w = t >> 5, lane = t & 31;
    const int bhx = blockIdx.y, b = bhx >> 4, h = bhx & 15;
    const int q0 = blockIdx.x * 256;
    const size_t MC = (size_t)M_ * C_;
    const int NT = T_ / 64;   // 32 tiles

    const __half* qgh = qkvh + (size_t)(b*T_ + q0) * C_ + h*64;
    const __half* kgh = qkvh + MC   + (size_t)(b*T_) * C_ + h*64;
    const __half* vgh = qkvh + 2*MC + (size_t)(b*T_) * C_ + h*64;

    // Q loads: each thread loads one full row (8 x 16B)
    {
        const int qr = t;
        const __half* qrow = qgh + (size_t)qr * C_;
        #pragma unroll
        for (int i = 0; i < 8; i++) {
            const uint32_t d = (uint32_t)(qr*128 + ((i ^ (qr & 7)) << 4));
            CP_ASYNC16(sb + d, qrow + i*8);
        }
    }
    CP_COMMIT;

    // KV stage loader: 64 rows x 128B for K and V (each thread: 1 chunk K + 1 chunk V x2)
    const int kr = t >> 2, kc2 = (t & 3) * 2;
    auto load_kv = [&](int kt, int slot) {
        const uint32_t s0 = sb + AQSZ + (uint32_t)slot * ASTG;
        const size_t rowoff = (size_t)(kt*64 + kr) * C_;
        #pragma unroll
        for (int i = 0; i < 2; i++) {
            const int c16 = kc2 + i;
            const uint32_t d = (uint32_t)(kr*128 + ((c16 ^ (kr & 7)) << 4));
            CP_ASYNC16(s0 + d,         kgh + rowoff + c16*8);
            CP_ASYNC16(s0 + 8192u + d, vgh + rowoff + c16*8);
        }
    };
    load_kv(0, 0); CP_COMMIT;
    load_kv(1, 1); CP_COMMIT;

    const int ra = lane & 15, ca = lane >> 4;
    const int rb = (lane & 7) + ((lane >> 4) << 3), cb = (lane >> 3) & 1;
    const int rv = (lane & 7) + (((lane >> 3) & 1) << 3), cv = lane >> 4;
    const int xr = lane & 7;

    CP_WAIT(2);           // Q landed
    __syncthreads();
    uint32_t qh4[4][2][4];   // [ks][mt][regs]
    {
        #pragma unroll
        for (int mt = 0; mt < 2; mt++) {
            const uint32_t qro = (uint32_t)((w*32 + mt*16 + ra) * 128);
            #pragma unroll
            for (int ks = 0; ks < 4; ks++) {
                const uint32_t off = qro + (uint32_t)(((ks*2 + ca) ^ xr) << 4);
                ldsm4(qh4[ks][mt], sb + off);
            }
        }
    }

    float o_[2][8][4];
    #pragma unroll
    for (int mt = 0; mt < 2; mt++)
        #pragma unroll
        for (int i = 0; i < 8; i++)
            #pragma unroll
            for (int j = 0; j < 4; j++) o_[mt][i][j] = 0.f;
    float m_a[2] = {-1e30f, -1e30f}, m_b[2] = {-1e30f, -1e30f};
    float l_a[2] = {0.f, 0.f},       l_b[2] = {0.f, 0.f};

    int slot = 0;
    for (int kt = 0; kt < NT; kt++) {
        CP_WAIT(1);
        __syncthreads();
        if (kt + 2 < NT) {
            int ns = slot + 2; if (ns >= 3) ns -= 3;
            load_kv(kt + 2, ns);
        }
        CP_COMMIT;
        const uint32_t st = sb + AQSZ + (uint32_t)slot * ASTG;

        // ---- S = qh·kh (1-pass), warp tile 32x64 ----
        float sc[2][8][4];
        #pragma unroll
        for (int mt = 0; mt < 2; mt++)
            #pragma unroll
            for (int i = 0; i < 8; i++)
                #pragma unroll
                for (int j = 0; j < 4; j++) sc[mt][i][j] = 0.f;
        #pragma unroll
        for (int ks = 0; ks < 4; ks++) {
            uint32_t kh4[4][4];
            #pragma unroll
            for (int nq = 0; nq < 4; nq++) {
                const uint32_t off = (uint32_t)((nq*16 + rb) * 128)
                                   + (uint32_t)(((ks*2 + cb) ^ xr) << 4);
                ldsm4(kh4[nq], st + off);
            }
            #pragma unroll
            for (int mt = 0; mt < 2; mt++)
                #pragma unroll
                for (int nt = 0; nt < 8; nt++) {
                    const int nq = nt >> 1, s2 = (nt & 1) * 2;
                    mma16816(sc[mt][nt], qh4[ks][mt], kh4[nq][s2], kh4[nq][s2+1]);
                }
        }

        // ---- online softmax (base-2), per mt tile ----
        #pragma unroll
        for (int mt = 0; mt < 2; mt++) {
            float mxa = -1e30f, mxb = -1e30f;
            #pragma unroll
            for (int nt = 0; nt < 8; nt++) {
                mxa = fmaxf(mxa, fmaxf(sc[mt][nt][0], sc[mt][nt][1]));
                mxb = fmaxf(mxb, fmaxf(sc[mt][nt][2], sc[mt][nt][3]));
            }
            mxa = fmaxf(mxa, __shfl_xor_sync(0xffffffffu, mxa, 1));
            mxa = fmaxf(mxa, __shfl_xor_sync(0xffffffffu, mxa, 2));
            mxb = fmaxf(mxb, __shfl_xor_sync(0xffffffffu, mxb, 1));
            mxb = fmaxf(mxb, __shfl_xor_sync(0xffffffffu, mxb, 2));
            const float nma = fmaxf(m_a[mt], mxa), nmb = fmaxf(m_b[mt], mxb);
            const float cfa = fex2(m_a[mt] - nma), cfb = fex2(m_b[mt] - nmb);
            m_a[mt] = nma; m_b[mt] = nmb;
            float rsa = 0.f, rsb = 0.f;
            #pragma unroll
            for (int nt = 0; nt < 8; nt++) {
                sc[mt][nt][0] = fex2(sc[mt][nt][0] - nma); rsa += sc[mt][nt][0];
                sc[mt][nt][1] = fex2(sc[mt][nt][1] - nma); rsa += sc[mt][nt][1];
                sc[mt][nt][2] = fex2(sc[mt][nt][2] - nmb); rsb += sc[mt][nt][2];
                sc[mt][nt][3] = fex2(sc[mt][nt][3] - nmb); rsb += sc[mt][nt][3];
            }
            rsa += __shfl_xor_sync(0xffffffffu, rsa, 1);
            rsa += __shfl_xor_sync(0xffffffffu, rsa, 2);
            rsb += __shfl_xor_sync(0xffffffffu, rsb, 1);
            rsb += __shfl_xor_sync(0xffffffffu, rsb, 2);
            l_a[mt] = l_a[mt] * cfa + rsa;
            l_b[mt] = l_b[mt] * cfb + rsb;
            #pragma unroll
            for (int dt = 0; dt < 8; dt++) {
                o_[mt][dt][0] *= cfa; o_[mt][dt][1] *= cfa;
                o_[mt][dt][2] *= cfb; o_[mt][dt][3] *= cfb;
            }
        }

        // ---- O += ph·vh (1-pass) ----
        #pragma unroll
        for (int ks = 0; ks < 4; ks++) {
            uint32_t ph[2][4];
            #pragma unroll
            for (int mt = 0; mt < 2; mt++) {
                ph[mt][0] = pack_h2(sc[mt][2*ks][0],   sc[mt][2*ks][1]);
                ph[mt][1] = pack_h2(sc[mt][2*ks][2],   sc[mt][2*ks][3]);
                ph[mt][2] = pack_h2(sc[mt][2*ks+1][0], sc[mt][2*ks+1][1]);
                ph[mt][3] = pack_h2(sc[mt][2*ks+1][2], sc[mt][2*ks+1][3]);
            }
            uint32_t vh4[4][4];
            #pragma unroll
            for (int nq = 0; nq < 4; nq++) {
                const uint32_t off = (uint32_t)((ks*16 + rv) * 128)
                                   + (uint32_t)(((nq*2 + cv) ^ xr) << 4);
                ldsm4t(vh4[nq], st + 8192u + off);
            }
            #pragma unroll
            for (int mt = 0; mt < 2; mt++)
                #pragma unroll
                for (int dt = 0; dt < 8; dt++) {
                    const int nq = dt >> 1, s2 = (dt & 1) * 2;
                    mma16816(o_[mt][dt], ph[mt], vh4[nq][s2], vh4[nq][s2+1]);
                }
        }
        slot = (slot + 1 == 3) ? 0 : slot + 1;
    }

    // ---- write y (fp16 hi only) ----
    #pragma unroll
    for (int mt = 0; mt < 2; mt++) {
        const float ia = 1.f / l_a[mt], ib = 1.f / l_b[mt];
        const int r0 = q0 + w*32 + mt*16 + (lane >> 2);
        __half* ybh = yh + (size_t)(b*T_ + r0) * C_ + h*64;
        #pragma unroll
        for (int dt = 0; dt < 8; dt++) {
            const int gc = dt*8 + (lane & 3)*2;
            *(uint32_t*)(ybh + gc)                = pack_h2(o_[mt][dt][0]*ia, o_[mt][dt][1]*ia);
            *(uint32_t*)(ybh + (size_t)8*C_ + gc) = pack_h2(o_[mt][dt][2]*ib, o_[mt][dt][3]*ib);
        }
    }
}

// ================= orchestration =================
extern "C" void kernel_launch(void* const* d_in, const int* in_sizes, int n_in,
                              void* d_out, int out_size)
{
    const float* seq  = (const float*)d_in[0];
    const float* pos  = (const float*)d_in[1];
    const float* Wq   = (const float*)d_in[2];
    const float* bq   = (const float*)d_in[3];
    const float* Wk   = (const float*)d_in[4];
    const float* bk   = (const float*)d_in[5];
    const float* Wv   = (const float*)d_in[6];
    const float* bv   = (const float*)d_in[7];
    const float* Wo   = (const float*)d_in[8];
    const float* bo   = (const float*)d_in[9];
    const float* ln1w = (const float*)d_in[10];
    const float* ln1b = (const float*)d_in[11];
    const float* ln2w = (const float*)d_in[12];
    const float* ln2b = (const float*)d_in[13];
    const float* W1   = (const float*)d_in[14];
    const float* b1   = (const float*)d_in[15];
    const float* W2   = (const float*)d_in[16];
    const float* b2   = (const float*)d_in[17];
    const float* lnfw = (const float*)d_in[18];
    const float* lnfb = (const float*)d_in[19];
    const float* Wh   = (const float*)d_in[20];
    float* out = (float*)d_out;

    float *px, *pbqkv;
    __half *phh, *phl, *pqkvh, *pyh, *puh, *pwh, *pwl;
    cudaGetSymbolAddress((void**)&px, g_x);
    cudaGetSymbolAddress((void**)&phh, g_hh);
    cudaGetSymbolAddress((void**)&phl, g_hl);
    cudaGetSymbolAddress((void**)&pqkvh, g_qkvh);
    cudaGetSymbolAddress((void**)&pyh, g_yh);
    cudaGetSymbolAddress((void**)&puh, g_uh);
    cudaGetSymbolAddress((void**)&pwh, g_wh);
    cudaGetSymbolAddress((void**)&pwl, g_wl);
    cudaGetSymbolAddress((void**)&pbqkv, g_bqkv);

    cudaFuncSetAttribute(attn_h, cudaFuncAttributeMaxDynamicSharedMemorySize, ATT_SMEM);
    cudaFuncSetAttribute((gemm_h2<1>), cudaFuncAttributeMaxDynamicSharedMemorySize, GEMM_SMEM2);
    cudaFuncSetAttribute((gemm_h2<2>), cudaFuncAttributeMaxDynamicSharedMemorySize, GEMM_SMEM2);
    cudaFuncSetAttribute((gemm_h2<3>), cudaFuncAttributeMaxDynamicSharedMemorySize, GEMM_SMEM2);
    cudaFuncSetAttribute(gemm_head, cudaFuncAttributeMaxDynamicSharedMemorySize, GEMM_SMEM3);

    // ---- weight conversion: ONE launch ----
    conv_all<<<(int)(WTOT / 2048), 256>>>(Wq, Wk, Wv, Wo, W1, W2, Wh, pwh, pwl);
    packqkvb<<<L_*3*C_/256, 256>>>(bq, bk, bv, pbqkv);
    addpos_kernel<<<M_ * C_ / 4 / 256, 256>>>(seq, pos, px);

    dim3 gQKV(3*C_ / 128, M_ / 256);   // (24, 32)
    dim3 gC(C_ / 128, M_ / 256);       // (8, 32)
    dim3 gF(FF_ / 128, M_ / 256);      // (32, 32)
    dim3 gA(T_ / 256, B_ * H_);        // (8, 64)
    dim3 gHead(OUT_ / 128, M_ / 128);  // (8, 64)

    for (int l = 0; l < L_; l++) {
        const size_t wl = (size_t)l * WPL_;
        ln_split<<<M_, 256>>>(px, ln1w + l*C_, ln1b + l*C_, phh, nullptr);
        gemm_h2<1><<<gQKV, 256, GEMM_SMEM2>>>(phh, pwh + wl,
            pbqkv + l*3*C_, nullptr, nullptr, pqkvh, 3*C_, C_);
        attn_h<<<gA, 256, ATT_SMEM>>>(pqkvh, pyh);
        gemm_h2<3><<<gC, 256, GEMM_SMEM2>>>(pyh, pwh + wl + WOFF_WO,
            bo + l*C_, px, px, nullptr, C_, C_);
        ln_split<<<M_, 256>>>(px, ln2w + l*C_, ln2b + l*C_, phh, nullptr);
        gemm_h2<2><<<gF, 256, GEMM_SMEM2>>>(phh, pwh + wl + WOFF_W1,
            b1 + l*FF_, nullptr, nullptr, puh, FF_, C_);
        gemm_h2<3><<<gC, 256, GEMM_SMEM2>>>(puh, pwh + wl + WOFF_W2,
            b2 + l*C_, px, px, nullptr, C_, FF_);
    }

    // final LN needs lo for the 3-pass head GEMM
    ln_split<<<M_, 256>>>(px, lnfw, lnfb, phh, phl);
    gemm_head<<<gHead, 256, GEMM_SMEM3>>>(phh, phl, pwh + WHEAD_OFF, pwl + WHEAD_OFF,
        out, OUT_, C_);
}

// round 13
// speedup vs baseline: 6.6779x; 1.0113x over previous
#include <cuda_runtime.h>
#include <cuda_fp16.h>
#include <math.h>
#include <stdint.h>

#define L_ 8
#define H_ 16
#define T_ 2048
#define C_ 1024
#define OUT_ 1024
#define B_ 4
#define DH_ 64
#define FF_ 4096
#define M_ (B_*T_)   // 8192 rows

#define CC_ (C_*C_)                   // 1048576
#define WPL_ (12*CC_)                 // weights per layer (halves)
#define WOFF_WO  (3*CC_)
#define WOFF_W1  (4*CC_)
#define WOFF_W2  (8*CC_)
#define WHEAD_OFF ((size_t)L_*WPL_)   // 100663296
#define WTOT (WHEAD_OFF + CC_)        // 101711872

// q pre-scale: 0.125 (1/sqrt(DH)) * log2(e) -> softmax in base-2 domain
#define QSCALE 0.1803368801111204f

// ---------------- scratch (static device globals) ----------------
__device__ float g_x[M_*C_];
__device__ __align__(16) __half g_hh[M_*C_],  g_hl[M_*C_];
__device__ __align__(16) __half g_qkvh[3*M_*C_];
__device__ __align__(16) __half g_yh[M_*C_];
__device__ __align__(16) __half g_uh[(size_t)M_*FF_];
__device__ __align__(16) __half g_wh[WTOT],   g_wl[WTOT];
__device__ float g_bqkv[L_*3*C_];

// ================= helpers =================
__device__ __forceinline__ uint32_t smem_u32(const void* p) {
    uint32_t a;
    asm("{ .reg .u64 t; cvta.to.shared.u64 t, %1; cvt.u32.u64 %0, t; }" : "=r"(a) : "l"(p));
    return a;
}
__device__ __forceinline__ void mma16816(float* c, const uint32_t* a, uint32_t b0, uint32_t b1) {
    asm volatile(
        "mma.sync.aligned.m16n8k16.row.col.f32.f16.f16.f32 "
        "{%0,%1,%2,%3}, {%4,%5,%6,%7}, {%8,%9}, {%0,%1,%2,%3};"
        : "+f"(c[0]), "+f"(c[1]), "+f"(c[2]), "+f"(c[3])
        : "r"(a[0]), "r"(a[1]), "r"(a[2]), "r"(a[3]), "r"(b0), "r"(b1));
}
__device__ __forceinline__ void ldsm4(uint32_t* r, uint32_t addr) {
    asm volatile("ldmatrix.sync.aligned.m8n8.x4.shared.b16 {%0,%1,%2,%3}, [%4];"
                 : "=r"(r[0]), "=r"(r[1]), "=r"(r[2]), "=r"(r[3]) : "r"(addr));
}
__device__ __forceinline__ void ldsm4t(uint32_t* r, uint32_t addr) {
    asm volatile("ldmatrix.sync.aligned.m8n8.x4.trans.shared.b16 {%0,%1,%2,%3}, [%4];"
                 : "=r"(r[0]), "=r"(r[1]), "=r"(r[2]), "=r"(r[3]) : "r"(addr));
}
#define CP_ASYNC16(dst, src) \
    asm volatile("cp.async.cg.shared.global [%0], [%1], 16;" :: "r"(dst), "l"(src))
#define CP_COMMIT asm volatile("cp.async.commit_group;" ::: "memory")
#define CP_WAIT(n) asm volatile("cp.async.wait_group %0;" :: "n"(n) : "memory")

__device__ __forceinline__ float fex2(float x) {
    float y;
    asm("ex2.approx.f32 %0, %1;" : "=f"(y) : "f"(x));
    return y;
}
// two exps in one MUFU op: pack (a,b) to half2, ex2.approx.f16x2
__device__ __forceinline__ uint32_t ex2_h2(float a, float b) {
    __half2 hv = __floats2half2_rn(a, b);
    uint32_t r;
    asm("ex2.approx.f16x2 %0, %1;" : "=r"(r) : "r"(*(uint32_t*)&hv));
    return r;
}
__device__ __forceinline__ void split2(float x, float y, uint32_t& h, uint32_t& l) {
    __half2 hh = __floats2half2_rn(x, y);
    float2 hf = __half22float2(hh);
    __half2 ll = __floats2half2_rn(x - hf.x, y - hf.y);
    h = *(uint32_t*)&hh;
    l = *(uint32_t*)&ll;
}
__device__ __forceinline__ uint32_t pack_h2(float x, float y) {
    __half2 hh = __floats2half2_rn(x, y);
    return *(uint32_t*)&hh;
}
__device__ __forceinline__ float gelu_exact(float v) {
    return 0.5f * v * (1.0f + erff(v * 0.70710678118654752f));
}

// ================= fused weight conversion (single launch) =================
__global__ void __launch_bounds__(256) conv_all(
    const float* __restrict__ Wq, const float* __restrict__ Wk,
    const float* __restrict__ Wv, const float* __restrict__ Wo,
    const float* __restrict__ W1, const float* __restrict__ W2,
    const float* __restrict__ Whd,
    __half* __restrict__ dh, __half* __restrict__ dl)
{
    const size_t i = ((size_t)blockIdx.x * 256 + threadIdx.x) * 8;
    const float* src;
    if (i >= WHEAD_OFF) {
        src = Whd + (i - WHEAD_OFF);
    } else {
        const int l = (int)(i / WPL_);
        const size_t r = i % WPL_;
        if      (r <   (size_t)CC_)   src = Wq + (size_t)l*CC_   + r;
        else if (r < 2*(size_t)CC_)   src = Wk + (size_t)l*CC_   + (r -   CC_);
        else if (r < 3*(size_t)CC_)   src = Wv + (size_t)l*CC_   + (r - 2*CC_);
        else if (r < 4*(size_t)CC_)   src = Wo + (size_t)l*CC_   + (r - 3*CC_);
        else if (r < 8*(size_t)CC_)   src = W1 + (size_t)l*4*CC_ + (r - 4*CC_);
        else                          src = W2 + (size_t)l*4*CC_ + (r - 8*CC_);
    }
    float4 a = *(const float4*)(src), b = *(const float4*)(src + 4);
    uint32_t h[4], l4[4];
    split2(a.x, a.y, h[0], l4[0]); split2(a.z, a.w, h[1], l4[1]);
    split2(b.x, b.y, h[2], l4[2]); split2(b.z, b.w, h[3], l4[3]);
    *(uint4*)(dh + i) = make_uint4(h[0], h[1], h[2], h[3]);
    if (i >= WHEAD_OFF)
        *(uint4*)(dl + i) = make_uint4(l4[0], l4[1], l4[2], l4[3]);
}
__global__ void __launch_bounds__(256) packqkvb(
    const float* __restrict__ bq, const float* __restrict__ bk,
    const float* __restrict__ bv, float* __restrict__ dst)
{
    int idx = blockIdx.x * 256 + threadIdx.x;      // L_*3072
    int l = idx / 3072, c = idx % 3072;
    float v = (c < 1024) ? bq[l*1024 + c] : (c < 2048) ? bk[l*1024 + c - 1024]
                                                        : bv[l*1024 + c - 2048];
    dst[idx] = v;
}

// ================= x = seq + pos =================
__global__ void __launch_bounds__(256) addpos_kernel(
    const float* __restrict__ seq, const float* __restrict__ pos, float* __restrict__ x)
{
    int i = blockIdx.x * 256 + threadIdx.x;
    float4 s = ((const float4*)seq)[i];
    float4 p = ((const float4*)pos)[i & (T_*C_/4 - 1)];
    s.x += p.x; s.y += p.y; s.z += p.z; s.w += p.w;
    ((float4*)x)[i] = s;
}

// ================= LayerNorm -> fp16 hi (+ optional lo) =================
__global__ void __launch_bounds__(256) ln_split(
    const float* __restrict__ x, const float* __restrict__ w,
    const float* __restrict__ b, __half* __restrict__ outh, __half* __restrict__ outl)
{
    const int row = blockIdx.x;
    const int t = threadIdx.x;
    const float4 v = *(const float4*)(x + (size_t)row * C_ + t * 4);
    float s  = v.x + v.y + v.z + v.w;
    float sq = v.x*v.x + v.y*v.y + v.z*v.z + v.w*v.w;
    #pragma unroll
    for (int off = 16; off; off >>= 1) {
        s  += __shfl_xor_sync(0xffffffffu, s,  off);
        sq += __shfl_xor_sync(0xffffffffu, sq, off);
    }
    __shared__ float rs_[8], rq_[8];
    if ((t & 31) == 0) { rs_[t >> 5] = s; rq_[t >> 5] = sq; }
    __syncthreads();
    s = 0.f; sq = 0.f;
    #pragma unroll
    for (int i = 0; i < 8; i++) { s += rs_[i]; sq += rq_[i]; }
    const float mu   = s * (1.0f / 1024.0f);
    const float var  = sq * (1.0f / 1024.0f) - mu * mu;
    const float rstd = rsqrtf(var + 1e-5f);
    const float4 wv = *(const float4*)(w + t * 4);
    const float4 bv = *(const float4*)(b + t * 4);
    float ox = (v.x - mu) * rstd * wv.x + bv.x;
    float oy = (v.y - mu) * rstd * wv.y + bv.y;
    float oz = (v.z - mu) * rstd * wv.z + bv.z;
    float ow = (v.w - mu) * rstd * wv.w + bv.w;
    uint32_t h0, l0, h1, l1;
    split2(ox, oy, h0, l0);
    split2(oz, ow, h1, l1);
    *(uint2*)(outh + (size_t)row * C_ + t * 4) = make_uint2(h0, h1);
    if (outl) *(uint2*)(outl + (size_t)row * C_ + t * 4) = make_uint2(l0, l1);
}

// ================= 1-pass fp16 GEMM, 256x128 block, 64x64 warp tile =================
#define GSTG2 49152u
#define GEMM_SMEM2 (3*49152)

template <int EPI>
__global__ void __launch_bounds__(256, 1) gemm_h2(
    const __half* __restrict__ Ah,
    const __half* __restrict__ Wh,
    const float* __restrict__ bias, const float* __restrict__ resid,
    float* __restrict__ outf, __half* __restrict__ outh,
    int N, int K)
{
    extern __shared__ char sm[];
    const uint32_t sb = smem_u32(sm);
    const int t = threadIdx.x, w = t >> 5, lane = t & 31;
    const int bm = blockIdx.y, bn = blockIdx.x;
    const int wm = w & 3, wn = w >> 2;

    const int crow = t >> 1, chalf = t & 1;
    const __half* agh = Ah + (size_t)(bm*256 + crow) * K + chalf*32;
    const __half* bgh = Wh + (size_t)(bn*128 + crow) * K + chalf*32;
    uint32_t dsto[4];
    #pragma unroll
    for (int i = 0; i < 4; i++) {
        int c16 = chalf*4 + i;
        dsto[i] = (uint32_t)(crow*128 + ((c16 ^ (crow & 7)) << 4));
    }
    auto load_stage = [&](int c, int slot) {
        const uint32_t s0 = sb + (uint32_t)slot * GSTG2;
        const __half* a0 = agh + c*64;
        const __half* b0 = bgh + c*64;
        #pragma unroll
        for (int i = 0; i < 4; i++) CP_ASYNC16(s0 + dsto[i],           a0 + i*8);
        #pragma unroll
        for (int i = 0; i < 4; i++) CP_ASYNC16(s0 + 16384u + dsto[i],  a0 + (size_t)128*K + i*8);
        #pragma unroll
        for (int i = 0; i < 4; i++) CP_ASYNC16(s0 + 32768u + dsto[i],  b0 + i*8);
    };

    const int ra = lane & 15, ca = lane >> 4;
    const int rb = (lane & 7) + ((lane >> 4) << 3), cb = (lane >> 3) & 1;
    const int xr = lane & 7;
    const uint32_t aro = (uint32_t)((wm*64 + ra) * 128);
    const uint32_t bro = (uint32_t)((wn*64 + rb) * 128);

    float acc[4][8][4];
    #pragma unroll
    for (int i = 0; i < 4; i++)
        #pragma unroll
        for (int j = 0; j < 8; j++)
            #pragma unroll
            for (int r = 0; r < 4; r++) acc[i][j][r] = 0.f;

    load_stage(0, 0); CP_COMMIT;
    load_stage(1, 1); CP_COMMIT;

    const int NC = K >> 6;
    int slot = 0;
    for (int c = 0; c < NC; c++) {
        CP_WAIT(1);
        __syncthreads();
        if (c + 2 < NC) {
            int ns = slot + 2; if (ns >= 3) ns -= 3;
            load_stage(c + 2, ns);
        }
        CP_COMMIT;
        const uint32_t st = sb + (uint32_t)slot * GSTG2;
        #pragma unroll
        for (int ks = 0; ks < 4; ks++) {
            const uint32_t kca = (uint32_t)(((ks*2 + ca) ^ xr) << 4);
            const uint32_t kcb = (uint32_t)(((ks*2 + cb) ^ xr) << 4);
            uint32_t ah[4][4], bh[4][4];
            #pragma unroll
            for (int mt = 0; mt < 4; mt++)
                ldsm4(ah[mt], st + aro + mt*2048u + kca);
            #pragma unroll
            for (int nq = 0; nq < 4; nq++)
                ldsm4(bh[nq], st + 32768u + bro + nq*2048u + kcb);
            #pragma unroll
            for (int mt = 0; mt < 4; mt++)
                #pragma unroll
                for (int nt = 0; nt < 8; nt++) {
                    const int nq = nt >> 1, s2 = (nt & 1) * 2;
                    mma16816(acc[mt][nt], ah[mt], bh[nq][s2], bh[nq][s2+1]);
                }
        }
        slot = (slot + 1 == 3) ? 0 : slot + 1;
    }

    // ---- epilogue ----
    const int grbase = bm*256 + wm*64;
    const int gcbase = bn*128 + wn*64;
    #pragma unroll
    for (int mt = 0; mt < 4; mt++) {
        const int r0 = grbase + mt*16 + (lane >> 2);
        #pragma unroll
        for (int nt = 0; nt < 8; nt++) {
            const int gc = gcbase + nt*8 + (lane & 3)*2;
            float2 v0 = make_float2(acc[mt][nt][0], acc[mt][nt][1]);
            float2 v1 = make_float2(acc[mt][nt][2], acc[mt][nt][3]);
            {
                float2 bb = *(const float2*)(bias + gc);
                v0.x += bb.x; v0.y += bb.y; v1.x += bb.x; v1.y += bb.y;
            }
            if (EPI == 1) {
                const int third = gc >> 10, lc = gc & 1023;
                __half* oh = outh + (size_t)third * ((size_t)M_ * C_);
                if (third == 0) {
                    v0.x *= QSCALE; v0.y *= QSCALE; v1.x *= QSCALE; v1.y *= QSCALE;
                }
                *(uint32_t*)(oh + (size_t)r0 * 1024 + lc)     = pack_h2(v0.x, v0.y);
                *(uint32_t*)(oh + (size_t)(r0+8) * 1024 + lc) = pack_h2(v1.x, v1.y);
            } else if (EPI == 2) {
                v0.x = gelu_exact(v0.x); v0.y = gelu_exact(v0.y);
                v1.x = gelu_exact(v1.x); v1.y = gelu_exact(v1.y);
                *(uint32_t*)(outh + (size_t)r0 * N + gc)     = pack_h2(v0.x, v0.y);
                *(uint32_t*)(outh + (size_t)(r0+8) * N + gc) = pack_h2(v1.x, v1.y);
            } else {  // EPI == 3
                float2 ra2 = *(const float2*)(resid + (size_t)r0 * N + gc);
                float2 rb2 = *(const float2*)(resid + (size_t)(r0+8) * N + gc);
                v0.x += ra2.x; v0.y += ra2.y; v1.x += rb2.x; v1.y += rb2.y;
                *(float2*)(outf + (size_t)r0 * N + gc) = v0;
                *(float2*)(outf + (size_t)(r0+8) * N + gc) = v1;
            }
        }
    }
}

// ================= head GEMM: 3-pass, 128x128 block =================
#define GSTG3 65536u
#define GEMM_SMEM3 (3*65536)

__global__ void __launch_bounds__(256, 1) gemm_head(
    const __half* __restrict__ Ah, const __half* __restrict__ Al,
    const __half* __restrict__ Wh, const __half* __restrict__ Wl,
    float* __restrict__ outf, int N, int K)
{
    extern __shared__ char sm[];
    const uint32_t sb = smem_u32(sm);
    const int t = threadIdx.x, w = t >> 5, lane = t & 31;
    const int bm = blockIdx.y, bn = blockIdx.x;
    const int wm = w & 3, wn = w >> 2;

    const int crow = t >> 1, chalf = t & 1;
    const __half* agh = Ah + (size_t)(bm*128 + crow) * K + chalf*32;
    const __half* agl = Al + (size_t)(bm*128 + crow) * K + chalf*32;
    const __half* bgh = Wh + (size_t)(bn*128 + crow) * K + chalf*32;
    const __half* bgl = Wl + (size_t)(bn*128 + crow) * K + chalf*32;
    uint32_t dsto[4];
    #pragma unroll
    for (int i = 0; i < 4; i++) {
        int c16 = chalf*4 + i;
        dsto[i] = (uint32_t)(crow*128 + ((c16 ^ (crow & 7)) << 4));
    }
    auto load_stage = [&](int c, int slot) {
        const uint32_t s0 = sb + (uint32_t)slot * GSTG3;
        #pragma unroll
        for (int i = 0; i < 4; i++) CP_ASYNC16(s0 + dsto[i],          agh + c*64 + i*8);
        #pragma unroll
        for (int i = 0; i < 4; i++) CP_ASYNC16(s0 + 16384u + dsto[i], agl + c*64 + i*8);
        #pragma unroll
        for (int i = 0; i < 4; i++) CP_ASYNC16(s0 + 32768u + dsto[i], bgh + c*64 + i*8);
        #pragma unroll
        for (int i = 0; i < 4; i++) CP_ASYNC16(s0 + 49152u + dsto[i], bgl + c*64 + i*8);
    };

    const int ra = lane & 15, ca = lane >> 4;
    const int rb = (lane & 7) + ((lane >> 4) << 3), cb = (lane >> 3) & 1;
    const int xr = lane & 7;
    const uint32_t aro = (uint32_t)((wm*32 + ra) * 128);
    const uint32_t bro = (uint32_t)((wn*64 + rb) * 128);

    float acc[2][8][4];
    #pragma unroll
    for (int i = 0; i < 2; i++)
        #pragma unroll
        for (int j = 0; j < 8; j++)
            #pragma unroll
            for (int r = 0; r < 4; r++) acc[i][j][r] = 0.f;

    load_stage(0, 0); CP_COMMIT;
    load_stage(1, 1); CP_COMMIT;

    const int NC = K >> 6;
    int slot = 0;
    for (int c = 0; c < NC; c++) {
        CP_WAIT(1);
        __syncthreads();
        if (c + 2 < NC) {
            int ns = slot + 2; if (ns >= 3) ns -= 3;
            load_stage(c + 2, ns);
        }
        CP_COMMIT;
        const uint32_t st = sb + (uint32_t)slot * GSTG3;
        #pragma unroll
        for (int ks = 0; ks < 4; ks++) {
            const uint32_t kca = (uint32_t)(((ks*2 + ca) ^ xr) << 4);
            const uint32_t kcb = (uint32_t)(((ks*2 + cb) ^ xr) << 4);
            uint32_t ah[2][4], al4[2][4], bh[4][4], bl4[4][4];
            #pragma unroll
            for (int mt = 0; mt < 2; mt++) {
                ldsm4(ah[mt],  st + aro + mt*2048u + kca);
                ldsm4(al4[mt], st + 16384u + aro + mt*2048u + kca);
            }
            #pragma unroll
            for (int nq = 0; nq < 4; nq++) {
                ldsm4(bh[nq],  st + 32768u + bro + nq*2048u + kcb);
                ldsm4(bl4[nq], st + 49152u + bro + nq*2048u + kcb);
            }
            #pragma unroll
            for (int mt = 0; mt < 2; mt++)
                #pragma unroll
                for (int nt = 0; nt < 8; nt++) {
                    const int nq = nt >> 1, s2 = (nt & 1) * 2;
                    mma16816(acc[mt][nt], ah[mt], bh[nq][s2], bh[nq][s2+1]);
                }
            #pragma unroll
            for (int mt = 0; mt < 2; mt++)
                #pragma unroll
                for (int nt = 0; nt < 8; nt++) {
                    const int nq = nt >> 1, s2 = (nt & 1) * 2;
                    mma16816(acc[mt][nt], ah[mt], bl4[nq][s2], bl4[nq][s2+1]);
                }
            #pragma unroll
            for (int mt = 0; mt < 2; mt++)
                #pragma unroll
                for (int nt = 0; nt < 8; nt++) {
                    const int nq = nt >> 1, s2 = (nt & 1) * 2;
                    mma16816(acc[mt][nt], al4[mt], bh[nq][s2], bh[nq][s2+1]);
                }
        }
        slot = (slot + 1 == 3) ? 0 : slot + 1;
    }

    const int grbase = bm*128 + wm*32;
    const int gcbase = bn*128 + wn*64;
    #pragma unroll
    for (int mt = 0; mt < 2; mt++) {
        const int r0 = grbase + mt*16 + (lane >> 2);
        #pragma unroll
        for (int nt = 0; nt < 8; nt++) {
            const int gc = gcbase + nt*8 + (lane & 3)*2;
            *(float2*)(outf + (size_t)r0 * N + gc) =
                make_float2(acc[mt][nt][0], acc[mt][nt][1]);
            *(float2*)(outf + (size_t)(r0+8) * N + gc) =
                make_float2(acc[mt][nt][2], acc[mt][nt][3]);
        }
    }
}

// ================= flash attention: 1-pass fp16, Q tile 256, f16x2 exp =================
// 8 warps, each warp 32 Q rows. KV tile 64.
// smem: Qh[256x64]@0 (32KB), then 3 stages of 16KB: Kh@0 Vh@8K.
#define ASTG 16384
#define AQSZ 32768
#define ATT_SMEM (AQSZ + 3*ASTG)

__global__ void __launch_bounds__(256, 1) attn_h(
    const __half* __restrict__ qkvh, __half* __restrict__ yh)
{
    extern __shared__ char sm[];
    const uint32_t sb = smem_u32(sm);
    const int t = threadIdx.x, w = t >> 5, lane = t & 31;
    const int bhx = blockIdx.y, b = bhx >> 4, h = bhx & 15;
    const int q0 = blockIdx.x * 256;
    const size_t MC = (size_t)M_ * C_;
    const int NT = T_ / 64;   // 32 tiles

    const __half* qgh = qkvh + (size_t)(b*T_ + q0) * C_ + h*64;
    const __half* kgh = qkvh + MC   + (size_t)(b*T_) * C_ + h*64;
    const __half* vgh = qkvh + 2*MC + (size_t)(b*T_) * C_ + h*64;

    // Q loads: each thread loads one full row (8 x 16B)
    {
        const int qr = t;
        const __half* qrow = qgh + (size_t)qr * C_;
        #pragma unroll
        for (int i = 0; i < 8; i++) {
            const uint32_t d = (uint32_t)(qr*128 + ((i ^ (qr & 7)) << 4));
            CP_ASYNC16(sb + d, qrow + i*8);
        }
    }
    CP_COMMIT;

    // KV stage loader
    const int kr = t >> 2, kc2 = (t & 3) * 2;
    auto load_kv = [&](int kt, int slot) {
        const uint32_t s0 = sb + AQSZ + (uint32_t)slot * ASTG;
        const size_t rowoff = (size_t)(kt*64 + kr) * C_;
        #pragma unroll
        for (int i = 0; i < 2; i++) {
            const int c16 = kc2 + i;
            const uint32_t d = (uint32_t)(kr*128 + ((c16 ^ (kr & 7)) << 4));
            CP_ASYNC16(s0 + d,         kgh + rowoff + c16*8);
            CP_ASYNC16(s0 + 8192u + d, vgh + rowoff + c16*8);
        }
    };
    load_kv(0, 0); CP_COMMIT;
    load_kv(1, 1); CP_COMMIT;

    const int ra = lane & 15, ca = lane >> 4;
    const int rb = (lane & 7) + ((lane >> 4) << 3), cb = (lane >> 3) & 1;
    const int rv = (lane & 7) + (((lane >> 3) & 1) << 3), cv = lane >> 4;
    const int xr = lane & 7;

    CP_WAIT(2);           // Q landed
    __syncthreads();
    uint32_t qh4[4][2][4];   // [ks][mt][regs]
    {
        #pragma unroll
        for (int mt = 0; mt < 2; mt++) {
            const uint32_t qro = (uint32_t)((w*32 + mt*16 + ra) * 128);
            #pragma unroll
            for (int ks = 0; ks < 4; ks++) {
                const uint32_t off = qro + (uint32_t)(((ks*2 + ca) ^ xr) << 4);
                ldsm4(qh4[ks][mt], sb + off);
            }
        }
    }

    float o_[2][8][4];
    #pragma unroll
    for (int mt = 0; mt < 2; mt++)
        #pragma unroll
        for (int i = 0; i < 8; i++)
            #pragma unroll
            for (int j = 0; j < 4; j++) o_[mt][i][j] = 0.f;
    float m_a[2] = {-1e30f, -1e30f}, m_b[2] = {-1e30f, -1e30f};
    float l_a[2] = {0.f, 0.f},       l_b[2] = {0.f, 0.f};

    int slot = 0;
    for (int kt = 0; kt < NT; kt++) {
        CP_WAIT(1);
        __syncthreads();
        if (kt + 2 < NT) {
            int ns = slot + 2; if (ns >= 3) ns -= 3;
            load_kv(kt + 2, ns);
        }
        CP_COMMIT;
        const uint32_t st = sb + AQSZ + (uint32_t)slot * ASTG;

        // ---- S = qh·kh (1-pass), warp tile 32x64 ----
        float sc[2][8][4];
        #pragma unroll
        for (int mt = 0; mt < 2; mt++)
            #pragma unroll
            for (int i = 0; i < 8; i++)
                #pragma unroll
                for (int j = 0; j < 4; j++) sc[mt][i][j] = 0.f;
        #pragma unroll
        for (int ks = 0; ks < 4; ks++) {
            uint32_t kh4[4][4];
            #pragma unroll
            for (int nq = 0; nq < 4; nq++) {
                const uint32_t off = (uint32_t)((nq*16 + rb) * 128)
                                   + (uint32_t)(((ks*2 + cb) ^ xr) << 4);
                ldsm4(kh4[nq], st + off);
            }
            #pragma unroll
            for (int mt = 0; mt < 2; mt++)
                #pragma unroll
                for (int nt = 0; nt < 8; nt++) {
                    const int nq = nt >> 1, s2 = (nt & 1) * 2;
                    mma16816(sc[mt][nt], qh4[ks][mt], kh4[nq][s2], kh4[nq][s2+1]);
                }
        }

        // ---- online softmax (base-2, fp16x2 exp -> P packed directly) ----
        uint32_t pc[2][8][2];   // [mt][nt][pair]: half2 exp values, MMA-ready
        #pragma unroll
        for (int mt = 0; mt < 2; mt++) {
            float mxa = -1e30f, mxb = -1e30f;
            #pragma unroll
            for (int nt = 0; nt < 8; nt++) {
                mxa = fmaxf(mxa, fmaxf(sc[mt][nt][0], sc[mt][nt][1]));
                mxb = fmaxf(mxb, fmaxf(sc[mt][nt][2], sc[mt][nt][3]));
            }
            mxa = fmaxf(mxa, __shfl_xor_sync(0xffffffffu, mxa, 1));
            mxa = fmaxf(mxa, __shfl_xor_sync(0xffffffffu, mxa, 2));
            mxb = fmaxf(mxb, __shfl_xor_sync(0xffffffffu, mxb, 1));
            mxb = fmaxf(mxb, __shfl_xor_sync(0xffffffffu, mxb, 2));
            const float nma = fmaxf(m_a[mt], mxa), nmb = fmaxf(m_b[mt], mxb);
            const float cfa = fex2(m_a[mt] - nma), cfb = fex2(m_b[mt] - nmb);
            m_a[mt] = nma; m_b[mt] = nmb;
            float rsa = 0.f, rsb = 0.f;
            #pragma unroll
            for (int nt = 0; nt < 8; nt++) {
                const uint32_t e01 = ex2_h2(sc[mt][nt][0] - nma, sc[mt][nt][1] - nma);
                const uint32_t e23 = ex2_h2(sc[mt][nt][2] - nmb, sc[mt][nt][3] - nmb);
                pc[mt][nt][0] = e01;
                pc[mt][nt][1] = e23;
                float2 f01 = __half22float2(*(const __half2*)&e01);
                float2 f23 = __half22float2(*(const __half2*)&e23);
                rsa += f01.x + f01.y;
                rsb += f23.x + f23.y;
            }
            rsa += __shfl_xor_sync(0xffffffffu, rsa, 1);
            rsa += __shfl_xor_sync(0xffffffffu, rsa, 2);
            rsb += __shfl_xor_sync(0xffffffffu, rsb, 1);
            rsb += __shfl_xor_sync(0xffffffffu, rsb, 2);
            l_a[mt] = l_a[mt] * cfa + rsa;
            l_b[mt] = l_b[mt] * cfb + rsb;
            #pragma unroll
            for (int dt = 0; dt < 8; dt++) {
                o_[mt][dt][0] *= cfa; o_[mt][dt][1] *= cfa;
                o_[mt][dt][2] *= cfb; o_[mt][dt][3] *= cfb;
            }
        }

        // ---- O += ph·vh (1-pass) ----
        #pragma unroll
        for (int ks = 0; ks < 4; ks++) {
            uint32_t ph[2][4];
            #pragma unroll
            for (int mt = 0; mt < 2; mt++) {
                ph[mt][0] = pc[mt][2*ks][0];
                ph[mt][1] = pc[mt][2*ks][1];
                ph[mt][2] = pc[mt][2*ks+1][0];
                ph[mt][3] = pc[mt][2*ks+1][1];
            }
            uint32_t vh4[4][4];
            #pragma unroll
            for (int nq = 0; nq < 4; nq++) {
                const uint32_t off = (uint32_t)((ks*16 + rv) * 128)
                                   + (uint32_t)(((nq*2 + cv) ^ xr) << 4);
                ldsm4t(vh4[nq], st + 8192u + off);
            }
            #pragma unroll
            for (int mt = 0; mt < 2; mt++)
                #pragma unroll
                for (int dt = 0; dt < 8; dt++) {
                    const int nq = dt >> 1, s2 = (dt & 1) * 2;
                    mma16816(o_[mt][dt], ph[mt], vh4[nq][s2], vh4[nq][s2+1]);
                }
        }
        slot = (slot + 1 == 3) ? 0 : slot + 1;
    }

    // ---- write y (fp16 hi only) ----
    #pragma unroll
    for (int mt = 0; mt < 2; mt++) {
        const float ia = 1.f / l_a[mt], ib = 1.f / l_b[mt];
        const int r0 = q0 + w*32 + mt*16 + (lane >> 2);
        __half* ybh = yh + (size_t)(b*T_ + r0) * C_ + h*64;
        #pragma unroll
        for (int dt = 0; dt < 8; dt++) {
            const int gc = dt*8 + (lane & 3)*2;
            *(uint32_t*)(ybh + gc)                = pack_h2(o_[mt][dt][0]*ia, o_[mt][dt][1]*ia);
            *(uint32_t*)(ybh + (size_t)8*C_ + gc) = pack_h2(o_[mt][dt][2]*ib, o_[mt][dt][3]*ib);
        }
    }
}

// ================= orchestration =================
extern "C" void kernel_launch(void* const* d_in, const int* in_sizes, int n_in,
                              void* d_out, int out_size)
{
    const float* seq  = (const float*)d_in[0];
    const float* pos  = (const float*)d_in[1];
    const float* Wq   = (const float*)d_in[2];
    const float* bq   = (const float*)d_in[3];
    const float* Wk   = (const float*)d_in[4];
    const float* bk   = (const float*)d_in[5];
    const float* Wv   = (const float*)d_in[6];
    const float* bv   = (const float*)d_in[7];
    const float* Wo   = (const float*)d_in[8];
    const float* bo   = (const float*)d_in[9];
    const float* ln1w = (const float*)d_in[10];
    const float* ln1b = (const float*)d_in[11];
    const float* ln2w = (const float*)d_in[12];
    const float* ln2b = (const float*)d_in[13];
    const float* W1   = (const float*)d_in[14];
    const float* b1   = (const float*)d_in[15];
    const float* W2   = (const float*)d_in[16];
    const float* b2   = (const float*)d_in[17];
    const float* lnfw = (const float*)d_in[18];
    const float* lnfb = (const float*)d_in[19];
    const float* Wh   = (const float*)d_in[20];
    float* out = (float*)d_out;

    float *px, *pbqkv;
    __half *phh, *phl, *pqkvh, *pyh, *puh, *pwh, *pwl;
    cudaGetSymbolAddress((void**)&px, g_x);
    cudaGetSymbolAddress((void**)&phh, g_hh);
    cudaGetSymbolAddress((void**)&phl, g_hl);
    cudaGetSymbolAddress((void**)&pqkvh, g_qkvh);
    cudaGetSymbolAddress((void**)&pyh, g_yh);
    cudaGetSymbolAddress((void**)&puh, g_uh);
    cudaGetSymbolAddress((void**)&pwh, g_wh);
    cudaGetSymbolAddress((void**)&pwl, g_wl);
    cudaGetSymbolAddress((void**)&pbqkv, g_bqkv);

    cudaFuncSetAttribute(attn_h, cudaFuncAttributeMaxDynamicSharedMemorySize, ATT_SMEM);
    cudaFuncSetAttribute((gemm_h2<1>), cudaFuncAttributeMaxDynamicSharedMemorySize, GEMM_SMEM2);
    cudaFuncSetAttribute((gemm_h2<2>), cudaFuncAttributeMaxDynamicSharedMemorySize, GEMM_SMEM2);
    cudaFuncSetAttribute((gemm_h2<3>), cudaFuncAttributeMaxDynamicSharedMemorySize, GEMM_SMEM2);
    cudaFuncSetAttribute(gemm_head, cudaFuncAttributeMaxDynamicSharedMemorySize, GEMM_SMEM3);

    // ---- weight conversion: ONE launch ----
    conv_all<<<(int)(WTOT / 2048), 256>>>(Wq, Wk, Wv, Wo, W1, W2, Wh, pwh, pwl);
    packqkvb<<<L_*3*C_/256, 256>>>(bq, bk, bv, pbqkv);
    addpos_kernel<<<M_ * C_ / 4 / 256, 256>>>(seq, pos, px);

    dim3 gQKV(3*C_ / 128, M_ / 256);   // (24, 32)
    dim3 gC(C_ / 128, M_ / 256);       // (8, 32)
    dim3 gF(FF_ / 128, M_ / 256);      // (32, 32)
    dim3 gA(T_ / 256, B_ * H_);        // (8, 64)
    dim3 gHead(OUT_ / 128, M_ / 128);  // (8, 64)

    for (int l = 0; l < L_; l++) {
        const size_t wl = (size_t)l * WPL_;
        ln_split<<<M_, 256>>>(px, ln1w + l*C_, ln1b + l*C_, phh, nullptr);
        gemm_h2<1><<<gQKV, 256, GEMM_SMEM2>>>(phh, pwh + wl,
            pbqkv + l*3*C_, nullptr, nullptr, pqkvh, 3*C_, C_);
        attn_h<<<gA, 256, ATT_SMEM>>>(pqkvh, pyh);
        gemm_h2<3><<<gC, 256, GEMM_SMEM2>>>(pyh, pwh + wl + WOFF_WO,
            bo + l*C_, px, px, nullptr, C_, C_);
        ln_split<<<M_, 256>>>(px, ln2w + l*C_, ln2b + l*C_, phh, nullptr);
        gemm_h2<2><<<gF, 256, GEMM_SMEM2>>>(phh, pwh + wl + WOFF_W1,
            b1 + l*FF_, nullptr, nullptr, puh, FF_, C_);
        gemm_h2<3><<<gC, 256, GEMM_SMEM2>>>(puh, pwh + wl + WOFF_W2,
            b2 + l*C_, px, px, nullptr, C_, FF_);
    }

    // final LN needs lo for the 3-pass head GEMM
    ln_split<<<M_, 256>>>(px, lnfw, lnfb, phh, phl);
    gemm_head<<<gHead, 256, GEMM_SMEM3>>>(phh, phl, pwh + WHEAD_OFF, pwl + WHEAD_OFF,
        out, OUT_, C_);
}

// round 15
// speedup vs baseline: 6.7711x; 1.0140x over previous
#include <cuda_runtime.h>
#include <cuda_fp16.h>
#include <math.h>
#include <stdint.h>

#define L_ 8
#define H_ 16
#define T_ 2048
#define C_ 1024
#define OUT_ 1024
#define B_ 4
#define DH_ 64
#define FF_ 4096
#define M_ (B_*T_)   // 8192 rows

#define CC_ (C_*C_)                   // 1048576
#define WPL_ (12*CC_)                 // weights per layer (halves)
#define WOFF_WO  (3*CC_)
#define WOFF_W1  (4*CC_)
#define WOFF_W2  (8*CC_)
#define WHEAD_OFF ((size_t)L_*WPL_)   // 100663296
#define WTOT (WHEAD_OFF + CC_)        // 101711872

// q pre-scale: 0.125 (1/sqrt(DH)) * log2(e) -> softmax in base-2 domain
#define QSCALE 0.1803368801111204f

// ---------------- scratch (static device globals) ----------------
__device__ float g_x[M_*C_];
__device__ __align__(16) __half g_hh[M_*C_],  g_hl[M_*C_];
__device__ __align__(16) __half g_qkvh[3*M_*C_];
__device__ __align__(16) __half g_yh[M_*C_];
__device__ __align__(16) __half g_uh[(size_t)M_*FF_];
__device__ __align__(16) __half g_wh[WTOT],   g_wl[WTOT];
__device__ float g_bqkv[L_*3*C_];

// ================= helpers =================
__device__ __forceinline__ uint32_t smem_u32(const void* p) {
    uint32_t a;
    asm("{ .reg .u64 t; cvta.to.shared.u64 t, %1; cvt.u32.u64 %0, t; }" : "=r"(a) : "l"(p));
    return a;
}
__device__ __forceinline__ void mma16816(float* c, const uint32_t* a, uint32_t b0, uint32_t b1) {
    asm volatile(
        "mma.sync.aligned.m16n8k16.row.col.f32.f16.f16.f32 "
        "{%0,%1,%2,%3}, {%4,%5,%6,%7}, {%8,%9}, {%0,%1,%2,%3};"
        : "+f"(c[0]), "+f"(c[1]), "+f"(c[2]), "+f"(c[3])
        : "r"(a[0]), "r"(a[1]), "r"(a[2]), "r"(a[3]), "r"(b0), "r"(b1));
}
__device__ __forceinline__ void ldsm4(uint32_t* r, uint32_t addr) {
    asm volatile("ldmatrix.sync.aligned.m8n8.x4.shared.b16 {%0,%1,%2,%3}, [%4];"
                 : "=r"(r[0]), "=r"(r[1]), "=r"(r[2]), "=r"(r[3]) : "r"(addr));
}
__device__ __forceinline__ void ldsm4t(uint32_t* r, uint32_t addr) {
    asm volatile("ldmatrix.sync.aligned.m8n8.x4.trans.shared.b16 {%0,%1,%2,%3}, [%4];"
                 : "=r"(r[0]), "=r"(r[1]), "=r"(r[2]), "=r"(r[3]) : "r"(addr));
}
#define CP_ASYNC16(dst, src) \
    asm volatile("cp.async.cg.shared.global [%0], [%1], 16;" :: "r"(dst), "l"(src))
#define CP_COMMIT asm volatile("cp.async.commit_group;" ::: "memory")
#define CP_WAIT(n) asm volatile("cp.async.wait_group %0;" :: "n"(n) : "memory")

__device__ __forceinline__ float fex2(float x) {
    float y;
    asm("ex2.approx.f32 %0, %1;" : "=f"(y) : "f"(x));
    return y;
}
// two exps in one MUFU op: pack (a,b) to half2, ex2.approx.f16x2
__device__ __forceinline__ uint32_t ex2_h2(float a, float b) {
    __half2 hv = __floats2half2_rn(a, b);
    uint32_t r;
    asm("ex2.approx.f16x2 %0, %1;" : "=r"(r) : "r"(*(uint32_t*)&hv));
    return r;
}
__device__ __forceinline__ void split2(float x, float y, uint32_t& h, uint32_t& l) {
    __half2 hh = __floats2half2_rn(x, y);
    float2 hf = __half22float2(hh);
    __half2 ll = __floats2half2_rn(x - hf.x, y - hf.y);
    h = *(uint32_t*)&hh;
    l = *(uint32_t*)&ll;
}
__device__ __forceinline__ uint32_t pack_h2(float x, float y) {
    __half2 hh = __floats2half2_rn(x, y);
    return *(uint32_t*)&hh;
}
__device__ __forceinline__ float gelu_exact(float v) {
    return 0.5f * v * (1.0f + erff(v * 0.70710678118654752f));
}

// ================= fused weight conversion (single launch) =================
__global__ void __launch_bounds__(256) conv_all(
    const float* __restrict__ Wq, const float* __restrict__ Wk,
    const float* __restrict__ Wv, const float* __restrict__ Wo,
    const float* __restrict__ W1, const float* __restrict__ W2,
    const float* __restrict__ Whd,
    __half* __restrict__ dh, __half* __restrict__ dl)
{
    const size_t i = ((size_t)blockIdx.x * 256 + threadIdx.x) * 8;
    const float* src;
    if (i >= WHEAD_OFF) {
        src = Whd + (i - WHEAD_OFF);
    } else {
        const int l = (int)(i / WPL_);
        const size_t r = i % WPL_;
        if      (r <   (size_t)CC_)   src = Wq + (size_t)l*CC_   + r;
        else if (r < 2*(size_t)CC_)   src = Wk + (size_t)l*CC_   + (r -   CC_);
        else if (r < 3*(size_t)CC_)   src = Wv + (size_t)l*CC_   + (r - 2*CC_);
        else if (r < 4*(size_t)CC_)   src = Wo + (size_t)l*CC_   + (r - 3*CC_);
        else if (r < 8*(size_t)CC_)   src = W1 + (size_t)l*4*CC_ + (r - 4*CC_);
        else                          src = W2 + (size_t)l*4*CC_ + (r - 8*CC_);
    }
    float4 a = *(const float4*)(src), b = *(const float4*)(src + 4);
    uint32_t h[4], l4[4];
    split2(a.x, a.y, h[0], l4[0]); split2(a.z, a.w, h[1], l4[1]);
    split2(b.x, b.y, h[2], l4[2]); split2(b.z, b.w, h[3], l4[3]);
    *(uint4*)(dh + i) = make_uint4(h[0], h[1], h[2], h[3]);
    if (i >= WHEAD_OFF)
        *(uint4*)(dl + i) = make_uint4(l4[0], l4[1], l4[2], l4[3]);
}
__global__ void __launch_bounds__(256) packqkvb(
    const float* __restrict__ bq, const float* __restrict__ bk,
    const float* __restrict__ bv, float* __restrict__ dst)
{
    int idx = blockIdx.x * 256 + threadIdx.x;      // L_*3072
    int l = idx / 3072, c = idx % 3072;
    float v = (c < 1024) ? bq[l*1024 + c] : (c < 2048) ? bk[l*1024 + c - 1024]
                                                        : bv[l*1024 + c - 2048];
    dst[idx] = v;
}

// ================= x = seq + pos =================
__global__ void __launch_bounds__(256) addpos_kernel(
    const float* __restrict__ seq, const float* __restrict__ pos, float* __restrict__ x)
{
    int i = blockIdx.x * 256 + threadIdx.x;
    float4 s = ((const float4*)seq)[i];
    float4 p = ((const float4*)pos)[i & (T_*C_/4 - 1)];
    s.x += p.x; s.y += p.y; s.z += p.z; s.w += p.w;
    ((float4*)x)[i] = s;
}

// ================= LayerNorm -> fp16 hi (+ optional lo) =================
__global__ void __launch_bounds__(256) ln_split(
    const float* __restrict__ x, const float* __restrict__ w,
    const float* __restrict__ b, __half* __restrict__ outh, __half* __restrict__ outl)
{
    const int row = blockIdx.x;
    const int t = threadIdx.x;
    const float4 v = *(const float4*)(x + (size_t)row * C_ + t * 4);
    float s  = v.x + v.y + v.z + v.w;
    float sq = v.x*v.x + v.y*v.y + v.z*v.z + v.w*v.w;
    #pragma unroll
    for (int off = 16; off; off >>= 1) {
        s  += __shfl_xor_sync(0xffffffffu, s,  off);
        sq += __shfl_xor_sync(0xffffffffu, sq, off);
    }
    __shared__ float rs_[8], rq_[8];
    if ((t & 31) == 0) { rs_[t >> 5] = s; rq_[t >> 5] = sq; }
    __syncthreads();
    s = 0.f; sq = 0.f;
    #pragma unroll
    for (int i = 0; i < 8; i++) { s += rs_[i]; sq += rq_[i]; }
    const float mu   = s * (1.0f / 1024.0f);
    const float var  = sq * (1.0f / 1024.0f) - mu * mu;
    const float rstd = rsqrtf(var + 1e-5f);
    const float4 wv = *(const float4*)(w + t * 4);
    const float4 bv = *(const float4*)(b + t * 4);
    float ox = (v.x - mu) * rstd * wv.x + bv.x;
    float oy = (v.y - mu) * rstd * wv.y + bv.y;
    float oz = (v.z - mu) * rstd * wv.z + bv.z;
    float ow = (v.w - mu) * rstd * wv.w + bv.w;
    uint32_t h0, l0, h1, l1;
    split2(ox, oy, h0, l0);
    split2(oz, ow, h1, l1);
    *(uint2*)(outh + (size_t)row * C_ + t * 4) = make_uint2(h0, h1);
    if (outl) *(uint2*)(outl + (size_t)row * C_ + t * 4) = make_uint2(l0, l1);
}

// ================= 1-pass fp16 GEMM, 256x128 block, 64x64 warp tile =================
#define GSTG2 49152u
#define GEMM_SMEM2 (3*49152)

template <int EPI>
__global__ void __launch_bounds__(256, 1) gemm_h2(
    const __half* __restrict__ Ah,
    const __half* __restrict__ Wh,
    const float* __restrict__ bias, const float* __restrict__ resid,
    float* __restrict__ outf, __half* __restrict__ outh,
    int N, int K)
{
    extern __shared__ char sm[];
    const uint32_t sb = smem_u32(sm);
    const int t = threadIdx.x, w = t >> 5, lane = t & 31;
    const int bm = blockIdx.y, bn = blockIdx.x;
    const int wm = w & 3, wn = w >> 2;

    const int crow = t >> 1, chalf = t & 1;
    const __half* agh = Ah + (size_t)(bm*256 + crow) * K + chalf*32;
    const __half* bgh = Wh + (size_t)(bn*128 + crow) * K + chalf*32;
    uint32_t dsto[4];
    #pragma unroll
    for (int i = 0; i < 4; i++) {
        int c16 = chalf*4 + i;
        dsto[i] = (uint32_t)(crow*128 + ((c16 ^ (crow & 7)) << 4));
    }
    auto load_stage = [&](int c, int slot) {
        const uint32_t s0 = sb + (uint32_t)slot * GSTG2;
        const __half* a0 = agh + c*64;
        const __half* b0 = bgh + c*64;
        #pragma unroll
        for (int i = 0; i < 4; i++) CP_ASYNC16(s0 + dsto[i],           a0 + i*8);
        #pragma unroll
        for (int i = 0; i < 4; i++) CP_ASYNC16(s0 + 16384u + dsto[i],  a0 + (size_t)128*K + i*8);
        #pragma unroll
        for (int i = 0; i < 4; i++) CP_ASYNC16(s0 + 32768u + dsto[i],  b0 + i*8);
    };

    const int ra = lane & 15, ca = lane >> 4;
    const int rb = (lane & 7) + ((lane >> 4) << 3), cb = (lane >> 3) & 1;
    const int xr = lane & 7;
    const uint32_t aro = (uint32_t)((wm*64 + ra) * 128);
    const uint32_t bro = (uint32_t)((wn*64 + rb) * 128);

    float acc[4][8][4];
    #pragma unroll
    for (int i = 0; i < 4; i++)
        #pragma unroll
        for (int j = 0; j < 8; j++)
            #pragma unroll
            for (int r = 0; r < 4; r++) acc[i][j][r] = 0.f;

    load_stage(0, 0); CP_COMMIT;
    load_stage(1, 1); CP_COMMIT;

    const int NC = K >> 6;
    int slot = 0;
    for (int c = 0; c < NC; c++) {
        CP_WAIT(1);
        __syncthreads();
        if (c + 2 < NC) {
            int ns = slot + 2; if (ns >= 3) ns -= 3;
            load_stage(c + 2, ns);
        }
        CP_COMMIT;
        const uint32_t st = sb + (uint32_t)slot * GSTG2;
        #pragma unroll
        for (int ks = 0; ks < 4; ks++) {
            const uint32_t kca = (uint32_t)(((ks*2 + ca) ^ xr) << 4);
            const uint32_t kcb = (uint32_t)(((ks*2 + cb) ^ xr) << 4);
            uint32_t ah[4][4], bh[4][4];
            #pragma unroll
            for (int mt = 0; mt < 4; mt++)
                ldsm4(ah[mt], st + aro + mt*2048u + kca);
            #pragma unroll
            for (int nq = 0; nq < 4; nq++)
                ldsm4(bh[nq], st + 32768u + bro + nq*2048u + kcb);
            #pragma unroll
            for (int mt = 0; mt < 4; mt++)
                #pragma unroll
                for (int nt = 0; nt < 8; nt++) {
                    const int nq = nt >> 1, s2 = (nt & 1) * 2;
                    mma16816(acc[mt][nt], ah[mt], bh[nq][s2], bh[nq][s2+1]);
                }
        }
        slot = (slot + 1 == 3) ? 0 : slot + 1;
    }

    // ---- epilogue ----
    const int grbase = bm*256 + wm*64;
    const int gcbase = bn*128 + wn*64;
    #pragma unroll
    for (int mt = 0; mt < 4; mt++) {
        const int r0 = grbase + mt*16 + (lane >> 2);
        #pragma unroll
        for (int nt = 0; nt < 8; nt++) {
            const int gc = gcbase + nt*8 + (lane & 3)*2;
            float2 v0 = make_float2(acc[mt][nt][0], acc[mt][nt][1]);
            float2 v1 = make_float2(acc[mt][nt][2], acc[mt][nt][3]);
            {
                float2 bb = *(const float2*)(bias + gc);
                v0.x += bb.x; v0.y += bb.y; v1.x += bb.x; v1.y += bb.y;
            }
            if (EPI == 1) {
                const int third = gc >> 10, lc = gc & 1023;
                __half* oh = outh + (size_t)third * ((size_t)M_ * C_);
                if (third == 0) {
                    v0.x *= QSCALE; v0.y *= QSCALE; v1.x *= QSCALE; v1.y *= QSCALE;
                }
                *(uint32_t*)(oh + (size_t)r0 * 1024 + lc)     = pack_h2(v0.x, v0.y);
                *(uint32_t*)(oh + (size_t)(r0+8) * 1024 + lc) = pack_h2(v1.x, v1.y);
            } else if (EPI == 2) {
                v0.x = gelu_exact(v0.x); v0.y = gelu_exact(v0.y);
                v1.x = gelu_exact(v1.x); v1.y = gelu_exact(v1.y);
                *(uint32_t*)(outh + (size_t)r0 * N + gc)     = pack_h2(v0.x, v0.y);
                *(uint32_t*)(outh + (size_t)(r0+8) * N + gc) = pack_h2(v1.x, v1.y);
            } else {  // EPI == 3
                float2 ra2 = *(const float2*)(resid + (size_t)r0 * N + gc);
                float2 rb2 = *(const float2*)(resid + (size_t)(r0+8) * N + gc);
                v0.x += ra2.x; v0.y += ra2.y; v1.x += rb2.x; v1.y += rb2.y;
                *(float2*)(outf + (size_t)r0 * N + gc) = v0;
                *(float2*)(outf + (size_t)(r0+8) * N + gc) = v1;
            }
        }
    }
}

// ================= head GEMM: 3-pass, 128x128 block =================
#define GSTG3 65536u
#define GEMM_SMEM3 (3*65536)

__global__ void __launch_bounds__(256, 1) gemm_head(
    const __half* __restrict__ Ah, const __half* __restrict__ Al,
    const __half* __restrict__ Wh, const __half* __restrict__ Wl,
    float* __restrict__ outf, int N, int K)
{
    extern __shared__ char sm[];
    const uint32_t sb = smem_u32(sm);
    const int t = threadIdx.x, w = t >> 5, lane = t & 31;
    const int bm = blockIdx.y, bn = blockIdx.x;
    const int wm = w & 3, wn = w >> 2;

    const int crow = t >> 1, chalf = t & 1;
    const __half* agh = Ah + (size_t)(bm*128 + crow) * K + chalf*32;
    const __half* agl = Al + (size_t)(bm*128 + crow) * K + chalf*32;
    const __half* bgh = Wh + (size_t)(bn*128 + crow) * K + chalf*32;
    const __half* bgl = Wl + (size_t)(bn*128 + crow) * K + chalf*32;
    uint32_t dsto[4];
    #pragma unroll
    for (int i = 0; i < 4; i++) {
        int c16 = chalf*4 + i;
        dsto[i] = (uint32_t)(crow*128 + ((c16 ^ (crow & 7)) << 4));
    }
    auto load_stage = [&](int c, int slot) {
        const uint32_t s0 = sb + (uint32_t)slot * GSTG3;
        #pragma unroll
        for (int i = 0; i < 4; i++) CP_ASYNC16(s0 + dsto[i],          agh + c*64 + i*8);
        #pragma unroll
        for (int i = 0; i < 4; i++) CP_ASYNC16(s0 + 16384u + dsto[i], agl + c*64 + i*8);
        #pragma unroll
        for (int i = 0; i < 4; i++) CP_ASYNC16(s0 + 32768u + dsto[i], bgh + c*64 + i*8);
        #pragma unroll
        for (int i = 0; i < 4; i++) CP_ASYNC16(s0 + 49152u + dsto[i], bgl + c*64 + i*8);
    };

    const int ra = lane & 15, ca = lane >> 4;
    const int rb = (lane & 7) + ((lane >> 4) << 3), cb = (lane >> 3) & 1;
    const int xr = lane & 7;
    const uint32_t aro = (uint32_t)((wm*32 + ra) * 128);
    const uint32_t bro = (uint32_t)((wn*64 + rb) * 128);

    float acc[2][8][4];
    #pragma unroll
    for (int i = 0; i < 2; i++)
        #pragma unroll
        for (int j = 0; j < 8; j++)
            #pragma unroll
            for (int r = 0; r < 4; r++) acc[i][j][r] = 0.f;

    load_stage(0, 0); CP_COMMIT;
    load_stage(1, 1); CP_COMMIT;

    const int NC = K >> 6;
    int slot = 0;
    for (int c = 0; c < NC; c++) {
        CP_WAIT(1);
        __syncthreads();
        if (c + 2 < NC) {
            int ns = slot + 2; if (ns >= 3) ns -= 3;
            load_stage(c + 2, ns);
        }
        CP_COMMIT;
        const uint32_t st = sb + (uint32_t)slot * GSTG3;
        #pragma unroll
        for (int ks = 0; ks < 4; ks++) {
            const uint32_t kca = (uint32_t)(((ks*2 + ca) ^ xr) << 4);
            const uint32_t kcb = (uint32_t)(((ks*2 + cb) ^ xr) << 4);
            uint32_t ah[2][4], al4[2][4], bh[4][4], bl4[4][4];
            #pragma unroll
            for (int mt = 0; mt < 2; mt++) {
                ldsm4(ah[mt],  st + aro + mt*2048u + kca);
                ldsm4(al4[mt], st + 16384u + aro + mt*2048u + kca);
            }
            #pragma unroll
            for (int nq = 0; nq < 4; nq++) {
                ldsm4(bh[nq],  st + 32768u + bro + nq*2048u + kcb);
                ldsm4(bl4[nq], st + 49152u + bro + nq*2048u + kcb);
            }
            #pragma unroll
            for (int mt = 0; mt < 2; mt++)
                #pragma unroll
                for (int nt = 0; nt < 8; nt++) {
                    const int nq = nt >> 1, s2 = (nt & 1) * 2;
                    mma16816(acc[mt][nt], ah[mt], bh[nq][s2], bh[nq][s2+1]);
                }
            #pragma unroll
            for (int mt = 0; mt < 2; mt++)
                #pragma unroll
                for (int nt = 0; nt < 8; nt++) {
                    const int nq = nt >> 1, s2 = (nt & 1) * 2;
                    mma16816(acc[mt][nt], ah[mt], bl4[nq][s2], bl4[nq][s2+1]);
                }
            #pragma unroll
            for (int mt = 0; mt < 2; mt++)
                #pragma unroll
                for (int nt = 0; nt < 8; nt++) {
                    const int nq = nt >> 1, s2 = (nt & 1) * 2;
                    mma16816(acc[mt][nt], al4[mt], bh[nq][s2], bh[nq][s2+1]);
                }
        }
        slot = (slot + 1 == 3) ? 0 : slot + 1;
    }

    const int grbase = bm*128 + wm*32;
    const int gcbase = bn*128 + wn*64;
    #pragma unroll
    for (int mt = 0; mt < 2; mt++) {
        const int r0 = grbase + mt*16 + (lane >> 2);
        #pragma unroll
        for (int nt = 0; nt < 8; nt++) {
            const int gc = gcbase + nt*8 + (lane & 3)*2;
            *(float2*)(outf + (size_t)r0 * N + gc) =
                make_float2(acc[mt][nt][0], acc[mt][nt][1]);
            *(float2*)(outf + (size_t)(r0+8) * N + gc) =
                make_float2(acc[mt][nt][2], acc[mt][nt][3]);
        }
    }
}

// ================= flash attention: 1-pass fp16, Q tile 128, 2 CTAs/SM =================
// 8 warps, each warp 16 Q rows. KV tile 64. f16x2 exp.
// smem/CTA: Qh[128x64]@0 (16KB), then 3 stages of 16KB: Kh@0 Vh@8K -> 64KB total.
#define ASTG 16384
#define AQSZ 16384
#define ATT_SMEM (AQSZ + 3*ASTG)

__global__ void __launch_bounds__(256, 2) attn_h(
    const __half* __restrict__ qkvh, __half* __restrict__ yh)
{
    extern __shared__ char sm[];
    const uint32_t sb = smem_u32(sm);
    const int t = threadIdx.x, w = t >> 5, lane = t & 31;
    const int bhx = blockIdx.y, b = bhx >> 4, h = bhx & 15;
    const int q0 = blockIdx.x * 128;
    const size_t MC = (size_t)M_ * C_;
    const int NT = T_ / 64;   // 32 tiles

    const __half* qgh = qkvh + (size_t)(b*T_ + q0) * C_ + h*64;
    const __half* kgh = qkvh + MC   + (size_t)(b*T_) * C_ + h*64;
    const __half* vgh = qkvh + 2*MC + (size_t)(b*T_) * C_ + h*64;

    // Q loads: row = t>>1, half-row = t&1 (4 chunks each, chunk = 8 halves)
    {
        const int qr = t >> 1, qc = t & 1;
        const __half* qrow = qgh + (size_t)qr * C_;
        #pragma unroll
        for (int i = 0; i < 4; i++) {
            const int c16 = qc*4 + i;
            const uint32_t d = (uint32_t)(qr*128 + ((c16 ^ (qr & 7)) << 4));
            CP_ASYNC16(sb + d, qrow + c16*8);
        }
    }
    CP_COMMIT;

    // KV stage loader
    const int kr = t >> 2, kc2 = (t & 3) * 2;
    auto load_kv = [&](int kt, int slot) {
        const uint32_t s0 = sb + AQSZ + (uint32_t)slot * ASTG;
        const size_t rowoff = (size_t)(kt*64 + kr) * C_;
        #pragma unroll
        for (int i = 0; i < 2; i++) {
            const int c16 = kc2 + i;
            const uint32_t d = (uint32_t)(kr*128 + ((c16 ^ (kr & 7)) << 4));
            CP_ASYNC16(s0 + d,         kgh + rowoff + c16*8);
            CP_ASYNC16(s0 + 8192u + d, vgh + rowoff + c16*8);
        }
    };
    load_kv(0, 0); CP_COMMIT;
    load_kv(1, 1); CP_COMMIT;

    const int ra = lane & 15, ca = lane >> 4;
    const int rb = (lane & 7) + ((lane >> 4) << 3), cb = (lane >> 3) & 1;
    const int rv = (lane & 7) + (((lane >> 3) & 1) << 3), cv = lane >> 4;
    const int xr = lane & 7;

    CP_WAIT(2);           // Q landed
    __syncthreads();
    uint32_t qh4[4][4];
    {
        const uint32_t qro = (uint32_t)((w*16 + ra) * 128);
        #pragma unroll
        for (int ks = 0; ks < 4; ks++) {
            const uint32_t off = qro + (uint32_t)(((ks*2 + ca) ^ xr) << 4);
            ldsm4(qh4[ks], sb + off);
        }
    }

    float o_[8][4];
    #pragma unroll
    for (int i = 0; i < 8; i++)
        #pragma unroll
        for (int j = 0; j < 4; j++) o_[i][j] = 0.f;
    float m_a = -1e30f, m_b = -1e30f, l_a = 0.f, l_b = 0.f;

    int slot = 0;
    for (int kt = 0; kt < NT; kt++) {
        CP_WAIT(1);
        __syncthreads();
        if (kt + 2 < NT) {
            int ns = slot + 2; if (ns >= 3) ns -= 3;
            load_kv(kt + 2, ns);
        }
        CP_COMMIT;
        const uint32_t st = sb + AQSZ + (uint32_t)slot * ASTG;

        // ---- S = qh·kh (1-pass), warp tile 16x64 ----
        float sc[8][4];
        #pragma unroll
        for (int i = 0; i < 8; i++)
            #pragma unroll
            for (int j = 0; j < 4; j++) sc[i][j] = 0.f;
        #pragma unroll
        for (int ks = 0; ks < 4; ks++) {
            uint32_t kh4[4][4];
            #pragma unroll
            for (int nq = 0; nq < 4; nq++) {
                const uint32_t off = (uint32_t)((nq*16 + rb) * 128)
                                   + (uint32_t)(((ks*2 + cb) ^ xr) << 4);
                ldsm4(kh4[nq], st + off);
            }
            #pragma unroll
            for (int nt = 0; nt < 8; nt++) {
                const int nq = nt >> 1, s2 = (nt & 1) * 2;
                mma16816(sc[nt], qh4[ks], kh4[nq][s2], kh4[nq][s2+1]);
            }
        }

        // ---- online softmax (base-2, fp16x2 exp -> P packed) ----
        uint32_t pc[8][2];
        {
            float mxa = -1e30f, mxb = -1e30f;
            #pragma unroll
            for (int nt = 0; nt < 8; nt++) {
                mxa = fmaxf(mxa, fmaxf(sc[nt][0], sc[nt][1]));
                mxb = fmaxf(mxb, fmaxf(sc[nt][2], sc[nt][3]));
            }
            mxa = fmaxf(mxa, __shfl_xor_sync(0xffffffffu, mxa, 1));
            mxa = fmaxf(mxa, __shfl_xor_sync(0xffffffffu, mxa, 2));
            mxb = fmaxf(mxb, __shfl_xor_sync(0xffffffffu, mxb, 1));
            mxb = fmaxf(mxb, __shfl_xor_sync(0xffffffffu, mxb, 2));
            const float nma = fmaxf(m_a, mxa), nmb = fmaxf(m_b, mxb);
            const float cfa = fex2(m_a - nma), cfb = fex2(m_b - nmb);
            m_a = nma; m_b = nmb;
            float rsa = 0.f, rsb = 0.f;
            #pragma unroll
            for (int nt = 0; nt < 8; nt++) {
                const uint32_t e01 = ex2_h2(sc[nt][0] - nma, sc[nt][1] - nma);
                const uint32_t e23 = ex2_h2(sc[nt][2] - nmb, sc[nt][3] - nmb);
                pc[nt][0] = e01;
                pc[nt][1] = e23;
                float2 f01 = __half22float2(*(const __half2*)&e01);
                float2 f23 = __half22float2(*(const __half2*)&e23);
                rsa += f01.x + f01.y;
                rsb += f23.x + f23.y;
            }
            rsa += __shfl_xor_sync(0xffffffffu, rsa, 1);
            rsa += __shfl_xor_sync(0xffffffffu, rsa, 2);
            rsb += __shfl_xor_sync(0xffffffffu, rsb, 1);
            rsb += __shfl_xor_sync(0xffffffffu, rsb, 2);
            l_a = l_a * cfa + rsa;
            l_b = l_b * cfb + rsb;
            #pragma unroll
            for (int dt = 0; dt < 8; dt++) {
                o_[dt][0] *= cfa; o_[dt][1] *= cfa;
                o_[dt][2] *= cfb; o_[dt][3] *= cfb;
            }
        }

        // ---- O += ph·vh (1-pass) ----
        #pragma unroll
        for (int ks = 0; ks < 4; ks++) {
            uint32_t ph[4];
            ph[0] = pc[2*ks][0];
            ph[1] = pc[2*ks][1];
            ph[2] = pc[2*ks+1][0];
            ph[3] = pc[2*ks+1][1];
            uint32_t vh4[4][4];
            #pragma unroll
            for (int nq = 0; nq < 4; nq++) {
                const uint32_t off = (uint32_t)((ks*16 + rv) * 128)
                                   + (uint32_t)(((nq*2 + cv) ^ xr) << 4);
                ldsm4t(vh4[nq], st + 8192u + off);
            }
            #pragma unroll
            for (int dt = 0; dt < 8; dt++) {
                const int nq = dt >> 1, s2 = (dt & 1) * 2;
                mma16816(o_[dt], ph, vh4[nq][s2], vh4[nq][s2+1]);
            }
        }
        slot = (slot + 1 == 3) ? 0 : slot + 1;
    }

    // ---- write y (fp16 hi only) ----
    const float ia = 1.f / l_a, ib = 1.f / l_b;
    const int r0 = q0 + w*16 + (lane >> 2);
    __half* ybh = yh + (size_t)(b*T_ + r0) * C_ + h*64;
    #pragma unroll
    for (int dt = 0; dt < 8; dt++) {
        const int gc = dt*8 + (lane & 3)*2;
        *(uint32_t*)(ybh + gc)                = pack_h2(o_[dt][0]*ia, o_[dt][1]*ia);
        *(uint32_t*)(ybh + (size_t)8*C_ + gc) = pack_h2(o_[dt][2]*ib, o_[dt][3]*ib);
    }
}

// ================= orchestration =================
extern "C" void kernel_launch(void* const* d_in, const int* in_sizes, int n_in,
                              void* d_out, int out_size)
{
    const float* seq  = (const float*)d_in[0];
    const float* pos  = (const float*)d_in[1];
    const float* Wq   = (const float*)d_in[2];
    const float* bq   = (const float*)d_in[3];
    const float* Wk   = (const float*)d_in[4];
    const float* bk   = (const float*)d_in[5];
    const float* Wv   = (const float*)d_in[6];
    const float* bv   = (const float*)d_in[7];
    const float* Wo   = (const float*)d_in[8];
    const float* bo   = (const float*)d_in[9];
    const float* ln1w = (const float*)d_in[10];
    const float* ln1b = (const float*)d_in[11];
    const float* ln2w = (const float*)d_in[12];
    const float* ln2b = (const float*)d_in[13];
    const float* W1   = (const float*)d_in[14];
    const float* b1   = (const float*)d_in[15];
    const float* W2   = (const float*)d_in[16];
    const float* b2   = (const float*)d_in[17];
    const float* lnfw = (const float*)d_in[18];
    const float* lnfb = (const float*)d_in[19];
    const float* Wh   = (const float*)d_in[20];
    float* out = (float*)d_out;

    float *px, *pbqkv;
    __half *phh, *phl, *pqkvh, *pyh, *puh, *pwh, *pwl;
    cudaGetSymbolAddress((void**)&px, g_x);
    cudaGetSymbolAddress((void**)&phh, g_hh);
    cudaGetSymbolAddress((void**)&phl, g_hl);
    cudaGetSymbolAddress((void**)&pqkvh, g_qkvh);
    cudaGetSymbolAddress((void**)&pyh, g_yh);
    cudaGetSymbolAddress((void**)&puh, g_uh);
    cudaGetSymbolAddress((void**)&pwh, g_wh);
    cudaGetSymbolAddress((void**)&pwl, g_wl);
    cudaGetSymbolAddress((void**)&pbqkv, g_bqkv);

    cudaFuncSetAttribute(attn_h, cudaFuncAttributeMaxDynamicSharedMemorySize, ATT_SMEM);
    cudaFuncSetAttribute((gemm_h2<1>), cudaFuncAttributeMaxDynamicSharedMemorySize, GEMM_SMEM2);
    cudaFuncSetAttribute((gemm_h2<2>), cudaFuncAttributeMaxDynamicSharedMemorySize, GEMM_SMEM2);
    cudaFuncSetAttribute((gemm_h2<3>), cudaFuncAttributeMaxDynamicSharedMemorySize, GEMM_SMEM2);
    cudaFuncSetAttribute(gemm_head, cudaFuncAttributeMaxDynamicSharedMemorySize, GEMM_SMEM3);

    // ---- weight conversion: ONE launch ----
    conv_all<<<(int)(WTOT / 2048), 256>>>(Wq, Wk, Wv, Wo, W1, W2, Wh, pwh, pwl);
    packqkvb<<<L_*3*C_/256, 256>>>(bq, bk, bv, pbqkv);
    addpos_kernel<<<M_ * C_ / 4 / 256, 256>>>(seq, pos, px);

    dim3 gQKV(3*C_ / 128, M_ / 256);   // (24, 32)
    dim3 gC(C_ / 128, M_ / 256);       // (8, 32)
    dim3 gF(FF_ / 128, M_ / 256);      // (32, 32)
    dim3 gA(T_ / 128, B_ * H_);        // (16, 64)
    dim3 gHead(OUT_ / 128, M_ / 128);  // (8, 64)

    for (int l = 0; l < L_; l++) {
        const size_t wl = (size_t)l * WPL_;
        ln_split<<<M_, 256>>>(px, ln1w + l*C_, ln1b + l*C_, phh, nullptr);
        gemm_h2<1><<<gQKV, 256, GEMM_SMEM2>>>(phh, pwh + wl,
            pbqkv + l*3*C_, nullptr, nullptr, pqkvh, 3*C_, C_);
        attn_h<<<gA, 256, ATT_SMEM>>>(pqkvh, pyh);
        gemm_h2<3><<<gC, 256, GEMM_SMEM2>>>(pyh, pwh + wl + WOFF_WO,
            bo + l*C_, px, px, nullptr, C_, C_);
        ln_split<<<M_, 256>>>(px, ln2w + l*C_, ln2b + l*C_, phh, nullptr);
        gemm_h2<2><<<gF, 256, GEMM_SMEM2>>>(phh, pwh + wl + WOFF_W1,
            b1 + l*FF_, nullptr, nullptr, puh, FF_, C_);
        gemm_h2<3><<<gC, 256, GEMM_SMEM2>>>(puh, pwh + wl + WOFF_W2,
            b2 + l*C_, px, px, nullptr, C_, FF_);
    }

    // final LN needs lo for the 3-pass head GEMM
    ln_split<<<M_, 256>>>(px, lnfw, lnfb, phh, phl);
    gemm_head<<<gHead, 256, GEMM_SMEM3>>>(phh, phl, pwh + WHEAD_OFF, pwl + WHEAD_OFF,
        out, OUT_, C_);
}